// round 9
// baseline (speedup 1.0000x reference)
#include <cuda_runtime.h>
#include <math.h>
#include <stdint.h>

// Problem constants
#define BDIM   4
#define TDIM   2048
#define CDIM   1024
#define HEADS  16
#define HD     64
#define FFDIM  4096
#define BT     8192            // B*T rows
#define QKVW   3072            // 3*C

// ---------------------------------------------------------------------------
// Scratch (no allocations allowed — __device__ globals)
// ---------------------------------------------------------------------------
__device__ float g_ln [BT * CDIM];
__device__ float g_qkv[BT * QKVW];
__device__ float g_y  [BT * CDIM];
__device__ float g_x2 [BT * CDIM];
__device__ float g_h  [BT * FFDIM];
// tf32-rounded weights
__device__ float g_wq [QKVW * CDIM];
__device__ float g_wo [CDIM * CDIM];
__device__ float g_wfc[FFDIM * CDIM];
__device__ float g_wp [CDIM * FFDIM];

// ---------------------------------------------------------------------------
// Helpers
// ---------------------------------------------------------------------------
__device__ __forceinline__ uint32_t f2tf32(float f) {
    uint32_t u;
    asm("cvt.rna.tf32.f32 %0, %1;" : "=r"(u) : "f"(f));
    return u;
}
__device__ __forceinline__ float tf32r(float f) {
    return __uint_as_float(f2tf32(f));
}
__device__ __forceinline__ uint32_t smem_u32(const void* p) {
    uint32_t a;
    asm("{ .reg .u64 t; cvta.to.shared.u64 t, %1; cvt.u32.u64 %0, t; }"
        : "=r"(a) : "l"(p));
    return a;
}
__device__ __forceinline__ void cp_async16(uint32_t saddr, const void* gaddr) {
    asm volatile("cp.async.cg.shared.global [%0], [%1], 16;"
                 :: "r"(saddr), "l"(gaddr) : "memory");
}
__device__ __forceinline__ void cp_commit() {
    asm volatile("cp.async.commit_group;" ::: "memory");
}
__device__ __forceinline__ void ldsm_x4(uint32_t& r0, uint32_t& r1,
                                        uint32_t& r2, uint32_t& r3,
                                        uint32_t addr) {
    asm volatile("ldmatrix.sync.aligned.m8n8.x4.shared.b16 {%0,%1,%2,%3}, [%4];"
                 : "=r"(r0), "=r"(r1), "=r"(r2), "=r"(r3) : "r"(addr));
}
__device__ __forceinline__ void mma_tf32(float* d, const uint32_t* a,
                                         uint32_t b0, uint32_t b1) {
    asm volatile(
        "mma.sync.aligned.m16n8k8.row.col.f32.tf32.tf32.f32 "
        "{%0,%1,%2,%3}, {%4,%5,%6,%7}, {%8,%9}, {%0,%1,%2,%3};"
        : "+f"(d[0]), "+f"(d[1]), "+f"(d[2]), "+f"(d[3])
        : "r"(a[0]), "r"(a[1]), "r"(a[2]), "r"(a[3]), "r"(b0), "r"(b1));
}
__device__ __forceinline__ float gelu_f(float v) {
    return 0.5f * v * (1.0f + erff(v * 0.70710678118654752f));
}

// ---------------------------------------------------------------------------
// Weight prep: round to tf32 once
// ---------------------------------------------------------------------------
__global__ __launch_bounds__(256)
void round_tf32_kernel(const float* __restrict__ src, float* __restrict__ dst,
                       int n4)
{
    const int i = blockIdx.x * blockDim.x + threadIdx.x;
    if (i < n4) {
        float4 v = ((const float4*)src)[i];
        v.x = tf32r(v.x); v.y = tf32r(v.y);
        v.z = tf32r(v.z); v.w = tf32r(v.w);
        ((float4*)dst)[i] = v;
    }
}

// ---------------------------------------------------------------------------
// LayerNorm: one block per row, C=1024, 256 threads x float4 (tf32 output)
// ---------------------------------------------------------------------------
__global__ __launch_bounds__(256)
void ln_kernel(const float* __restrict__ x, const float* __restrict__ g,
               float* __restrict__ y)
{
    const int row = blockIdx.x;
    const int tid = threadIdx.x;
    const float4 v = ((const float4*)(x + (size_t)row * CDIM))[tid];
    float s  = v.x + v.y + v.z + v.w;
    float ss = v.x * v.x + v.y * v.y + v.z * v.z + v.w * v.w;
#pragma unroll
    for (int o = 16; o > 0; o >>= 1) {
        s  += __shfl_xor_sync(0xffffffffu, s,  o);
        ss += __shfl_xor_sync(0xffffffffu, ss, o);
    }
    __shared__ float rs[8], rss[8];
    const int w = tid >> 5, lane = tid & 31;
    if (lane == 0) { rs[w] = s; rss[w] = ss; }
    __syncthreads();
    if (tid == 0) {
        float a = 0.f, b = 0.f;
#pragma unroll
        for (int i = 0; i < 8; i++) { a += rs[i]; b += rss[i]; }
        const float mean = a * (1.0f / CDIM);
        const float var  = b * (1.0f / CDIM) - mean * mean;
        rs[0]  = mean;
        rss[0] = rsqrtf(var + 1e-5f);
    }
    __syncthreads();
    const float mean = rs[0], rstd = rss[0];
    const float4 gv = ((const float4*)g)[tid];
    float4 o4;
    o4.x = tf32r((v.x - mean) * rstd * gv.x);
    o4.y = tf32r((v.y - mean) * rstd * gv.y);
    o4.z = tf32r((v.z - mean) * rstd * gv.z);
    o4.w = tf32r((v.w - mean) * rstd * gv.w);
    ((float4*)(y + (size_t)row * CDIM))[tid] = o4;
}

// ---------------------------------------------------------------------------
// TF32 mma.sync GEMM v6 (NT): C[m,n] = sum_k A[m,k]*B[n,k]
// CTA 128x128, 256 threads (8 warps in 2x4), warp tile 64x32 (acc=64 regs),
// K-chunk 32, 2-stage cp.async double buffer, ldmatrix fragments.
// 2 CTAs/SM -> 16 warps/SM (4/SMSP) to hide LDSM latency.
// EPI: 0 = round(acc), 1 = acc + res, 2 = round(gelu(acc)).
// ---------------------------------------------------------------------------
#define GP     36
#define TILE_F (128 * GP)
#define GSMEM2 (4 * TILE_F * 4)

template <int EPI>
__global__ __launch_bounds__(256, 2)
void gemm_v6(const float* __restrict__ A, const float* __restrict__ B,
             const float* __restrict__ res, float* __restrict__ C,
             int M, int N, int K)
{
    extern __shared__ float sm[];
    const uint32_t sb = smem_u32(sm);

    const int tid  = threadIdx.x;
    const int wid  = tid >> 5, lane = tid & 31;
    const int gid  = lane >> 2, tig = lane & 3;
    const int wm   = (wid & 1) << 6;     // 0 / 64 row slab
    const int wn   = (wid >> 1) << 5;    // 0/32/64/96 col slab
    const int bm   = blockIdx.y << 7, bn = blockIdx.x << 7;

    // cp.async map: 4 x 16B per operand tile per thread (256 threads)
    const int lr = tid >> 3;             // 0..31
    const int lc = (tid & 7) << 2;       // 0,4,...,28
    const float* Ag = A + (size_t)(bm + lr) * K + lc;
    const float* Bg = B + (size_t)(bn + lr) * K + lc;
    uint32_t so[4];
#pragma unroll
    for (int p = 0; p < 4; p++)
        so[p] = (uint32_t)((p * 32 + lr) * GP + lc) * 4u;

    const uint32_t aB[2] = { sb,                sb + 2u * TILE_F * 4u };
    const uint32_t bB[2] = { sb + TILE_F * 4u,  sb + 3u * TILE_F * 4u };

    // ldmatrix lane->address maps (byte offsets within a tile buffer)
    const int aRow = wm + (lane & 7) + ((lane >> 3) & 1) * 8;
    const uint32_t aMap = (uint32_t)(aRow * GP + (lane >> 4) * 4) * 4u;
    const int bRow = wn + (lane >> 4) * 8 + (lane & 7);
    const uint32_t bMap = (uint32_t)(bRow * GP + ((lane >> 3) & 1) * 4) * 4u;

    float acc[4][4][4];                  // [mf][nf][4] -> 64 regs
#pragma unroll
    for (int i = 0; i < 4; i++)
#pragma unroll
        for (int j = 0; j < 4; j++)
#pragma unroll
            for (int q = 0; q < 4; q++) acc[i][j][q] = 0.f;

    const int nk = K >> 5;

#pragma unroll
    for (int p = 0; p < 4; p++) {
        cp_async16(aB[0] + so[p], Ag + (size_t)(p * 32) * K);
        cp_async16(bB[0] + so[p], Bg + (size_t)(p * 32) * K);
    }
    cp_commit();

    for (int c = 0; c < nk; c++) {
        if (c + 1 < nk) {
            const int ko = (c + 1) << 5;
            const int nb = (c + 1) & 1;
#pragma unroll
            for (int p = 0; p < 4; p++) {
                cp_async16(aB[nb] + so[p], Ag + (size_t)(p * 32) * K + ko);
                cp_async16(bB[nb] + so[p], Bg + (size_t)(p * 32) * K + ko);
            }
            cp_commit();
            asm volatile("cp.async.wait_group 1;" ::: "memory");
        } else {
            asm volatile("cp.async.wait_group 0;" ::: "memory");
        }
        __syncthreads();

        const uint32_t aBase = aB[c & 1] + aMap;
        const uint32_t bBase = bB[c & 1] + bMap;
#pragma unroll
        for (int ks = 0; ks < 4; ks++) {
            uint32_t afr[4][4], bfr[4][2];
#pragma unroll
            for (int mf = 0; mf < 4; mf++)
                ldsm_x4(afr[mf][0], afr[mf][1], afr[mf][2], afr[mf][3],
                        aBase + (uint32_t)((mf * 16 * GP + ks * 8) * 4));
#pragma unroll
            for (int p = 0; p < 2; p++)
                ldsm_x4(bfr[2 * p][0], bfr[2 * p][1],
                        bfr[2 * p + 1][0], bfr[2 * p + 1][1],
                        bBase + (uint32_t)((p * 16 * GP + ks * 8) * 4));
#pragma unroll
            for (int mf = 0; mf < 4; mf++)
#pragma unroll
                for (int nf = 0; nf < 4; nf++)
                    mma_tf32(acc[mf][nf], afr[mf], bfr[nf][0], bfr[nf][1]);
        }
        __syncthreads();
    }

#pragma unroll
    for (int mf = 0; mf < 4; mf++) {
        const int row0 = bm + wm + mf * 16 + gid;
#pragma unroll
        for (int nf = 0; nf < 4; nf++) {
            const int col = bn + wn + nf * 8 + 2 * tig;
            float2 v0 = make_float2(acc[mf][nf][0], acc[mf][nf][1]);
            float2 v1 = make_float2(acc[mf][nf][2], acc[mf][nf][3]);
            const size_t i0 = (size_t)row0 * N + col;
            const size_t i1 = (size_t)(row0 + 8) * N + col;
            if (EPI == 0) {
                v0.x = tf32r(v0.x); v0.y = tf32r(v0.y);
                v1.x = tf32r(v1.x); v1.y = tf32r(v1.y);
            }
            if (EPI == 1) {
                const float2 r0 = *(const float2*)(res + i0);
                const float2 r1 = *(const float2*)(res + i1);
                v0.x += r0.x; v0.y += r0.y;
                v1.x += r1.x; v1.y += r1.y;
            }
            if (EPI == 2) {
                v0.x = tf32r(gelu_f(v0.x)); v0.y = tf32r(gelu_f(v0.y));
                v1.x = tf32r(gelu_f(v1.x)); v1.y = tf32r(gelu_f(v1.y));
            }
            *(float2*)(C + i0) = v0;
            *(float2*)(C + i1) = v1;
        }
    }
}

// ---------------------------------------------------------------------------
// Flash attention with tf32 mma.sync (R7 version — best measured).
// Grid: (T/64, B*H), 128 threads (4 warps). Warp w owns query rows w*16..+15.
// ---------------------------------------------------------------------------
#define AP 68
#define SMEM_ATTN (4 * 64 * AP * 4)

__global__ __launch_bounds__(128)
void attn_mma(const float* __restrict__ qkv, float* __restrict__ y)
{
    extern __shared__ float smA[];
    float* Qs = smA;
    float* Ks = smA + 64 * AP;
    float* Vt = smA + 2 * 64 * AP;
    float* Ps = smA + 3 * 64 * AP;

    const int qb   = gridDim.x - 1 - blockIdx.x;   // heavy tiles first
    const int b    = blockIdx.y >> 4;
    const int h    = blockIdx.y & 15;
    const int tid  = threadIdx.x;
    const int wid  = tid >> 5, lane = tid & 31;
    const int gid  = lane >> 2, tig = lane & 3;
    const int r0   = wid * 16 + gid;

    const float* base = qkv + (size_t)b * TDIM * QKVW + h * HD;

    const int lr  = tid & 63;
    const int lch = (tid >> 6) << 5;
    {
        const float* src = base + (size_t)(qb * 64 + lr) * QKVW + lch;
        float* dst = &Qs[lr * AP + lch];
#pragma unroll
        for (int i = 0; i < 8; i++) {
            float4 v = ((const float4*)src)[i];
            v.x *= 0.125f; v.y *= 0.125f; v.z *= 0.125f; v.w *= 0.125f;
            *(float4*)(dst + 4 * i) = v;
        }
    }

    float oacc[8][4];
#pragma unroll
    for (int nf = 0; nf < 8; nf++)
#pragma unroll
        for (int q = 0; q < 4; q++) oacc[nf][q] = 0.f;
    float m0 = -1e30f, m1 = -1e30f, l0 = 0.f, l1 = 0.f;

    for (int kb = 0; kb <= qb; kb++) {
        __syncthreads();
        {
            const float* ksrc = base + CDIM     + (size_t)(kb * 64 + lr) * QKVW + lch;
            const float* vsrc = base + 2 * CDIM + (size_t)(kb * 64 + lr) * QKVW + lch;
#pragma unroll
            for (int i = 0; i < 8; i++) {
                *(float4*)&Ks[lr * AP + lch + 4 * i] = ((const float4*)ksrc)[i];
                const float4 vv = ((const float4*)vsrc)[i];
                const int d = lch + 4 * i;
                Vt[(d + 0) * AP + lr] = vv.x;
                Vt[(d + 1) * AP + lr] = vv.y;
                Vt[(d + 2) * AP + lr] = vv.z;
                Vt[(d + 3) * AP + lr] = vv.w;
            }
        }
        __syncthreads();

        float sacc[8][4];
#pragma unroll
        for (int nf = 0; nf < 8; nf++)
#pragma unroll
            for (int q = 0; q < 4; q++) sacc[nf][q] = 0.f;
#pragma unroll
        for (int ks = 0; ks < 8; ks++) {
            const int k0 = ks * 8;
            uint32_t a[4];
            a[0] = __float_as_uint(Qs[(r0)     * AP + k0 + tig]);
            a[1] = __float_as_uint(Qs[(r0 + 8) * AP + k0 + tig]);
            a[2] = __float_as_uint(Qs[(r0)     * AP + k0 + tig + 4]);
            a[3] = __float_as_uint(Qs[(r0 + 8) * AP + k0 + tig + 4]);
#pragma unroll
            for (int nf = 0; nf < 8; nf++) {
                const uint32_t b0 = __float_as_uint(Ks[(nf * 8 + gid) * AP + k0 + tig]);
                const uint32_t b1 = __float_as_uint(Ks[(nf * 8 + gid) * AP + k0 + tig + 4]);
                mma_tf32(sacc[nf], a, b0, b1);
            }
        }

        if (kb == qb) {
#pragma unroll
            for (int nf = 0; nf < 8; nf++) {
                const int c0 = nf * 8 + 2 * tig;
                if (c0     > r0)     sacc[nf][0] = -1e30f;
                if (c0 + 1 > r0)     sacc[nf][1] = -1e30f;
                if (c0     > r0 + 8) sacc[nf][2] = -1e30f;
                if (c0 + 1 > r0 + 8) sacc[nf][3] = -1e30f;
            }
        }

        float mx0 = -1e30f, mx1 = -1e30f;
#pragma unroll
        for (int nf = 0; nf < 8; nf++) {
            mx0 = fmaxf(mx0, fmaxf(sacc[nf][0], sacc[nf][1]));
            mx1 = fmaxf(mx1, fmaxf(sacc[nf][2], sacc[nf][3]));
        }
        mx0 = fmaxf(mx0, __shfl_xor_sync(0xffffffffu, mx0, 1));
        mx0 = fmaxf(mx0, __shfl_xor_sync(0xffffffffu, mx0, 2));
        mx1 = fmaxf(mx1, __shfl_xor_sync(0xffffffffu, mx1, 1));
        mx1 = fmaxf(mx1, __shfl_xor_sync(0xffffffffu, mx1, 2));
        const float mn0 = fmaxf(m0, mx0), mn1 = fmaxf(m1, mx1);
        const float al0 = __expf(m0 - mn0), al1 = __expf(m1 - mn1);
        float rs0 = 0.f, rs1 = 0.f;
#pragma unroll
        for (int nf = 0; nf < 8; nf++) {
            const float p0 = tf32r(__expf(sacc[nf][0] - mn0));
            const float p1 = tf32r(__expf(sacc[nf][1] - mn0));
            const float p2 = tf32r(__expf(sacc[nf][2] - mn1));
            const float p3 = tf32r(__expf(sacc[nf][3] - mn1));
            rs0 += p0 + p1;
            rs1 += p2 + p3;
            const int c = nf * 8 + 2 * tig;
            *(float2*)&Ps[(r0)     * AP + c] = make_float2(p0, p1);
            *(float2*)&Ps[(r0 + 8) * AP + c] = make_float2(p2, p3);
        }
        rs0 += __shfl_xor_sync(0xffffffffu, rs0, 1);
        rs0 += __shfl_xor_sync(0xffffffffu, rs0, 2);
        rs1 += __shfl_xor_sync(0xffffffffu, rs1, 1);
        rs1 += __shfl_xor_sync(0xffffffffu, rs1, 2);
        l0 = l0 * al0 + rs0;  m0 = mn0;
        l1 = l1 * al1 + rs1;  m1 = mn1;
#pragma unroll
        for (int nf = 0; nf < 8; nf++) {
            oacc[nf][0] *= al0; oacc[nf][1] *= al0;
            oacc[nf][2] *= al1; oacc[nf][3] *= al1;
        }
        __syncwarp();

#pragma unroll
        for (int ks = 0; ks < 8; ks++) {
            const int k0 = ks * 8;
            uint32_t a[4];
            a[0] = __float_as_uint(Ps[(r0)     * AP + k0 + tig]);
            a[1] = __float_as_uint(Ps[(r0 + 8) * AP + k0 + tig]);
            a[2] = __float_as_uint(Ps[(r0)     * AP + k0 + tig + 4]);
            a[3] = __float_as_uint(Ps[(r0 + 8) * AP + k0 + tig + 4]);
#pragma unroll
            for (int nf = 0; nf < 8; nf++) {
                const uint32_t b0 = __float_as_uint(Vt[(nf * 8 + gid) * AP + k0 + tig]);
                const uint32_t b1 = __float_as_uint(Vt[(nf * 8 + gid) * AP + k0 + tig + 4]);
                mma_tf32(oacc[nf], a, b0, b1);
            }
        }
    }

    const float inv0 = 1.0f / l0, inv1 = 1.0f / l1;
    float* dst0 = y + (size_t)(b * TDIM + qb * 64 + r0) * CDIM + h * HD;
    float* dst1 = dst0 + 8 * CDIM;
#pragma unroll
    for (int nf = 0; nf < 8; nf++) {
        const int c = nf * 8 + 2 * tig;
        *(float2*)(dst0 + c) = make_float2(tf32r(oacc[nf][0] * inv0),
                                           tf32r(oacc[nf][1] * inv0));
        *(float2*)(dst1 + c) = make_float2(tf32r(oacc[nf][2] * inv1),
                                           tf32r(oacc[nf][3] * inv1));
    }
}

// ---------------------------------------------------------------------------
// Launch orchestration (graph-capturable)
// ---------------------------------------------------------------------------
extern "C" void kernel_launch(void* const* d_in, const int* in_sizes, int n_in,
                              void* d_out, int out_size)
{
    const float* x      = (const float*)d_in[0];
    const float* g1     = (const float*)d_in[1];
    const float* w_qkv  = (const float*)d_in[2];
    const float* w_o    = (const float*)d_in[3];
    const float* g2     = (const float*)d_in[4];
    const float* w_fc   = (const float*)d_in[5];
    const float* w_proj = (const float*)d_in[6];
    float* out = (float*)d_out;

    float *ln, *qkvb, *yb, *x2, *hb, *wq, *wo, *wfc, *wp;
    cudaGetSymbolAddress((void**)&ln,   g_ln);
    cudaGetSymbolAddress((void**)&qkvb, g_qkv);
    cudaGetSymbolAddress((void**)&yb,   g_y);
    cudaGetSymbolAddress((void**)&x2,   g_x2);
    cudaGetSymbolAddress((void**)&hb,   g_h);
    cudaGetSymbolAddress((void**)&wq,   g_wq);
    cudaGetSymbolAddress((void**)&wo,   g_wo);
    cudaGetSymbolAddress((void**)&wfc,  g_wfc);
    cudaGetSymbolAddress((void**)&wp,   g_wp);

    cudaFuncSetAttribute(attn_mma,
                         cudaFuncAttributeMaxDynamicSharedMemorySize, SMEM_ATTN);
    cudaFuncSetAttribute(gemm_v6<0>,
                         cudaFuncAttributeMaxDynamicSharedMemorySize, GSMEM2);
    cudaFuncSetAttribute(gemm_v6<1>,
                         cudaFuncAttributeMaxDynamicSharedMemorySize, GSMEM2);
    cudaFuncSetAttribute(gemm_v6<2>,
                         cudaFuncAttributeMaxDynamicSharedMemorySize, GSMEM2);

    // Round weights to tf32 once per launch
    round_tf32_kernel<<<(QKVW * CDIM / 4 + 255) / 256, 256>>>(w_qkv, wq,
                                                              QKVW * CDIM / 4);
    round_tf32_kernel<<<(CDIM * CDIM / 4 + 255) / 256, 256>>>(w_o, wo,
                                                              CDIM * CDIM / 4);
    round_tf32_kernel<<<(FFDIM * CDIM / 4 + 255) / 256, 256>>>(w_fc, wfc,
                                                               FFDIM * CDIM / 4);
    round_tf32_kernel<<<(CDIM * FFDIM / 4 + 255) / 256, 256>>>(w_proj, wp,
                                                               CDIM * FFDIM / 4);

    // x1 = ln1(x); qkv = x1 @ Wqkv^T  (output rounded)
    ln_kernel<<<BT, 256>>>(x, g1, ln);
    gemm_v6<0><<<dim3(QKVW / 128, BT / 128), 256, GSMEM2>>>(
        ln, wq, nullptr, qkvb, BT, QKVW, CDIM);
    // y = causal attention (tf32 mma; output rounded)
    attn_mma<<<dim3(TDIM / 64, BDIM * HEADS), 128, SMEM_ATTN>>>(qkvb, yb);
    // x2 = x + y @ Wo^T
    gemm_v6<1><<<dim3(CDIM / 128, BT / 128), 256, GSMEM2>>>(
        yb, wo, x, x2, BT, CDIM, CDIM);
    // h = gelu(ln2(x2) @ Wfc^T)  (output rounded)
    ln_kernel<<<BT, 256>>>(x2, g2, ln);
    gemm_v6<2><<<dim3(FFDIM / 128, BT / 128), 256, GSMEM2>>>(
        ln, wfc, nullptr, hb, BT, FFDIM, CDIM);
    // out = x2 + h @ Wproj^T
    gemm_v6<1><<<dim3(CDIM / 128, BT / 128), 256, GSMEM2>>>(
        hb, wp, x2, out, BT, CDIM, FFDIM);
}

// round 10
// speedup vs baseline: 1.0297x; 1.0297x over previous
#include <cuda_runtime.h>
#include <math.h>
#include <stdint.h>

// Problem constants
#define BDIM   4
#define TDIM   2048
#define CDIM   1024
#define HEADS  16
#define HD     64
#define FFDIM  4096
#define BT     8192            // B*T rows
#define QKVW   3072            // 3*C

// ---------------------------------------------------------------------------
// Scratch (no allocations allowed — __device__ globals)
// ---------------------------------------------------------------------------
__device__ float g_ln [BT * CDIM];
__device__ float g_qkv[BT * QKVW];
__device__ float g_y  [BT * CDIM];
__device__ float g_x2 [BT * CDIM];
__device__ float g_h  [BT * FFDIM];
// tf32-rounded weights
__device__ float g_wq [QKVW * CDIM];
__device__ float g_wo [CDIM * CDIM];
__device__ float g_wfc[FFDIM * CDIM];
__device__ float g_wp [CDIM * FFDIM];

// ---------------------------------------------------------------------------
// Helpers
// ---------------------------------------------------------------------------
__device__ __forceinline__ uint32_t f2tf32(float f) {
    uint32_t u;
    asm("cvt.rna.tf32.f32 %0, %1;" : "=r"(u) : "f"(f));
    return u;
}
__device__ __forceinline__ float tf32r(float f) {
    return __uint_as_float(f2tf32(f));
}
__device__ __forceinline__ uint32_t smem_u32(const void* p) {
    uint32_t a;
    asm("{ .reg .u64 t; cvta.to.shared.u64 t, %1; cvt.u32.u64 %0, t; }"
        : "=r"(a) : "l"(p));
    return a;
}
__device__ __forceinline__ void cp_async16(uint32_t saddr, const void* gaddr) {
    asm volatile("cp.async.cg.shared.global [%0], [%1], 16;"
                 :: "r"(saddr), "l"(gaddr) : "memory");
}
__device__ __forceinline__ void cp_commit() {
    asm volatile("cp.async.commit_group;" ::: "memory");
}
__device__ __forceinline__ void ldsm_x4(uint32_t& r0, uint32_t& r1,
                                        uint32_t& r2, uint32_t& r3,
                                        uint32_t addr) {
    asm volatile("ldmatrix.sync.aligned.m8n8.x4.shared.b16 {%0,%1,%2,%3}, [%4];"
                 : "=r"(r0), "=r"(r1), "=r"(r2), "=r"(r3) : "r"(addr));
}
__device__ __forceinline__ void mma_tf32(float* d, const uint32_t* a,
                                         uint32_t b0, uint32_t b1) {
    asm volatile(
        "mma.sync.aligned.m16n8k8.row.col.f32.tf32.tf32.f32 "
        "{%0,%1,%2,%3}, {%4,%5,%6,%7}, {%8,%9}, {%0,%1,%2,%3};"
        : "+f"(d[0]), "+f"(d[1]), "+f"(d[2]), "+f"(d[3])
        : "r"(a[0]), "r"(a[1]), "r"(a[2]), "r"(a[3]), "r"(b0), "r"(b1));
}
__device__ __forceinline__ float gelu_f(float v) {
    return 0.5f * v * (1.0f + erff(v * 0.70710678118654752f));
}

// ---------------------------------------------------------------------------
// Weight prep: round to tf32 once
// ---------------------------------------------------------------------------
__global__ __launch_bounds__(256)
void round_tf32_kernel(const float* __restrict__ src, float* __restrict__ dst,
                       int n4)
{
    const int i = blockIdx.x * blockDim.x + threadIdx.x;
    if (i < n4) {
        float4 v = ((const float4*)src)[i];
        v.x = tf32r(v.x); v.y = tf32r(v.y);
        v.z = tf32r(v.z); v.w = tf32r(v.w);
        ((float4*)dst)[i] = v;
    }
}

// ---------------------------------------------------------------------------
// LayerNorm: one block per row, C=1024, 256 threads x float4 (tf32 output)
// ---------------------------------------------------------------------------
__global__ __launch_bounds__(256)
void ln_kernel(const float* __restrict__ x, const float* __restrict__ g,
               float* __restrict__ y)
{
    const int row = blockIdx.x;
    const int tid = threadIdx.x;
    const float4 v = ((const float4*)(x + (size_t)row * CDIM))[tid];
    float s  = v.x + v.y + v.z + v.w;
    float ss = v.x * v.x + v.y * v.y + v.z * v.z + v.w * v.w;
#pragma unroll
    for (int o = 16; o > 0; o >>= 1) {
        s  += __shfl_xor_sync(0xffffffffu, s,  o);
        ss += __shfl_xor_sync(0xffffffffu, ss, o);
    }
    __shared__ float rs[8], rss[8];
    const int w = tid >> 5, lane = tid & 31;
    if (lane == 0) { rs[w] = s; rss[w] = ss; }
    __syncthreads();
    if (tid == 0) {
        float a = 0.f, b = 0.f;
#pragma unroll
        for (int i = 0; i < 8; i++) { a += rs[i]; b += rss[i]; }
        const float mean = a * (1.0f / CDIM);
        const float var  = b * (1.0f / CDIM) - mean * mean;
        rs[0]  = mean;
        rss[0] = rsqrtf(var + 1e-5f);
    }
    __syncthreads();
    const float mean = rs[0], rstd = rss[0];
    const float4 gv = ((const float4*)g)[tid];
    float4 o4;
    o4.x = tf32r((v.x - mean) * rstd * gv.x);
    o4.y = tf32r((v.y - mean) * rstd * gv.y);
    o4.z = tf32r((v.z - mean) * rstd * gv.z);
    o4.w = tf32r((v.w - mean) * rstd * gv.w);
    ((float4*)(y + (size_t)row * CDIM))[tid] = o4;
}

// ---------------------------------------------------------------------------
// TF32 mma.sync GEMM v7 (NT): C[m,n] = sum_k A[m,k]*B[n,k]
// CTA 128x128, 128 threads (4 warps 2x2), warp tile 64x64, K-chunk 32,
// 2-stage cp.async double buffer, ldmatrix fragments SOFTWARE-PIPELINED
// over ks (load ks+1 fragments before issuing ks MMAs).
// EPI: 0 = round(acc), 1 = acc + res, 2 = round(gelu(acc)).
// ---------------------------------------------------------------------------
#define GP     36
#define TILE_F (128 * GP)
#define GSMEM2 (4 * TILE_F * 4)

template <int EPI>
__global__ __launch_bounds__(128, 2)
void gemm_v7(const float* __restrict__ A, const float* __restrict__ B,
             const float* __restrict__ res, float* __restrict__ C,
             int M, int N, int K)
{
    extern __shared__ float sm[];
    const uint32_t sb = smem_u32(sm);

    const int tid  = threadIdx.x;
    const int wid  = tid >> 5, lane = tid & 31;
    const int gid  = lane >> 2, tig = lane & 3;
    const int wm   = (wid & 1) << 6;     // 0 / 64 row slab
    const int wn   = (wid >> 1) << 6;    // 0 / 64 col slab
    const int bm   = blockIdx.y << 7, bn = blockIdx.x << 7;

    // cp.async map: 8 x 16B per operand tile per thread
    const int lr = tid >> 3;             // 0..15
    const int lc = (tid & 7) << 2;       // 0,4,...,28
    const float* Ag = A + (size_t)(bm + lr) * K + lc;
    const float* Bg = B + (size_t)(bn + lr) * K + lc;
    uint32_t so[8];
#pragma unroll
    for (int p = 0; p < 8; p++)
        so[p] = (uint32_t)((p * 16 + lr) * GP + lc) * 4u;

    const uint32_t aB[2] = { sb,                sb + 2u * TILE_F * 4u };
    const uint32_t bB[2] = { sb + TILE_F * 4u,  sb + 3u * TILE_F * 4u };

    // ldmatrix lane->address maps (byte offsets within a tile buffer)
    const int aRow = wm + (lane & 7) + ((lane >> 3) & 1) * 8;
    const uint32_t aMap = (uint32_t)(aRow * GP + (lane >> 4) * 4) * 4u;
    const int bRow = wn + (lane >> 4) * 8 + (lane & 7);
    const uint32_t bMap = (uint32_t)(bRow * GP + ((lane >> 3) & 1) * 4) * 4u;

    float acc[4][8][4];
#pragma unroll
    for (int i = 0; i < 4; i++)
#pragma unroll
        for (int j = 0; j < 8; j++)
#pragma unroll
            for (int q = 0; q < 4; q++) acc[i][j][q] = 0.f;

    const int nk = K >> 5;

#pragma unroll
    for (int p = 0; p < 8; p++) {
        cp_async16(aB[0] + so[p], Ag + (size_t)(p * 16) * K);
        cp_async16(bB[0] + so[p], Bg + (size_t)(p * 16) * K);
    }
    cp_commit();

    // Double-buffered fragment registers (ks-level software pipeline)
    uint32_t afr[2][4][4], bfr[2][8][2];

    for (int c = 0; c < nk; c++) {
        if (c + 1 < nk) {
            const int ko = (c + 1) << 5;
            const int nb = (c + 1) & 1;
#pragma unroll
            for (int p = 0; p < 8; p++) {
                cp_async16(aB[nb] + so[p], Ag + (size_t)(p * 16) * K + ko);
                cp_async16(bB[nb] + so[p], Bg + (size_t)(p * 16) * K + ko);
            }
            cp_commit();
            asm volatile("cp.async.wait_group 1;" ::: "memory");
        } else {
            asm volatile("cp.async.wait_group 0;" ::: "memory");
        }
        __syncthreads();

        const uint32_t aBase = aB[c & 1] + aMap;
        const uint32_t bBase = bB[c & 1] + bMap;

        // Prime fragments for ks = 0
#pragma unroll
        for (int mf = 0; mf < 4; mf++)
            ldsm_x4(afr[0][mf][0], afr[0][mf][1], afr[0][mf][2], afr[0][mf][3],
                    aBase + (uint32_t)((mf * 16 * GP) * 4));
#pragma unroll
        for (int p = 0; p < 4; p++)
            ldsm_x4(bfr[0][2 * p][0], bfr[0][2 * p][1],
                    bfr[0][2 * p + 1][0], bfr[0][2 * p + 1][1],
                    bBase + (uint32_t)((p * 16 * GP) * 4));

#pragma unroll
        for (int ks = 0; ks < 4; ks++) {
            const int cur = ks & 1, nxt = cur ^ 1;
            if (ks < 3) {   // prefetch fragments for ks+1 before MMA block
#pragma unroll
                for (int mf = 0; mf < 4; mf++)
                    ldsm_x4(afr[nxt][mf][0], afr[nxt][mf][1],
                            afr[nxt][mf][2], afr[nxt][mf][3],
                            aBase + (uint32_t)((mf * 16 * GP + (ks + 1) * 8) * 4));
#pragma unroll
                for (int p = 0; p < 4; p++)
                    ldsm_x4(bfr[nxt][2 * p][0], bfr[nxt][2 * p][1],
                            bfr[nxt][2 * p + 1][0], bfr[nxt][2 * p + 1][1],
                            bBase + (uint32_t)((p * 16 * GP + (ks + 1) * 8) * 4));
            }
#pragma unroll
            for (int mf = 0; mf < 4; mf++)
#pragma unroll
                for (int nf = 0; nf < 8; nf++)
                    mma_tf32(acc[mf][nf], afr[cur][mf],
                             bfr[cur][nf][0], bfr[cur][nf][1]);
        }
        __syncthreads();
    }

#pragma unroll
    for (int mf = 0; mf < 4; mf++) {
        const int row0 = bm + wm + mf * 16 + gid;
#pragma unroll
        for (int nf = 0; nf < 8; nf++) {
            const int col = bn + wn + nf * 8 + 2 * tig;
            float2 v0 = make_float2(acc[mf][nf][0], acc[mf][nf][1]);
            float2 v1 = make_float2(acc[mf][nf][2], acc[mf][nf][3]);
            const size_t i0 = (size_t)row0 * N + col;
            const size_t i1 = (size_t)(row0 + 8) * N + col;
            if (EPI == 0) {
                v0.x = tf32r(v0.x); v0.y = tf32r(v0.y);
                v1.x = tf32r(v1.x); v1.y = tf32r(v1.y);
            }
            if (EPI == 1) {
                const float2 r0 = *(const float2*)(res + i0);
                const float2 r1 = *(const float2*)(res + i1);
                v0.x += r0.x; v0.y += r0.y;
                v1.x += r1.x; v1.y += r1.y;
            }
            if (EPI == 2) {
                v0.x = tf32r(gelu_f(v0.x)); v0.y = tf32r(gelu_f(v0.y));
                v1.x = tf32r(gelu_f(v1.x)); v1.y = tf32r(gelu_f(v1.y));
            }
            *(float2*)(C + i0) = v0;
            *(float2*)(C + i1) = v1;
        }
    }
}

// ---------------------------------------------------------------------------
// Flash attention with tf32 mma.sync (R7 version — best measured).
// Grid: (T/64, B*H), 128 threads (4 warps). Warp w owns query rows w*16..+15.
// ---------------------------------------------------------------------------
#define AP 68
#define SMEM_ATTN (4 * 64 * AP * 4)

__global__ __launch_bounds__(128)
void attn_mma(const float* __restrict__ qkv, float* __restrict__ y)
{
    extern __shared__ float smA[];
    float* Qs = smA;
    float* Ks = smA + 64 * AP;
    float* Vt = smA + 2 * 64 * AP;
    float* Ps = smA + 3 * 64 * AP;

    const int qb   = gridDim.x - 1 - blockIdx.x;   // heavy tiles first
    const int b    = blockIdx.y >> 4;
    const int h    = blockIdx.y & 15;
    const int tid  = threadIdx.x;
    const int wid  = tid >> 5, lane = tid & 31;
    const int gid  = lane >> 2, tig = lane & 3;
    const int r0   = wid * 16 + gid;

    const float* base = qkv + (size_t)b * TDIM * QKVW + h * HD;

    const int lr  = tid & 63;
    const int lch = (tid >> 6) << 5;
    {
        const float* src = base + (size_t)(qb * 64 + lr) * QKVW + lch;
        float* dst = &Qs[lr * AP + lch];
#pragma unroll
        for (int i = 0; i < 8; i++) {
            float4 v = ((const float4*)src)[i];
            v.x *= 0.125f; v.y *= 0.125f; v.z *= 0.125f; v.w *= 0.125f;
            *(float4*)(dst + 4 * i) = v;
        }
    }

    float oacc[8][4];
#pragma unroll
    for (int nf = 0; nf < 8; nf++)
#pragma unroll
        for (int q = 0; q < 4; q++) oacc[nf][q] = 0.f;
    float m0 = -1e30f, m1 = -1e30f, l0 = 0.f, l1 = 0.f;

    for (int kb = 0; kb <= qb; kb++) {
        __syncthreads();
        {
            const float* ksrc = base + CDIM     + (size_t)(kb * 64 + lr) * QKVW + lch;
            const float* vsrc = base + 2 * CDIM + (size_t)(kb * 64 + lr) * QKVW + lch;
#pragma unroll
            for (int i = 0; i < 8; i++) {
                *(float4*)&Ks[lr * AP + lch + 4 * i] = ((const float4*)ksrc)[i];
                const float4 vv = ((const float4*)vsrc)[i];
                const int d = lch + 4 * i;
                Vt[(d + 0) * AP + lr] = vv.x;
                Vt[(d + 1) * AP + lr] = vv.y;
                Vt[(d + 2) * AP + lr] = vv.z;
                Vt[(d + 3) * AP + lr] = vv.w;
            }
        }
        __syncthreads();

        float sacc[8][4];
#pragma unroll
        for (int nf = 0; nf < 8; nf++)
#pragma unroll
            for (int q = 0; q < 4; q++) sacc[nf][q] = 0.f;
#pragma unroll
        for (int ks = 0; ks < 8; ks++) {
            const int k0 = ks * 8;
            uint32_t a[4];
            a[0] = __float_as_uint(Qs[(r0)     * AP + k0 + tig]);
            a[1] = __float_as_uint(Qs[(r0 + 8) * AP + k0 + tig]);
            a[2] = __float_as_uint(Qs[(r0)     * AP + k0 + tig + 4]);
            a[3] = __float_as_uint(Qs[(r0 + 8) * AP + k0 + tig + 4]);
#pragma unroll
            for (int nf = 0; nf < 8; nf++) {
                const uint32_t b0 = __float_as_uint(Ks[(nf * 8 + gid) * AP + k0 + tig]);
                const uint32_t b1 = __float_as_uint(Ks[(nf * 8 + gid) * AP + k0 + tig + 4]);
                mma_tf32(sacc[nf], a, b0, b1);
            }
        }

        if (kb == qb) {
#pragma unroll
            for (int nf = 0; nf < 8; nf++) {
                const int c0 = nf * 8 + 2 * tig;
                if (c0     > r0)     sacc[nf][0] = -1e30f;
                if (c0 + 1 > r0)     sacc[nf][1] = -1e30f;
                if (c0     > r0 + 8) sacc[nf][2] = -1e30f;
                if (c0 + 1 > r0 + 8) sacc[nf][3] = -1e30f;
            }
        }

        float mx0 = -1e30f, mx1 = -1e30f;
#pragma unroll
        for (int nf = 0; nf < 8; nf++) {
            mx0 = fmaxf(mx0, fmaxf(sacc[nf][0], sacc[nf][1]));
            mx1 = fmaxf(mx1, fmaxf(sacc[nf][2], sacc[nf][3]));
        }
        mx0 = fmaxf(mx0, __shfl_xor_sync(0xffffffffu, mx0, 1));
        mx0 = fmaxf(mx0, __shfl_xor_sync(0xffffffffu, mx0, 2));
        mx1 = fmaxf(mx1, __shfl_xor_sync(0xffffffffu, mx1, 1));
        mx1 = fmaxf(mx1, __shfl_xor_sync(0xffffffffu, mx1, 2));
        const float mn0 = fmaxf(m0, mx0), mn1 = fmaxf(m1, mx1);
        const float al0 = __expf(m0 - mn0), al1 = __expf(m1 - mn1);
        float rs0 = 0.f, rs1 = 0.f;
#pragma unroll
        for (int nf = 0; nf < 8; nf++) {
            const float p0 = tf32r(__expf(sacc[nf][0] - mn0));
            const float p1 = tf32r(__expf(sacc[nf][1] - mn0));
            const float p2 = tf32r(__expf(sacc[nf][2] - mn1));
            const float p3 = tf32r(__expf(sacc[nf][3] - mn1));
            rs0 += p0 + p1;
            rs1 += p2 + p3;
            const int c = nf * 8 + 2 * tig;
            *(float2*)&Ps[(r0)     * AP + c] = make_float2(p0, p1);
            *(float2*)&Ps[(r0 + 8) * AP + c] = make_float2(p2, p3);
        }
        rs0 += __shfl_xor_sync(0xffffffffu, rs0, 1);
        rs0 += __shfl_xor_sync(0xffffffffu, rs0, 2);
        rs1 += __shfl_xor_sync(0xffffffffu, rs1, 1);
        rs1 += __shfl_xor_sync(0xffffffffu, rs1, 2);
        l0 = l0 * al0 + rs0;  m0 = mn0;
        l1 = l1 * al1 + rs1;  m1 = mn1;
#pragma unroll
        for (int nf = 0; nf < 8; nf++) {
            oacc[nf][0] *= al0; oacc[nf][1] *= al0;
            oacc[nf][2] *= al1; oacc[nf][3] *= al1;
        }
        __syncwarp();

#pragma unroll
        for (int ks = 0; ks < 8; ks++) {
            const int k0 = ks * 8;
            uint32_t a[4];
            a[0] = __float_as_uint(Ps[(r0)     * AP + k0 + tig]);
            a[1] = __float_as_uint(Ps[(r0 + 8) * AP + k0 + tig]);
            a[2] = __float_as_uint(Ps[(r0)     * AP + k0 + tig + 4]);
            a[3] = __float_as_uint(Ps[(r0 + 8) * AP + k0 + tig + 4]);
#pragma unroll
            for (int nf = 0; nf < 8; nf++) {
                const uint32_t b0 = __float_as_uint(Vt[(nf * 8 + gid) * AP + k0 + tig]);
                const uint32_t b1 = __float_as_uint(Vt[(nf * 8 + gid) * AP + k0 + tig + 4]);
                mma_tf32(oacc[nf], a, b0, b1);
            }
        }
    }

    const float inv0 = 1.0f / l0, inv1 = 1.0f / l1;
    float* dst0 = y + (size_t)(b * TDIM + qb * 64 + r0) * CDIM + h * HD;
    float* dst1 = dst0 + 8 * CDIM;
#pragma unroll
    for (int nf = 0; nf < 8; nf++) {
        const int c = nf * 8 + 2 * tig;
        *(float2*)(dst0 + c) = make_float2(tf32r(oacc[nf][0] * inv0),
                                           tf32r(oacc[nf][1] * inv0));
        *(float2*)(dst1 + c) = make_float2(tf32r(oacc[nf][2] * inv1),
                                           tf32r(oacc[nf][3] * inv1));
    }
}

// ---------------------------------------------------------------------------
// Launch orchestration (graph-capturable)
// ---------------------------------------------------------------------------
extern "C" void kernel_launch(void* const* d_in, const int* in_sizes, int n_in,
                              void* d_out, int out_size)
{
    const float* x      = (const float*)d_in[0];
    const float* g1     = (const float*)d_in[1];
    const float* w_qkv  = (const float*)d_in[2];
    const float* w_o    = (const float*)d_in[3];
    const float* g2     = (const float*)d_in[4];
    const float* w_fc   = (const float*)d_in[5];
    const float* w_proj = (const float*)d_in[6];
    float* out = (float*)d_out;

    float *ln, *qkvb, *yb, *x2, *hb, *wq, *wo, *wfc, *wp;
    cudaGetSymbolAddress((void**)&ln,   g_ln);
    cudaGetSymbolAddress((void**)&qkvb, g_qkv);
    cudaGetSymbolAddress((void**)&yb,   g_y);
    cudaGetSymbolAddress((void**)&x2,   g_x2);
    cudaGetSymbolAddress((void**)&hb,   g_h);
    cudaGetSymbolAddress((void**)&wq,   g_wq);
    cudaGetSymbolAddress((void**)&wo,   g_wo);
    cudaGetSymbolAddress((void**)&wfc,  g_wfc);
    cudaGetSymbolAddress((void**)&wp,   g_wp);

    cudaFuncSetAttribute(attn_mma,
                         cudaFuncAttributeMaxDynamicSharedMemorySize, SMEM_ATTN);
    cudaFuncSetAttribute(gemm_v7<0>,
                         cudaFuncAttributeMaxDynamicSharedMemorySize, GSMEM2);
    cudaFuncSetAttribute(gemm_v7<1>,
                         cudaFuncAttributeMaxDynamicSharedMemorySize, GSMEM2);
    cudaFuncSetAttribute(gemm_v7<2>,
                         cudaFuncAttributeMaxDynamicSharedMemorySize, GSMEM2);

    // Round weights to tf32 once per launch
    round_tf32_kernel<<<(QKVW * CDIM / 4 + 255) / 256, 256>>>(w_qkv, wq,
                                                              QKVW * CDIM / 4);
    round_tf32_kernel<<<(CDIM * CDIM / 4 + 255) / 256, 256>>>(w_o, wo,
                                                              CDIM * CDIM / 4);
    round_tf32_kernel<<<(FFDIM * CDIM / 4 + 255) / 256, 256>>>(w_fc, wfc,
                                                               FFDIM * CDIM / 4);
    round_tf32_kernel<<<(CDIM * FFDIM / 4 + 255) / 256, 256>>>(w_proj, wp,
                                                               CDIM * FFDIM / 4);

    // x1 = ln1(x); qkv = x1 @ Wqkv^T  (output rounded)
    ln_kernel<<<BT, 256>>>(x, g1, ln);
    gemm_v7<0><<<dim3(QKVW / 128, BT / 128), 128, GSMEM2>>>(
        ln, wq, nullptr, qkvb, BT, QKVW, CDIM);
    // y = causal attention (tf32 mma; output rounded)
    attn_mma<<<dim3(TDIM / 64, BDIM * HEADS), 128, SMEM_ATTN>>>(qkvb, yb);
    // x2 = x + y @ Wo^T
    gemm_v7<1><<<dim3(CDIM / 128, BT / 128), 128, GSMEM2>>>(
        yb, wo, x, x2, BT, CDIM, CDIM);
    // h = gelu(ln2(x2) @ Wfc^T)  (output rounded)
    ln_kernel<<<BT, 256>>>(x2, g2, ln);
    gemm_v7<2><<<dim3(FFDIM / 128, BT / 128), 128, GSMEM2>>>(
        ln, wfc, nullptr, hb, BT, FFDIM, CDIM);
    // out = x2 + h @ Wproj^T
    gemm_v7<1><<<dim3(CDIM / 128, BT / 128), 128, GSMEM2>>>(
        hb, wp, x2, out, BT, CDIM, FFDIM);
}

// round 11
// speedup vs baseline: 2.0158x; 1.9577x over previous
#include <cuda_runtime.h>
#include <cuda_fp16.h>
#include <math.h>
#include <stdint.h>

// Problem constants
#define BDIM   4
#define TDIM   2048
#define CDIM   1024
#define HEADS  16
#define HD     64
#define FFDIM  4096
#define BT     8192            // B*T rows
#define QKVW   3072            // 3*C

// ---------------------------------------------------------------------------
// Scratch (no allocations allowed — __device__ globals)
// ---------------------------------------------------------------------------
__device__ __half g_ln [BT * CDIM];     // LN output (fp16, GEMM A operand)
__device__ __half g_qkv[BT * QKVW];     // QKV (fp16)
__device__ __half g_y  [BT * CDIM];     // attention out (fp16)
__device__ float  g_x2 [BT * CDIM];     // residual stream 2 (fp32)
__device__ __half g_h  [BT * FFDIM];    // gelu(fc) (fp16)
// fp16 weights
__device__ __half g_wq [QKVW * CDIM];
__device__ __half g_wo [CDIM * CDIM];
__device__ __half g_wfc[FFDIM * CDIM];
__device__ __half g_wp [CDIM * FFDIM];

// ---------------------------------------------------------------------------
// Helpers
// ---------------------------------------------------------------------------
__device__ __forceinline__ uint32_t smem_u32(const void* p) {
    uint32_t a;
    asm("{ .reg .u64 t; cvta.to.shared.u64 t, %1; cvt.u32.u64 %0, t; }"
        : "=r"(a) : "l"(p));
    return a;
}
__device__ __forceinline__ void cp_async16(uint32_t saddr, const void* gaddr) {
    asm volatile("cp.async.cg.shared.global [%0], [%1], 16;"
                 :: "r"(saddr), "l"(gaddr) : "memory");
}
__device__ __forceinline__ void cp_commit() {
    asm volatile("cp.async.commit_group;" ::: "memory");
}
__device__ __forceinline__ void ldsm_x4(uint32_t& r0, uint32_t& r1,
                                        uint32_t& r2, uint32_t& r3,
                                        uint32_t addr) {
    asm volatile("ldmatrix.sync.aligned.m8n8.x4.shared.b16 {%0,%1,%2,%3}, [%4];"
                 : "=r"(r0), "=r"(r1), "=r"(r2), "=r"(r3) : "r"(addr));
}
__device__ __forceinline__ void ldsm_x4_t(uint32_t& r0, uint32_t& r1,
                                          uint32_t& r2, uint32_t& r3,
                                          uint32_t addr) {
    asm volatile("ldmatrix.sync.aligned.m8n8.x4.trans.shared.b16 {%0,%1,%2,%3}, [%4];"
                 : "=r"(r0), "=r"(r1), "=r"(r2), "=r"(r3) : "r"(addr));
}
__device__ __forceinline__ void mma_f16(float* d, const uint32_t* a,
                                        uint32_t b0, uint32_t b1) {
    asm volatile(
        "mma.sync.aligned.m16n8k16.row.col.f32.f16.f16.f32 "
        "{%0,%1,%2,%3}, {%4,%5,%6,%7}, {%8,%9}, {%0,%1,%2,%3};"
        : "+f"(d[0]), "+f"(d[1]), "+f"(d[2]), "+f"(d[3])
        : "r"(a[0]), "r"(a[1]), "r"(a[2]), "r"(a[3]), "r"(b0), "r"(b1));
}
__device__ __forceinline__ float gelu_f(float v) {
    return 0.5f * v * (1.0f + erff(v * 0.70710678118654752f));
}

// ---------------------------------------------------------------------------
// Weight prep: fp32 -> fp16 (8 elements per thread)
// ---------------------------------------------------------------------------
__global__ __launch_bounds__(256)
void round_fp16_kernel(const float* __restrict__ src, __half* __restrict__ dst,
                       int n8)
{
    const int i = blockIdx.x * blockDim.x + threadIdx.x;
    if (i < n8) {
        const float4 v0 = ((const float4*)src)[2 * i];
        const float4 v1 = ((const float4*)src)[2 * i + 1];
        __half2 h[4];
        h[0] = __floats2half2_rn(v0.x, v0.y);
        h[1] = __floats2half2_rn(v0.z, v0.w);
        h[2] = __floats2half2_rn(v1.x, v1.y);
        h[3] = __floats2half2_rn(v1.z, v1.w);
        ((uint4*)dst)[i] = *(uint4*)h;
    }
}

// ---------------------------------------------------------------------------
// LayerNorm: one block per row, C=1024, 256 threads x float4 -> fp16 out
// ---------------------------------------------------------------------------
__global__ __launch_bounds__(256)
void ln_kernel(const float* __restrict__ x, const float* __restrict__ g,
               __half* __restrict__ y)
{
    const int row = blockIdx.x;
    const int tid = threadIdx.x;
    const float4 v = ((const float4*)(x + (size_t)row * CDIM))[tid];
    float s  = v.x + v.y + v.z + v.w;
    float ss = v.x * v.x + v.y * v.y + v.z * v.z + v.w * v.w;
#pragma unroll
    for (int o = 16; o > 0; o >>= 1) {
        s  += __shfl_xor_sync(0xffffffffu, s,  o);
        ss += __shfl_xor_sync(0xffffffffu, ss, o);
    }
    __shared__ float rs[8], rss[8];
    const int w = tid >> 5, lane = tid & 31;
    if (lane == 0) { rs[w] = s; rss[w] = ss; }
    __syncthreads();
    if (tid == 0) {
        float a = 0.f, b = 0.f;
#pragma unroll
        for (int i = 0; i < 8; i++) { a += rs[i]; b += rss[i]; }
        const float mean = a * (1.0f / CDIM);
        const float var  = b * (1.0f / CDIM) - mean * mean;
        rs[0]  = mean;
        rss[0] = rsqrtf(var + 1e-5f);
    }
    __syncthreads();
    const float mean = rs[0], rstd = rss[0];
    const float4 gv = ((const float4*)g)[tid];
    __half2 h0 = __floats2half2_rn((v.x - mean) * rstd * gv.x,
                                   (v.y - mean) * rstd * gv.y);
    __half2 h1 = __floats2half2_rn((v.z - mean) * rstd * gv.z,
                                   (v.w - mean) * rstd * gv.w);
    uint2 u;
    u.x = *(uint32_t*)&h0;
    u.y = *(uint32_t*)&h1;
    ((uint2*)(y + (size_t)row * CDIM))[tid] = u;
}

// ---------------------------------------------------------------------------
// FP16 mma.sync GEMM (NT): C[m,n] = sum_k A[m,k]*B[n,k]
// CTA 128x128, 128 threads (4 warps 2x2), warp tile 64x64, K-chunk 64 halves,
// 2-stage cp.async double buffer, ldmatrix fragments, m16n8k16 fp16 MMA
// (fp32 accumulate). EPI: 0 = fp16 out, 1 = acc + res (fp32 out),
// 2 = gelu (fp16 out).
// ---------------------------------------------------------------------------
#define KC      64
#define GPH     72                    // padded halves per row (144 B, 16B-mult)
#define TILE_H  (128 * GPH)
#define GSMEMH  (4 * TILE_H * 2)

template <int EPI>
__global__ __launch_bounds__(128, 2)
void gemm_h(const __half* __restrict__ A, const __half* __restrict__ B,
            const float* __restrict__ res, void* __restrict__ Cv,
            int M, int N, int K)
{
    extern __shared__ __half smh[];
    const uint32_t sb = smem_u32(smh);

    const int tid  = threadIdx.x;
    const int wid  = tid >> 5, lane = tid & 31;
    const int gid  = lane >> 2, tig = lane & 3;
    const int wm   = (wid & 1) << 6;     // 0 / 64 row slab
    const int wn   = (wid >> 1) << 6;    // 0 / 64 col slab
    const int bm   = blockIdx.y << 7, bn = blockIdx.x << 7;

    // cp.async map: 8 x 16B (8 halves) per operand tile per thread
    const int lr  = tid >> 3;            // 0..15
    const int lc8 = (tid & 7) << 3;      // half col 0,8,...,56
    const __half* Ag = A + (size_t)(bm + lr) * K + lc8;
    const __half* Bg = B + (size_t)(bn + lr) * K + lc8;
    uint32_t so[8];
#pragma unroll
    for (int p = 0; p < 8; p++)
        so[p] = (uint32_t)((p * 16 + lr) * GPH + lc8) * 2u;

    const uint32_t aB[2] = { sb,                 sb + 2u * TILE_H * 2u };
    const uint32_t bB[2] = { sb + TILE_H * 2u,   sb + 3u * TILE_H * 2u };

    // ldmatrix lane->address maps (byte offsets within a tile buffer)
    const int aRow = wm + (lane & 7) + ((lane >> 3) & 1) * 8;
    const uint32_t aMap = (uint32_t)aRow * (GPH * 2) + (lane >> 4) * 16;
    const int bRow = wn + (lane >> 4) * 8 + (lane & 7);
    const uint32_t bMap = (uint32_t)bRow * (GPH * 2) + ((lane >> 3) & 1) * 16;

    float acc[4][8][4];
#pragma unroll
    for (int i = 0; i < 4; i++)
#pragma unroll
        for (int j = 0; j < 8; j++)
#pragma unroll
            for (int q = 0; q < 4; q++) acc[i][j][q] = 0.f;

    const int nk = K / KC;

#pragma unroll
    for (int p = 0; p < 8; p++) {
        cp_async16(aB[0] + so[p], Ag + (size_t)(p * 16) * K);
        cp_async16(bB[0] + so[p], Bg + (size_t)(p * 16) * K);
    }
    cp_commit();

    for (int c = 0; c < nk; c++) {
        if (c + 1 < nk) {
            const int ko = (c + 1) * KC;
            const int nb = (c + 1) & 1;
#pragma unroll
            for (int p = 0; p < 8; p++) {
                cp_async16(aB[nb] + so[p], Ag + (size_t)(p * 16) * K + ko);
                cp_async16(bB[nb] + so[p], Bg + (size_t)(p * 16) * K + ko);
            }
            cp_commit();
            asm volatile("cp.async.wait_group 1;" ::: "memory");
        } else {
            asm volatile("cp.async.wait_group 0;" ::: "memory");
        }
        __syncthreads();

        const uint32_t aBase = aB[c & 1] + aMap;
        const uint32_t bBase = bB[c & 1] + bMap;
#pragma unroll
        for (int ks = 0; ks < 4; ks++) {          // k16 steps
            uint32_t afr[4][4], bfr[8][2];
#pragma unroll
            for (int mf = 0; mf < 4; mf++)
                ldsm_x4(afr[mf][0], afr[mf][1], afr[mf][2], afr[mf][3],
                        aBase + (uint32_t)(mf * 16 * GPH * 2 + ks * 32));
#pragma unroll
            for (int p = 0; p < 4; p++)
                ldsm_x4(bfr[2 * p][0], bfr[2 * p][1],
                        bfr[2 * p + 1][0], bfr[2 * p + 1][1],
                        bBase + (uint32_t)(p * 16 * GPH * 2 + ks * 32));
#pragma unroll
            for (int mf = 0; mf < 4; mf++)
#pragma unroll
                for (int nf = 0; nf < 8; nf++)
                    mma_f16(acc[mf][nf], afr[mf], bfr[nf][0], bfr[nf][1]);
        }
        __syncthreads();
    }

    __half* Ch = (__half*)Cv;
    float*  Cf = (float*)Cv;
#pragma unroll
    for (int mf = 0; mf < 4; mf++) {
        const int row0 = bm + wm + mf * 16 + gid;
#pragma unroll
        for (int nf = 0; nf < 8; nf++) {
            const int col = bn + wn + nf * 8 + 2 * tig;
            const size_t i0 = (size_t)row0 * N + col;
            const size_t i1 = (size_t)(row0 + 8) * N + col;
            if (EPI == 1) {
                const float2 r0 = *(const float2*)(res + i0);
                const float2 r1 = *(const float2*)(res + i1);
                *(float2*)(Cf + i0) = make_float2(acc[mf][nf][0] + r0.x,
                                                  acc[mf][nf][1] + r0.y);
                *(float2*)(Cf + i1) = make_float2(acc[mf][nf][2] + r1.x,
                                                  acc[mf][nf][3] + r1.y);
            } else if (EPI == 0) {
                *(__half2*)(Ch + i0) = __floats2half2_rn(acc[mf][nf][0],
                                                         acc[mf][nf][1]);
                *(__half2*)(Ch + i1) = __floats2half2_rn(acc[mf][nf][2],
                                                         acc[mf][nf][3]);
            } else {
                *(__half2*)(Ch + i0) = __floats2half2_rn(gelu_f(acc[mf][nf][0]),
                                                         gelu_f(acc[mf][nf][1]));
                *(__half2*)(Ch + i1) = __floats2half2_rn(gelu_f(acc[mf][nf][2]),
                                                         gelu_f(acc[mf][nf][3]));
            }
        }
    }
}

// ---------------------------------------------------------------------------
// Flash attention, fp16 mma m16n8k16 (qkv fp16).
// Grid: (T/64, B*H), 128 threads (4 warps). Warp w owns query rows w*16..+15.
// Smem (halves, stride APH=72): Qs[64], Ks[64], Vs[64] (natural [j][d]),
// Ps[64]. V consumed via ldmatrix.trans (no transpose store).
// ---------------------------------------------------------------------------
#define APH 72
#define SMEM_ATTN (4 * 64 * APH * 2)

__global__ __launch_bounds__(128)
void attn_h(const __half* __restrict__ qkv, __half* __restrict__ y)
{
    extern __shared__ __half smA[];
    __half* Qs = smA;
    __half* Ks = smA + 64 * APH;
    __half* Vs = smA + 2 * 64 * APH;
    __half* Ps = smA + 3 * 64 * APH;
    const uint32_t QsB = smem_u32(Qs), KsB = smem_u32(Ks);
    const uint32_t VsB = smem_u32(Vs), PsB = smem_u32(Ps);

    const int qb   = gridDim.x - 1 - blockIdx.x;   // heavy tiles first
    const int b    = blockIdx.y >> 4;
    const int h    = blockIdx.y & 15;
    const int tid  = threadIdx.x;
    const int wid  = tid >> 5, lane = tid & 31;
    const int gid  = lane >> 2, tig = lane & 3;
    const int r0   = wid * 16 + gid;

    // ldmatrix maps
    const int aRow = wid * 16 + (lane & 7) + ((lane >> 3) & 1) * 8;
    const uint32_t aMap = (uint32_t)aRow * (APH * 2) + (lane >> 4) * 16;
    const int bRow = (lane >> 4) * 8 + (lane & 7);
    const uint32_t bMap = (uint32_t)bRow * (APH * 2) + ((lane >> 3) & 1) * 16;
    const int vRow = (lane & 7) + ((lane >> 3) & 1) * 8;
    const uint32_t vMap = (uint32_t)vRow * (APH * 2) + (lane >> 4) * 16;

    const __half* base = qkv + (size_t)b * TDIM * QKVW + h * HD;

    const int lr  = tid & 63;
    const int lch = (tid >> 6) << 5;    // half col 0 or 32
    {   // Q tile, scaled by 0.125 (exact in fp16)
        const __half* src = base + (size_t)(qb * 64 + lr) * QKVW + lch;
        const __half2 s2 = __floats2half2_rn(0.125f, 0.125f);
#pragma unroll
        for (int i = 0; i < 4; i++) {
            uint4 v = ((const uint4*)src)[i];
            __half2* hp = (__half2*)&v;
            hp[0] = __hmul2(hp[0], s2); hp[1] = __hmul2(hp[1], s2);
            hp[2] = __hmul2(hp[2], s2); hp[3] = __hmul2(hp[3], s2);
            *(uint4*)&Qs[lr * APH + lch + 8 * i] = v;
        }
    }

    float oacc[8][4];
#pragma unroll
    for (int nf = 0; nf < 8; nf++)
#pragma unroll
        for (int q = 0; q < 4; q++) oacc[nf][q] = 0.f;
    float m0 = -1e30f, m1 = -1e30f, l0 = 0.f, l1 = 0.f;

    for (int kb = 0; kb <= qb; kb++) {
        __syncthreads();
        {   // K and V tiles (natural layout, vectorized)
            const __half* ksrc = base + CDIM     + (size_t)(kb * 64 + lr) * QKVW + lch;
            const __half* vsrc = base + 2 * CDIM + (size_t)(kb * 64 + lr) * QKVW + lch;
#pragma unroll
            for (int i = 0; i < 4; i++) {
                *(uint4*)&Ks[lr * APH + lch + 8 * i] = ((const uint4*)ksrc)[i];
                *(uint4*)&Vs[lr * APH + lch + 8 * i] = ((const uint4*)vsrc)[i];
            }
        }
        __syncthreads();

        // ---- S = Q K^T (16x64 per warp), d = 4 k16 steps ----
        float sacc[8][4];
#pragma unroll
        for (int nf = 0; nf < 8; nf++)
#pragma unroll
            for (int q = 0; q < 4; q++) sacc[nf][q] = 0.f;
#pragma unroll
        for (int ks = 0; ks < 4; ks++) {
            uint32_t a[4], bfr[8][2];
            ldsm_x4(a[0], a[1], a[2], a[3], QsB + aMap + ks * 32);
#pragma unroll
            for (int p = 0; p < 4; p++)
                ldsm_x4(bfr[2 * p][0], bfr[2 * p][1],
                        bfr[2 * p + 1][0], bfr[2 * p + 1][1],
                        KsB + bMap + (uint32_t)(p * 16 * APH * 2 + ks * 32));
#pragma unroll
            for (int nf = 0; nf < 8; nf++)
                mma_f16(sacc[nf], a, bfr[nf][0], bfr[nf][1]);
        }

        if (kb == qb) {
#pragma unroll
            for (int nf = 0; nf < 8; nf++) {
                const int c0 = nf * 8 + 2 * tig;
                if (c0     > r0)     sacc[nf][0] = -1e30f;
                if (c0 + 1 > r0)     sacc[nf][1] = -1e30f;
                if (c0     > r0 + 8) sacc[nf][2] = -1e30f;
                if (c0 + 1 > r0 + 8) sacc[nf][3] = -1e30f;
            }
        }

        // ---- online softmax ----
        float mx0 = -1e30f, mx1 = -1e30f;
#pragma unroll
        for (int nf = 0; nf < 8; nf++) {
            mx0 = fmaxf(mx0, fmaxf(sacc[nf][0], sacc[nf][1]));
            mx1 = fmaxf(mx1, fmaxf(sacc[nf][2], sacc[nf][3]));
        }
        mx0 = fmaxf(mx0, __shfl_xor_sync(0xffffffffu, mx0, 1));
        mx0 = fmaxf(mx0, __shfl_xor_sync(0xffffffffu, mx0, 2));
        mx1 = fmaxf(mx1, __shfl_xor_sync(0xffffffffu, mx1, 1));
        mx1 = fmaxf(mx1, __shfl_xor_sync(0xffffffffu, mx1, 2));
        const float mn0 = fmaxf(m0, mx0), mn1 = fmaxf(m1, mx1);
        const float al0 = __expf(m0 - mn0), al1 = __expf(m1 - mn1);
        float rs0 = 0.f, rs1 = 0.f;
#pragma unroll
        for (int nf = 0; nf < 8; nf++) {
            const __half2 p01 = __floats2half2_rn(__expf(sacc[nf][0] - mn0),
                                                  __expf(sacc[nf][1] - mn0));
            const __half2 p23 = __floats2half2_rn(__expf(sacc[nf][2] - mn1),
                                                  __expf(sacc[nf][3] - mn1));
            const float2 f01 = __half22float2(p01);
            const float2 f23 = __half22float2(p23);
            rs0 += f01.x + f01.y;
            rs1 += f23.x + f23.y;
            const int c = nf * 8 + 2 * tig;
            *(__half2*)&Ps[(r0)     * APH + c] = p01;
            *(__half2*)&Ps[(r0 + 8) * APH + c] = p23;
        }
        rs0 += __shfl_xor_sync(0xffffffffu, rs0, 1);
        rs0 += __shfl_xor_sync(0xffffffffu, rs0, 2);
        rs1 += __shfl_xor_sync(0xffffffffu, rs1, 1);
        rs1 += __shfl_xor_sync(0xffffffffu, rs1, 2);
        l0 = l0 * al0 + rs0;  m0 = mn0;
        l1 = l1 * al1 + rs1;  m1 = mn1;
#pragma unroll
        for (int nf = 0; nf < 8; nf++) {
            oacc[nf][0] *= al0; oacc[nf][1] *= al0;
            oacc[nf][2] *= al1; oacc[nf][3] *= al1;
        }
        __syncwarp();

        // ---- O += P V  (A = P rows, B = V via ldmatrix.trans) ----
#pragma unroll
        for (int ks = 0; ks < 4; ks++) {
            uint32_t a[4], bfr[8][2];
            ldsm_x4(a[0], a[1], a[2], a[3], PsB + aMap + ks * 32);
#pragma unroll
            for (int p = 0; p < 4; p++)
                ldsm_x4_t(bfr[2 * p][0], bfr[2 * p][1],
                          bfr[2 * p + 1][0], bfr[2 * p + 1][1],
                          VsB + vMap + (uint32_t)(ks * 16 * APH * 2 + p * 32));
#pragma unroll
            for (int nf = 0; nf < 8; nf++)
                mma_f16(oacc[nf], a, bfr[nf][0], bfr[nf][1]);
        }
    }

    const float inv0 = 1.0f / l0, inv1 = 1.0f / l1;
    __half* dst0 = y + (size_t)(b * TDIM + qb * 64 + r0) * CDIM + h * HD;
    __half* dst1 = dst0 + 8 * CDIM;
#pragma unroll
    for (int nf = 0; nf < 8; nf++) {
        const int c = nf * 8 + 2 * tig;
        *(__half2*)(dst0 + c) = __floats2half2_rn(oacc[nf][0] * inv0,
                                                  oacc[nf][1] * inv0);
        *(__half2*)(dst1 + c) = __floats2half2_rn(oacc[nf][2] * inv1,
                                                  oacc[nf][3] * inv1);
    }
}

// ---------------------------------------------------------------------------
// Launch orchestration (graph-capturable)
// ---------------------------------------------------------------------------
extern "C" void kernel_launch(void* const* d_in, const int* in_sizes, int n_in,
                              void* d_out, int out_size)
{
    const float* x      = (const float*)d_in[0];
    const float* g1     = (const float*)d_in[1];
    const float* w_qkv  = (const float*)d_in[2];
    const float* w_o    = (const float*)d_in[3];
    const float* g2     = (const float*)d_in[4];
    const float* w_fc   = (const float*)d_in[5];
    const float* w_proj = (const float*)d_in[6];
    float* out = (float*)d_out;

    __half *ln, *qkvb, *yb, *hb, *wq, *wo, *wfc, *wp;
    float *x2;
    cudaGetSymbolAddress((void**)&ln,   g_ln);
    cudaGetSymbolAddress((void**)&qkvb, g_qkv);
    cudaGetSymbolAddress((void**)&yb,   g_y);
    cudaGetSymbolAddress((void**)&x2,   g_x2);
    cudaGetSymbolAddress((void**)&hb,   g_h);
    cudaGetSymbolAddress((void**)&wq,   g_wq);
    cudaGetSymbolAddress((void**)&wo,   g_wo);
    cudaGetSymbolAddress((void**)&wfc,  g_wfc);
    cudaGetSymbolAddress((void**)&wp,   g_wp);

    cudaFuncSetAttribute(attn_h,
                         cudaFuncAttributeMaxDynamicSharedMemorySize, SMEM_ATTN);
    cudaFuncSetAttribute(gemm_h<0>,
                         cudaFuncAttributeMaxDynamicSharedMemorySize, GSMEMH);
    cudaFuncSetAttribute(gemm_h<1>,
                         cudaFuncAttributeMaxDynamicSharedMemorySize, GSMEMH);
    cudaFuncSetAttribute(gemm_h<2>,
                         cudaFuncAttributeMaxDynamicSharedMemorySize, GSMEMH);

    // Convert weights to fp16 once per launch
    round_fp16_kernel<<<(QKVW * CDIM / 8 + 255) / 256, 256>>>(w_qkv, wq,
                                                              QKVW * CDIM / 8);
    round_fp16_kernel<<<(CDIM * CDIM / 8 + 255) / 256, 256>>>(w_o, wo,
                                                              CDIM * CDIM / 8);
    round_fp16_kernel<<<(FFDIM * CDIM / 8 + 255) / 256, 256>>>(w_fc, wfc,
                                                               FFDIM * CDIM / 8);
    round_fp16_kernel<<<(CDIM * FFDIM / 8 + 255) / 256, 256>>>(w_proj, wp,
                                                               CDIM * FFDIM / 8);

    // x1 = ln1(x); qkv = x1 @ Wqkv^T   (fp16 out)
    ln_kernel<<<BT, 256>>>(x, g1, ln);
    gemm_h<0><<<dim3(QKVW / 128, BT / 128), 128, GSMEMH>>>(
        ln, wq, nullptr, qkvb, BT, QKVW, CDIM);
    // y = causal attention (fp16 mma; fp16 out)
    attn_h<<<dim3(TDIM / 64, BDIM * HEADS), 128, SMEM_ATTN>>>(qkvb, yb);
    // x2 = x + y @ Wo^T   (fp32 out)
    gemm_h<1><<<dim3(CDIM / 128, BT / 128), 128, GSMEMH>>>(
        yb, wo, x, x2, BT, CDIM, CDIM);
    // h = gelu(ln2(x2) @ Wfc^T)   (fp16 out)
    ln_kernel<<<BT, 256>>>(x2, g2, ln);
    gemm_h<2><<<dim3(FFDIM / 128, BT / 128), 128, GSMEMH>>>(
        ln, wfc, nullptr, hb, BT, FFDIM, CDIM);
    // out = x2 + h @ Wproj^T   (fp32 out)
    gemm_h<1><<<dim3(CDIM / 128, BT / 128), 128, GSMEMH>>>(
        hb, wp, x2, out, BT, CDIM, FFDIM);
}

// round 12
// speedup vs baseline: 2.1006x; 1.0420x over previous
#include <cuda_runtime.h>
#include <cuda_fp16.h>
#include <math.h>
#include <stdint.h>

// Problem constants
#define BDIM   4
#define TDIM   2048
#define CDIM   1024
#define HEADS  16
#define HD     64
#define FFDIM  4096
#define BT     8192            // B*T rows
#define QKVW   3072            // 3*C

// ---------------------------------------------------------------------------
// Scratch (no allocations allowed — __device__ globals)
// ---------------------------------------------------------------------------
__device__ __half g_ln [BT * CDIM];     // LN output (fp16, GEMM A operand)
__device__ __half g_qkv[BT * QKVW];     // QKV (fp16)
__device__ __half g_y  [BT * CDIM];     // attention out (fp16)
__device__ float  g_x2 [BT * CDIM];     // residual stream 2 (fp32)
__device__ __half g_h  [BT * FFDIM];    // gelu(fc) (fp16)
// fp16 weights
__device__ __half g_wq [QKVW * CDIM];
__device__ __half g_wo [CDIM * CDIM];
__device__ __half g_wfc[FFDIM * CDIM];
__device__ __half g_wp [CDIM * FFDIM];

// ---------------------------------------------------------------------------
// Helpers
// ---------------------------------------------------------------------------
__device__ __forceinline__ uint32_t smem_u32(const void* p) {
    uint32_t a;
    asm("{ .reg .u64 t; cvta.to.shared.u64 t, %1; cvt.u32.u64 %0, t; }"
        : "=r"(a) : "l"(p));
    return a;
}
__device__ __forceinline__ void cp_async16(uint32_t saddr, const void* gaddr) {
    asm volatile("cp.async.cg.shared.global [%0], [%1], 16;"
                 :: "r"(saddr), "l"(gaddr) : "memory");
}
__device__ __forceinline__ void cp_commit() {
    asm volatile("cp.async.commit_group;" ::: "memory");
}
__device__ __forceinline__ void ldsm_x4(uint32_t& r0, uint32_t& r1,
                                        uint32_t& r2, uint32_t& r3,
                                        uint32_t addr) {
    asm volatile("ldmatrix.sync.aligned.m8n8.x4.shared.b16 {%0,%1,%2,%3}, [%4];"
                 : "=r"(r0), "=r"(r1), "=r"(r2), "=r"(r3) : "r"(addr));
}
__device__ __forceinline__ void ldsm_x4_t(uint32_t& r0, uint32_t& r1,
                                          uint32_t& r2, uint32_t& r3,
                                          uint32_t addr) {
    asm volatile("ldmatrix.sync.aligned.m8n8.x4.trans.shared.b16 {%0,%1,%2,%3}, [%4];"
                 : "=r"(r0), "=r"(r1), "=r"(r2), "=r"(r3) : "r"(addr));
}
__device__ __forceinline__ void mma_f16(float* d, const uint32_t* a,
                                        uint32_t b0, uint32_t b1) {
    asm volatile(
        "mma.sync.aligned.m16n8k16.row.col.f32.f16.f16.f32 "
        "{%0,%1,%2,%3}, {%4,%5,%6,%7}, {%8,%9}, {%0,%1,%2,%3};"
        : "+f"(d[0]), "+f"(d[1]), "+f"(d[2]), "+f"(d[3])
        : "r"(a[0]), "r"(a[1]), "r"(a[2]), "r"(a[3]), "r"(b0), "r"(b1));
}
__device__ __forceinline__ float gelu_f(float v) {
    return 0.5f * v * (1.0f + erff(v * 0.70710678118654752f));
}

// ---------------------------------------------------------------------------
// Fused weight prep: fp32 -> fp16, all four weights in one launch.
// Unit = 8 elements (16B dst). Ranges: wq | wo | wfc | wp.
// ---------------------------------------------------------------------------
#define N8_WQ  (QKVW * CDIM / 8)
#define N8_WO  (CDIM * CDIM / 8)
#define N8_WFC (FFDIM * CDIM / 8)
#define N8_WP  (CDIM * FFDIM / 8)
#define N8_ALL (N8_WQ + N8_WO + N8_WFC + N8_WP)

__global__ __launch_bounds__(256)
void prep_weights(const float* __restrict__ wq_s, const float* __restrict__ wo_s,
                  const float* __restrict__ wfc_s, const float* __restrict__ wp_s,
                  __half* __restrict__ wq_d, __half* __restrict__ wo_d,
                  __half* __restrict__ wfc_d, __half* __restrict__ wp_d)
{
    int i = blockIdx.x * blockDim.x + threadIdx.x;
    const float* src;
    __half* dst;
    if (i < N8_WQ)                       { src = wq_s;  dst = wq_d; }
    else if ((i -= N8_WQ)  < N8_WO)      { src = wo_s;  dst = wo_d; }
    else if ((i -= N8_WO)  < N8_WFC)     { src = wfc_s; dst = wfc_d; }
    else if ((i -= N8_WFC) < N8_WP)      { src = wp_s;  dst = wp_d; }
    else return;
    const float4 v0 = ((const float4*)src)[2 * i];
    const float4 v1 = ((const float4*)src)[2 * i + 1];
    __half2 h[4];
    h[0] = __floats2half2_rn(v0.x, v0.y);
    h[1] = __floats2half2_rn(v0.z, v0.w);
    h[2] = __floats2half2_rn(v1.x, v1.y);
    h[3] = __floats2half2_rn(v1.z, v1.w);
    ((uint4*)dst)[i] = *(uint4*)h;
}

// ---------------------------------------------------------------------------
// LayerNorm: one block per row, C=1024, 256 threads x float4 -> fp16 out
// ---------------------------------------------------------------------------
__global__ __launch_bounds__(256)
void ln_kernel(const float* __restrict__ x, const float* __restrict__ g,
               __half* __restrict__ y)
{
    const int row = blockIdx.x;
    const int tid = threadIdx.x;
    const float4 v = ((const float4*)(x + (size_t)row * CDIM))[tid];
    float s  = v.x + v.y + v.z + v.w;
    float ss = v.x * v.x + v.y * v.y + v.z * v.z + v.w * v.w;
#pragma unroll
    for (int o = 16; o > 0; o >>= 1) {
        s  += __shfl_xor_sync(0xffffffffu, s,  o);
        ss += __shfl_xor_sync(0xffffffffu, ss, o);
    }
    __shared__ float rs[8], rss[8];
    const int w = tid >> 5, lane = tid & 31;
    if (lane == 0) { rs[w] = s; rss[w] = ss; }
    __syncthreads();
    if (tid == 0) {
        float a = 0.f, b = 0.f;
#pragma unroll
        for (int i = 0; i < 8; i++) { a += rs[i]; b += rss[i]; }
        const float mean = a * (1.0f / CDIM);
        const float var  = b * (1.0f / CDIM) - mean * mean;
        rs[0]  = mean;
        rss[0] = rsqrtf(var + 1e-5f);
    }
    __syncthreads();
    const float mean = rs[0], rstd = rss[0];
    const float4 gv = ((const float4*)g)[tid];
    __half2 h0 = __floats2half2_rn((v.x - mean) * rstd * gv.x,
                                   (v.y - mean) * rstd * gv.y);
    __half2 h1 = __floats2half2_rn((v.z - mean) * rstd * gv.z,
                                   (v.w - mean) * rstd * gv.w);
    uint2 u;
    u.x = *(uint32_t*)&h0;
    u.y = *(uint32_t*)&h1;
    ((uint2*)(y + (size_t)row * CDIM))[tid] = u;
}

// ---------------------------------------------------------------------------
// FP16 mma.sync GEMM (NT): C[m,n] = sum_k A[m,k]*B[n,k]   (unchanged, R11)
// ---------------------------------------------------------------------------
#define KC      64
#define GPH     72
#define TILE_H  (128 * GPH)
#define GSMEMH  (4 * TILE_H * 2)

template <int EPI>
__global__ __launch_bounds__(128, 2)
void gemm_h(const __half* __restrict__ A, const __half* __restrict__ B,
            const float* __restrict__ res, void* __restrict__ Cv,
            int M, int N, int K)
{
    extern __shared__ __half smh[];
    const uint32_t sb = smem_u32(smh);

    const int tid  = threadIdx.x;
    const int wid  = tid >> 5, lane = tid & 31;
    const int gid  = lane >> 2, tig = lane & 3;
    const int wm   = (wid & 1) << 6;
    const int wn   = (wid >> 1) << 6;
    const int bm   = blockIdx.y << 7, bn = blockIdx.x << 7;

    const int lr  = tid >> 3;
    const int lc8 = (tid & 7) << 3;
    const __half* Ag = A + (size_t)(bm + lr) * K + lc8;
    const __half* Bg = B + (size_t)(bn + lr) * K + lc8;
    uint32_t so[8];
#pragma unroll
    for (int p = 0; p < 8; p++)
        so[p] = (uint32_t)((p * 16 + lr) * GPH + lc8) * 2u;

    const uint32_t aB[2] = { sb,                 sb + 2u * TILE_H * 2u };
    const uint32_t bB[2] = { sb + TILE_H * 2u,   sb + 3u * TILE_H * 2u };

    const int aRow = wm + (lane & 7) + ((lane >> 3) & 1) * 8;
    const uint32_t aMap = (uint32_t)aRow * (GPH * 2) + (lane >> 4) * 16;
    const int bRow = wn + (lane >> 4) * 8 + (lane & 7);
    const uint32_t bMap = (uint32_t)bRow * (GPH * 2) + ((lane >> 3) & 1) * 16;

    float acc[4][8][4];
#pragma unroll
    for (int i = 0; i < 4; i++)
#pragma unroll
        for (int j = 0; j < 8; j++)
#pragma unroll
            for (int q = 0; q < 4; q++) acc[i][j][q] = 0.f;

    const int nk = K / KC;

#pragma unroll
    for (int p = 0; p < 8; p++) {
        cp_async16(aB[0] + so[p], Ag + (size_t)(p * 16) * K);
        cp_async16(bB[0] + so[p], Bg + (size_t)(p * 16) * K);
    }
    cp_commit();

    for (int c = 0; c < nk; c++) {
        if (c + 1 < nk) {
            const int ko = (c + 1) * KC;
            const int nb = (c + 1) & 1;
#pragma unroll
            for (int p = 0; p < 8; p++) {
                cp_async16(aB[nb] + so[p], Ag + (size_t)(p * 16) * K + ko);
                cp_async16(bB[nb] + so[p], Bg + (size_t)(p * 16) * K + ko);
            }
            cp_commit();
            asm volatile("cp.async.wait_group 1;" ::: "memory");
        } else {
            asm volatile("cp.async.wait_group 0;" ::: "memory");
        }
        __syncthreads();

        const uint32_t aBase = aB[c & 1] + aMap;
        const uint32_t bBase = bB[c & 1] + bMap;
#pragma unroll
        for (int ks = 0; ks < 4; ks++) {
            uint32_t afr[4][4], bfr[8][2];
#pragma unroll
            for (int mf = 0; mf < 4; mf++)
                ldsm_x4(afr[mf][0], afr[mf][1], afr[mf][2], afr[mf][3],
                        aBase + (uint32_t)(mf * 16 * GPH * 2 + ks * 32));
#pragma unroll
            for (int p = 0; p < 4; p++)
                ldsm_x4(bfr[2 * p][0], bfr[2 * p][1],
                        bfr[2 * p + 1][0], bfr[2 * p + 1][1],
                        bBase + (uint32_t)(p * 16 * GPH * 2 + ks * 32));
#pragma unroll
            for (int mf = 0; mf < 4; mf++)
#pragma unroll
                for (int nf = 0; nf < 8; nf++)
                    mma_f16(acc[mf][nf], afr[mf], bfr[nf][0], bfr[nf][1]);
        }
        __syncthreads();
    }

    __half* Ch = (__half*)Cv;
    float*  Cf = (float*)Cv;
#pragma unroll
    for (int mf = 0; mf < 4; mf++) {
        const int row0 = bm + wm + mf * 16 + gid;
#pragma unroll
        for (int nf = 0; nf < 8; nf++) {
            const int col = bn + wn + nf * 8 + 2 * tig;
            const size_t i0 = (size_t)row0 * N + col;
            const size_t i1 = (size_t)(row0 + 8) * N + col;
            if (EPI == 1) {
                const float2 r0 = *(const float2*)(res + i0);
                const float2 r1 = *(const float2*)(res + i1);
                *(float2*)(Cf + i0) = make_float2(acc[mf][nf][0] + r0.x,
                                                  acc[mf][nf][1] + r0.y);
                *(float2*)(Cf + i1) = make_float2(acc[mf][nf][2] + r1.x,
                                                  acc[mf][nf][3] + r1.y);
            } else if (EPI == 0) {
                *(__half2*)(Ch + i0) = __floats2half2_rn(acc[mf][nf][0],
                                                         acc[mf][nf][1]);
                *(__half2*)(Ch + i1) = __floats2half2_rn(acc[mf][nf][2],
                                                         acc[mf][nf][3]);
            } else {
                *(__half2*)(Ch + i0) = __floats2half2_rn(gelu_f(acc[mf][nf][0]),
                                                         gelu_f(acc[mf][nf][1]));
                *(__half2*)(Ch + i1) = __floats2half2_rn(gelu_f(acc[mf][nf][2]),
                                                         gelu_f(acc[mf][nf][3]));
            }
        }
    }
}

// ---------------------------------------------------------------------------
// Flash attention, fp16 mma, 128-row Q tiles.
// Grid: (T/128, B*H), 256 threads (8 warps). Warp w owns query rows w*16..+15.
// Smem (halves, stride APH=72): Qs[128], Ps[128], Ks[64], Vs[64].
// K/V tiles are loaded once per 128 query rows (half the traffic/barriers
// of the 64-row version). kb runs over 64-key blocks: 0 .. 2*qb+1.
// ---------------------------------------------------------------------------
#define APH 72
#define SMEM_ATTN ((128 + 128 + 64 + 64) * APH * 2)

__global__ __launch_bounds__(256)
void attn_h(const __half* __restrict__ qkv, __half* __restrict__ y)
{
    extern __shared__ __half smA[];
    __half* Qs = smA;                    // [128][APH]
    __half* Ps = smA + 128 * APH;        // [128][APH]
    __half* Ks = smA + 256 * APH;        // [64][APH]
    __half* Vs = smA + 320 * APH;        // [64][APH]
    const uint32_t QsB = smem_u32(Qs), PsB = smem_u32(Ps);
    const uint32_t KsB = smem_u32(Ks), VsB = smem_u32(Vs);

    const int qb   = gridDim.x - 1 - blockIdx.x;   // heavy tiles first
    const int b    = blockIdx.y >> 4;
    const int h    = blockIdx.y & 15;
    const int tid  = threadIdx.x;
    const int wid  = tid >> 5, lane = tid & 31;
    const int gid  = lane >> 2, tig = lane & 3;
    const int r0   = wid * 16 + gid;               // local q row (and r0+8)

    // ldmatrix maps
    const int aRow = wid * 16 + (lane & 7) + ((lane >> 3) & 1) * 8;
    const uint32_t aMap = (uint32_t)aRow * (APH * 2) + (lane >> 4) * 16;
    const int bRow = (lane >> 4) * 8 + (lane & 7);
    const uint32_t bMap = (uint32_t)bRow * (APH * 2) + ((lane >> 3) & 1) * 16;
    const int vRow = (lane & 7) + ((lane >> 3) & 1) * 8;
    const uint32_t vMap = (uint32_t)vRow * (APH * 2) + (lane >> 4) * 16;

    const __half* base = qkv + (size_t)b * TDIM * QKVW + h * HD;

    // ---- Q tile: 128 rows, scaled by 0.125 (exact in fp16) ----
    {
        const int lr  = tid & 127;          // row
        const int lch = (tid >> 7) << 5;    // half col 0 or 32
        const __half* src = base + (size_t)(qb * 128 + lr) * QKVW + lch;
        const __half2 s2 = __floats2half2_rn(0.125f, 0.125f);
#pragma unroll
        for (int i = 0; i < 4; i++) {
            uint4 v = ((const uint4*)src)[i];
            __half2* hp = (__half2*)&v;
            hp[0] = __hmul2(hp[0], s2); hp[1] = __hmul2(hp[1], s2);
            hp[2] = __hmul2(hp[2], s2); hp[3] = __hmul2(hp[3], s2);
            *(uint4*)&Qs[lr * APH + lch + 8 * i] = v;
        }
    }

    float oacc[8][4];
#pragma unroll
    for (int nf = 0; nf < 8; nf++)
#pragma unroll
        for (int q = 0; q < 4; q++) oacc[nf][q] = 0.f;
    float m0 = -1e30f, m1 = -1e30f, l0 = 0.f, l1 = 0.f;

    const int kv_lr  = tid & 63;            // K/V row
    const int kv_lch = (tid >> 6) << 4;     // half col 0/16/32/48

    const int nkb = 2 * qb + 2;             // 64-key blocks covering <= qb*128+127
    for (int kb = 0; kb < nkb; kb++) {
        __syncthreads();
        {   // K and V tiles (64 rows each)
            const __half* ksrc = base + CDIM     + (size_t)(kb * 64 + kv_lr) * QKVW + kv_lch;
            const __half* vsrc = base + 2 * CDIM + (size_t)(kb * 64 + kv_lr) * QKVW + kv_lch;
#pragma unroll
            for (int i = 0; i < 2; i++) {
                *(uint4*)&Ks[kv_lr * APH + kv_lch + 8 * i] = ((const uint4*)ksrc)[i];
                *(uint4*)&Vs[kv_lr * APH + kv_lch + 8 * i] = ((const uint4*)vsrc)[i];
            }
        }
        __syncthreads();

        // ---- S = Q K^T (16x64 per warp) ----
        float sacc[8][4];
#pragma unroll
        for (int nf = 0; nf < 8; nf++)
#pragma unroll
            for (int q = 0; q < 4; q++) sacc[nf][q] = 0.f;
#pragma unroll
        for (int ks = 0; ks < 4; ks++) {
            uint32_t a[4], bfr[8][2];
            ldsm_x4(a[0], a[1], a[2], a[3], QsB + aMap + ks * 32);
#pragma unroll
            for (int p = 0; p < 4; p++)
                ldsm_x4(bfr[2 * p][0], bfr[2 * p][1],
                        bfr[2 * p + 1][0], bfr[2 * p + 1][1],
                        KsB + bMap + (uint32_t)(p * 16 * APH * 2 + ks * 32));
#pragma unroll
            for (int nf = 0; nf < 8; nf++)
                mma_f16(sacc[nf], a, bfr[nf][0], bfr[nf][1]);
        }

        // ---- causal mask (only the last two key blocks can cross diag) ----
        if (kb >= 2 * qb) {
            const int rg0 = qb * 128 + r0;       // global q rows rg0, rg0+8
#pragma unroll
            for (int nf = 0; nf < 8; nf++) {
                const int cg = kb * 64 + nf * 8 + 2 * tig;
                if (cg     > rg0)     sacc[nf][0] = -1e30f;
                if (cg + 1 > rg0)     sacc[nf][1] = -1e30f;
                if (cg     > rg0 + 8) sacc[nf][2] = -1e30f;
                if (cg + 1 > rg0 + 8) sacc[nf][3] = -1e30f;
            }
        }

        // ---- online softmax ----
        float mx0 = -1e30f, mx1 = -1e30f;
#pragma unroll
        for (int nf = 0; nf < 8; nf++) {
            mx0 = fmaxf(mx0, fmaxf(sacc[nf][0], sacc[nf][1]));
            mx1 = fmaxf(mx1, fmaxf(sacc[nf][2], sacc[nf][3]));
        }
        mx0 = fmaxf(mx0, __shfl_xor_sync(0xffffffffu, mx0, 1));
        mx0 = fmaxf(mx0, __shfl_xor_sync(0xffffffffu, mx0, 2));
        mx1 = fmaxf(mx1, __shfl_xor_sync(0xffffffffu, mx1, 1));
        mx1 = fmaxf(mx1, __shfl_xor_sync(0xffffffffu, mx1, 2));
        const float mn0 = fmaxf(m0, mx0), mn1 = fmaxf(m1, mx1);
        const float al0 = __expf(m0 - mn0), al1 = __expf(m1 - mn1);
        float rs0 = 0.f, rs1 = 0.f;
#pragma unroll
        for (int nf = 0; nf < 8; nf++) {
            const __half2 p01 = __floats2half2_rn(__expf(sacc[nf][0] - mn0),
                                                  __expf(sacc[nf][1] - mn0));
            const __half2 p23 = __floats2half2_rn(__expf(sacc[nf][2] - mn1),
                                                  __expf(sacc[nf][3] - mn1));
            const float2 f01 = __half22float2(p01);
            const float2 f23 = __half22float2(p23);
            rs0 += f01.x + f01.y;
            rs1 += f23.x + f23.y;
            const int c = nf * 8 + 2 * tig;
            *(__half2*)&Ps[(r0)     * APH + c] = p01;
            *(__half2*)&Ps[(r0 + 8) * APH + c] = p23;
        }
        rs0 += __shfl_xor_sync(0xffffffffu, rs0, 1);
        rs0 += __shfl_xor_sync(0xffffffffu, rs0, 2);
        rs1 += __shfl_xor_sync(0xffffffffu, rs1, 1);
        rs1 += __shfl_xor_sync(0xffffffffu, rs1, 2);
        l0 = l0 * al0 + rs0;  m0 = mn0;
        l1 = l1 * al1 + rs1;  m1 = mn1;
#pragma unroll
        for (int nf = 0; nf < 8; nf++) {
            oacc[nf][0] *= al0; oacc[nf][1] *= al0;
            oacc[nf][2] *= al1; oacc[nf][3] *= al1;
        }
        __syncwarp();

        // ---- O += P V (A = P rows [warp-exclusive], B = V via trans) ----
#pragma unroll
        for (int ks = 0; ks < 4; ks++) {
            uint32_t a[4], bfr[8][2];
            ldsm_x4(a[0], a[1], a[2], a[3], PsB + aMap + ks * 32);
#pragma unroll
            for (int p = 0; p < 4; p++)
                ldsm_x4_t(bfr[2 * p][0], bfr[2 * p][1],
                          bfr[2 * p + 1][0], bfr[2 * p + 1][1],
                          VsB + vMap + (uint32_t)(ks * 16 * APH * 2 + p * 32));
#pragma unroll
            for (int nf = 0; nf < 8; nf++)
                mma_f16(oacc[nf], a, bfr[nf][0], bfr[nf][1]);
        }
    }

    const float inv0 = 1.0f / l0, inv1 = 1.0f / l1;
    __half* dst0 = y + (size_t)(b * TDIM + qb * 128 + r0) * CDIM + h * HD;
    __half* dst1 = dst0 + 8 * CDIM;
#pragma unroll
    for (int nf = 0; nf < 8; nf++) {
        const int c = nf * 8 + 2 * tig;
        *(__half2*)(dst0 + c) = __floats2half2_rn(oacc[nf][0] * inv0,
                                                  oacc[nf][1] * inv0);
        *(__half2*)(dst1 + c) = __floats2half2_rn(oacc[nf][2] * inv1,
                                                  oacc[nf][3] * inv1);
    }
}

// ---------------------------------------------------------------------------
// Launch orchestration (graph-capturable)
// ---------------------------------------------------------------------------
extern "C" void kernel_launch(void* const* d_in, const int* in_sizes, int n_in,
                              void* d_out, int out_size)
{
    const float* x      = (const float*)d_in[0];
    const float* g1     = (const float*)d_in[1];
    const float* w_qkv  = (const float*)d_in[2];
    const float* w_o    = (const float*)d_in[3];
    const float* g2     = (const float*)d_in[4];
    const float* w_fc   = (const float*)d_in[5];
    const float* w_proj = (const float*)d_in[6];
    float* out = (float*)d_out;

    __half *ln, *qkvb, *yb, *hb, *wq, *wo, *wfc, *wp;
    float *x2;
    cudaGetSymbolAddress((void**)&ln,   g_ln);
    cudaGetSymbolAddress((void**)&qkvb, g_qkv);
    cudaGetSymbolAddress((void**)&yb,   g_y);
    cudaGetSymbolAddress((void**)&x2,   g_x2);
    cudaGetSymbolAddress((void**)&hb,   g_h);
    cudaGetSymbolAddress((void**)&wq,   g_wq);
    cudaGetSymbolAddress((void**)&wo,   g_wo);
    cudaGetSymbolAddress((void**)&wfc,  g_wfc);
    cudaGetSymbolAddress((void**)&wp,   g_wp);

    cudaFuncSetAttribute(attn_h,
                         cudaFuncAttributeMaxDynamicSharedMemorySize, SMEM_ATTN);
    cudaFuncSetAttribute(gemm_h<0>,
                         cudaFuncAttributeMaxDynamicSharedMemorySize, GSMEMH);
    cudaFuncSetAttribute(gemm_h<1>,
                         cudaFuncAttributeMaxDynamicSharedMemorySize, GSMEMH);
    cudaFuncSetAttribute(gemm_h<2>,
                         cudaFuncAttributeMaxDynamicSharedMemorySize, GSMEMH);

    // Convert all four weights to fp16 (single launch)
    prep_weights<<<(N8_ALL + 255) / 256, 256>>>(w_qkv, w_o, w_fc, w_proj,
                                                wq, wo, wfc, wp);

    // x1 = ln1(x); qkv = x1 @ Wqkv^T   (fp16 out)
    ln_kernel<<<BT, 256>>>(x, g1, ln);
    gemm_h<0><<<dim3(QKVW / 128, BT / 128), 128, GSMEMH>>>(
        ln, wq, nullptr, qkvb, BT, QKVW, CDIM);
    // y = causal attention (fp16 mma; 128-row Q tiles)
    attn_h<<<dim3(TDIM / 128, BDIM * HEADS), 256, SMEM_ATTN>>>(qkvb, yb);
    // x2 = x + y @ Wo^T   (fp32 out)
    gemm_h<1><<<dim3(CDIM / 128, BT / 128), 128, GSMEMH>>>(
        yb, wo, x, x2, BT, CDIM, CDIM);
    // h = gelu(ln2(x2) @ Wfc^T)   (fp16 out)
    ln_kernel<<<BT, 256>>>(x2, g2, ln);
    gemm_h<2><<<dim3(FFDIM / 128, BT / 128), 128, GSMEMH>>>(
        ln, wfc, nullptr, hb, BT, FFDIM, CDIM);
    // out = x2 + h @ Wproj^T   (fp32 out)
    gemm_h<1><<<dim3(CDIM / 128, BT / 128), 128, GSMEMH>>>(
        hb, wp, x2, out, BT, CDIM, FFDIM);
}

// round 13
// speedup vs baseline: 2.1358x; 1.0168x over previous
#include <cuda_runtime.h>
#include <cuda_fp16.h>
#include <math.h>
#include <stdint.h>

// Problem constants
#define BDIM   4
#define TDIM   2048
#define CDIM   1024
#define HEADS  16
#define HD     64
#define FFDIM  4096
#define BT     8192            // B*T rows
#define QKVW   3072            // 3*C

// ---------------------------------------------------------------------------
// Scratch (no allocations allowed — __device__ globals)
// ---------------------------------------------------------------------------
__device__ __half g_ln [BT * CDIM];     // LN output (fp16, GEMM A operand)
__device__ __half g_qkv[BT * QKVW];     // QKV (fp16)
__device__ __half g_y  [BT * CDIM];     // attention out (fp16)
__device__ float  g_x2 [BT * CDIM];     // residual stream 2 (fp32)
__device__ __half g_h  [BT * FFDIM];    // gelu(fc) (fp16)
// fp16 weights
__device__ __half g_wq [QKVW * CDIM];
__device__ __half g_wo [CDIM * CDIM];
__device__ __half g_wfc[FFDIM * CDIM];
__device__ __half g_wp [CDIM * FFDIM];

// ---------------------------------------------------------------------------
// Helpers
// ---------------------------------------------------------------------------
__device__ __forceinline__ uint32_t smem_u32(const void* p) {
    uint32_t a;
    asm("{ .reg .u64 t; cvta.to.shared.u64 t, %1; cvt.u32.u64 %0, t; }"
        : "=r"(a) : "l"(p));
    return a;
}
__device__ __forceinline__ void cp_async16(uint32_t saddr, const void* gaddr) {
    asm volatile("cp.async.cg.shared.global [%0], [%1], 16;"
                 :: "r"(saddr), "l"(gaddr) : "memory");
}
__device__ __forceinline__ void cp_commit() {
    asm volatile("cp.async.commit_group;" ::: "memory");
}
__device__ __forceinline__ void ldsm_x4(uint32_t& r0, uint32_t& r1,
                                        uint32_t& r2, uint32_t& r3,
                                        uint32_t addr) {
    asm volatile("ldmatrix.sync.aligned.m8n8.x4.shared.b16 {%0,%1,%2,%3}, [%4];"
                 : "=r"(r0), "=r"(r1), "=r"(r2), "=r"(r3) : "r"(addr));
}
__device__ __forceinline__ void ldsm_x4_t(uint32_t& r0, uint32_t& r1,
                                          uint32_t& r2, uint32_t& r3,
                                          uint32_t addr) {
    asm volatile("ldmatrix.sync.aligned.m8n8.x4.trans.shared.b16 {%0,%1,%2,%3}, [%4];"
                 : "=r"(r0), "=r"(r1), "=r"(r2), "=r"(r3) : "r"(addr));
}
__device__ __forceinline__ void mma_f16(float* d, const uint32_t* a,
                                        uint32_t b0, uint32_t b1) {
    asm volatile(
        "mma.sync.aligned.m16n8k16.row.col.f32.f16.f16.f32 "
        "{%0,%1,%2,%3}, {%4,%5,%6,%7}, {%8,%9}, {%0,%1,%2,%3};"
        : "+f"(d[0]), "+f"(d[1]), "+f"(d[2]), "+f"(d[3])
        : "r"(a[0]), "r"(a[1]), "r"(a[2]), "r"(a[3]), "r"(b0), "r"(b1));
}
__device__ __forceinline__ float gelu_f(float v) {
    return 0.5f * v * (1.0f + erff(v * 0.70710678118654752f));
}

// ---------------------------------------------------------------------------
// Fused weight prep: fp32 -> fp16, all four weights in one launch.
// ---------------------------------------------------------------------------
#define N8_WQ  (QKVW * CDIM / 8)
#define N8_WO  (CDIM * CDIM / 8)
#define N8_WFC (FFDIM * CDIM / 8)
#define N8_WP  (CDIM * FFDIM / 8)
#define N8_ALL (N8_WQ + N8_WO + N8_WFC + N8_WP)

__global__ __launch_bounds__(256)
void prep_weights(const float* __restrict__ wq_s, const float* __restrict__ wo_s,
                  const float* __restrict__ wfc_s, const float* __restrict__ wp_s,
                  __half* __restrict__ wq_d, __half* __restrict__ wo_d,
                  __half* __restrict__ wfc_d, __half* __restrict__ wp_d)
{
    int i = blockIdx.x * blockDim.x + threadIdx.x;
    const float* src;
    __half* dst;
    if (i < N8_WQ)                       { src = wq_s;  dst = wq_d; }
    else if ((i -= N8_WQ)  < N8_WO)      { src = wo_s;  dst = wo_d; }
    else if ((i -= N8_WO)  < N8_WFC)     { src = wfc_s; dst = wfc_d; }
    else if ((i -= N8_WFC) < N8_WP)      { src = wp_s;  dst = wp_d; }
    else return;
    const float4 v0 = ((const float4*)src)[2 * i];
    const float4 v1 = ((const float4*)src)[2 * i + 1];
    __half2 h[4];
    h[0] = __floats2half2_rn(v0.x, v0.y);
    h[1] = __floats2half2_rn(v0.z, v0.w);
    h[2] = __floats2half2_rn(v1.x, v1.y);
    h[3] = __floats2half2_rn(v1.z, v1.w);
    ((uint4*)dst)[i] = *(uint4*)h;
}

// ---------------------------------------------------------------------------
// LayerNorm: one block per row, C=1024, 256 threads x float4 -> fp16 out
// ---------------------------------------------------------------------------
__global__ __launch_bounds__(256)
void ln_kernel(const float* __restrict__ x, const float* __restrict__ g,
               __half* __restrict__ y)
{
    const int row = blockIdx.x;
    const int tid = threadIdx.x;
    const float4 v = ((const float4*)(x + (size_t)row * CDIM))[tid];
    float s  = v.x + v.y + v.z + v.w;
    float ss = v.x * v.x + v.y * v.y + v.z * v.z + v.w * v.w;
#pragma unroll
    for (int o = 16; o > 0; o >>= 1) {
        s  += __shfl_xor_sync(0xffffffffu, s,  o);
        ss += __shfl_xor_sync(0xffffffffu, ss, o);
    }
    __shared__ float rs[8], rss[8];
    const int w = tid >> 5, lane = tid & 31;
    if (lane == 0) { rs[w] = s; rss[w] = ss; }
    __syncthreads();
    if (tid == 0) {
        float a = 0.f, b = 0.f;
#pragma unroll
        for (int i = 0; i < 8; i++) { a += rs[i]; b += rss[i]; }
        const float mean = a * (1.0f / CDIM);
        const float var  = b * (1.0f / CDIM) - mean * mean;
        rs[0]  = mean;
        rss[0] = rsqrtf(var + 1e-5f);
    }
    __syncthreads();
    const float mean = rs[0], rstd = rss[0];
    const float4 gv = ((const float4*)g)[tid];
    __half2 h0 = __floats2half2_rn((v.x - mean) * rstd * gv.x,
                                   (v.y - mean) * rstd * gv.y);
    __half2 h1 = __floats2half2_rn((v.z - mean) * rstd * gv.z,
                                   (v.w - mean) * rstd * gv.w);
    uint2 u;
    u.x = *(uint32_t*)&h0;
    u.y = *(uint32_t*)&h1;
    ((uint2*)(y + (size_t)row * CDIM))[tid] = u;
}

// ---------------------------------------------------------------------------
// FP16 mma.sync GEMM (NT): C[m,n] = sum_k A[m,k]*B[n,k]   (unchanged, R11)
// ---------------------------------------------------------------------------
#define KC      64
#define GPH     72
#define TILE_H  (128 * GPH)
#define GSMEMH  (4 * TILE_H * 2)

template <int EPI>
__global__ __launch_bounds__(128, 2)
void gemm_h(const __half* __restrict__ A, const __half* __restrict__ B,
            const float* __restrict__ res, void* __restrict__ Cv,
            int M, int N, int K)
{
    extern __shared__ __half smh[];
    const uint32_t sb = smem_u32(smh);

    const int tid  = threadIdx.x;
    const int wid  = tid >> 5, lane = tid & 31;
    const int gid  = lane >> 2, tig = lane & 3;
    const int wm   = (wid & 1) << 6;
    const int wn   = (wid >> 1) << 6;
    const int bm   = blockIdx.y << 7, bn = blockIdx.x << 7;

    const int lr  = tid >> 3;
    const int lc8 = (tid & 7) << 3;
    const __half* Ag = A + (size_t)(bm + lr) * K + lc8;
    const __half* Bg = B + (size_t)(bn + lr) * K + lc8;
    uint32_t so[8];
#pragma unroll
    for (int p = 0; p < 8; p++)
        so[p] = (uint32_t)((p * 16 + lr) * GPH + lc8) * 2u;

    const uint32_t aB[2] = { sb,                 sb + 2u * TILE_H * 2u };
    const uint32_t bB[2] = { sb + TILE_H * 2u,   sb + 3u * TILE_H * 2u };

    const int aRow = wm + (lane & 7) + ((lane >> 3) & 1) * 8;
    const uint32_t aMap = (uint32_t)aRow * (GPH * 2) + (lane >> 4) * 16;
    const int bRow = wn + (lane >> 4) * 8 + (lane & 7);
    const uint32_t bMap = (uint32_t)bRow * (GPH * 2) + ((lane >> 3) & 1) * 16;

    float acc[4][8][4];
#pragma unroll
    for (int i = 0; i < 4; i++)
#pragma unroll
        for (int j = 0; j < 8; j++)
#pragma unroll
            for (int q = 0; q < 4; q++) acc[i][j][q] = 0.f;

    const int nk = K / KC;

#pragma unroll
    for (int p = 0; p < 8; p++) {
        cp_async16(aB[0] + so[p], Ag + (size_t)(p * 16) * K);
        cp_async16(bB[0] + so[p], Bg + (size_t)(p * 16) * K);
    }
    cp_commit();

    for (int c = 0; c < nk; c++) {
        if (c + 1 < nk) {
            const int ko = (c + 1) * KC;
            const int nb = (c + 1) & 1;
#pragma unroll
            for (int p = 0; p < 8; p++) {
                cp_async16(aB[nb] + so[p], Ag + (size_t)(p * 16) * K + ko);
                cp_async16(bB[nb] + so[p], Bg + (size_t)(p * 16) * K + ko);
            }
            cp_commit();
            asm volatile("cp.async.wait_group 1;" ::: "memory");
        } else {
            asm volatile("cp.async.wait_group 0;" ::: "memory");
        }
        __syncthreads();

        const uint32_t aBase = aB[c & 1] + aMap;
        const uint32_t bBase = bB[c & 1] + bMap;
#pragma unroll
        for (int ks = 0; ks < 4; ks++) {
            uint32_t afr[4][4], bfr[8][2];
#pragma unroll
            for (int mf = 0; mf < 4; mf++)
                ldsm_x4(afr[mf][0], afr[mf][1], afr[mf][2], afr[mf][3],
                        aBase + (uint32_t)(mf * 16 * GPH * 2 + ks * 32));
#pragma unroll
            for (int p = 0; p < 4; p++)
                ldsm_x4(bfr[2 * p][0], bfr[2 * p][1],
                        bfr[2 * p + 1][0], bfr[2 * p + 1][1],
                        bBase + (uint32_t)(p * 16 * GPH * 2 + ks * 32));
#pragma unroll
            for (int mf = 0; mf < 4; mf++)
#pragma unroll
                for (int nf = 0; nf < 8; nf++)
                    mma_f16(acc[mf][nf], afr[mf], bfr[nf][0], bfr[nf][1]);
        }
        __syncthreads();
    }

    __half* Ch = (__half*)Cv;
    float*  Cf = (float*)Cv;
#pragma unroll
    for (int mf = 0; mf < 4; mf++) {
        const int row0 = bm + wm + mf * 16 + gid;
#pragma unroll
        for (int nf = 0; nf < 8; nf++) {
            const int col = bn + wn + nf * 8 + 2 * tig;
            const size_t i0 = (size_t)row0 * N + col;
            const size_t i1 = (size_t)(row0 + 8) * N + col;
            if (EPI == 1) {
                const float2 r0 = *(const float2*)(res + i0);
                const float2 r1 = *(const float2*)(res + i1);
                *(float2*)(Cf + i0) = make_float2(acc[mf][nf][0] + r0.x,
                                                  acc[mf][nf][1] + r0.y);
                *(float2*)(Cf + i1) = make_float2(acc[mf][nf][2] + r1.x,
                                                  acc[mf][nf][3] + r1.y);
            } else if (EPI == 0) {
                *(__half2*)(Ch + i0) = __floats2half2_rn(acc[mf][nf][0],
                                                         acc[mf][nf][1]);
                *(__half2*)(Ch + i1) = __floats2half2_rn(acc[mf][nf][2],
                                                         acc[mf][nf][3]);
            } else {
                *(__half2*)(Ch + i0) = __floats2half2_rn(gelu_f(acc[mf][nf][0]),
                                                         gelu_f(acc[mf][nf][1]));
                *(__half2*)(Ch + i1) = __floats2half2_rn(gelu_f(acc[mf][nf][2]),
                                                         gelu_f(acc[mf][nf][3]));
            }
        }
    }
}

// ---------------------------------------------------------------------------
// Flash attention, fp16 mma, 128-row Q tiles, register-resident Q and P.
// Grid: (T/128, B*H), 256 threads (8 warps). Warp w owns query rows w*16..+15.
// Smem (halves, stride APH=72): Qs[128] (used once), Ks[64], Vs[64].
// Q fragments hoisted to registers; P passes from S-accumulators directly
// into PV A-fragments (no smem round-trip, no extra syncs).
// ---------------------------------------------------------------------------
#define APH 72
#define SMEM_ATTN ((128 + 64 + 64) * APH * 2)

__global__ __launch_bounds__(256, 2)
void attn_h(const __half* __restrict__ qkv, __half* __restrict__ y)
{
    extern __shared__ __half smA[];
    __half* Qs = smA;                    // [128][APH]
    __half* Ks = smA + 128 * APH;        // [64][APH]
    __half* Vs = smA + 192 * APH;        // [64][APH]
    const uint32_t QsB = smem_u32(Qs);
    const uint32_t KsB = smem_u32(Ks), VsB = smem_u32(Vs);

    const int qb   = gridDim.x - 1 - blockIdx.x;   // heavy tiles first
    const int b    = blockIdx.y >> 4;
    const int h    = blockIdx.y & 15;
    const int tid  = threadIdx.x;
    const int wid  = tid >> 5, lane = tid & 31;
    const int gid  = lane >> 2, tig = lane & 3;
    const int r0   = wid * 16 + gid;               // local q row (and r0+8)

    // ldmatrix maps
    const int aRow = wid * 16 + (lane & 7) + ((lane >> 3) & 1) * 8;
    const uint32_t aMap = (uint32_t)aRow * (APH * 2) + (lane >> 4) * 16;
    const int bRow = (lane >> 4) * 8 + (lane & 7);
    const uint32_t bMap = (uint32_t)bRow * (APH * 2) + ((lane >> 3) & 1) * 16;
    const int vRow = (lane & 7) + ((lane >> 3) & 1) * 8;
    const uint32_t vMap = (uint32_t)vRow * (APH * 2) + (lane >> 4) * 16;

    const __half* base = qkv + (size_t)b * TDIM * QKVW + h * HD;

    // ---- Q tile: 128 rows, scaled by 0.125 (exact in fp16) ----
    {
        const int lr  = tid & 127;          // row
        const int lch = (tid >> 7) << 5;    // half col 0 or 32
        const __half* src = base + (size_t)(qb * 128 + lr) * QKVW + lch;
        const __half2 s2 = __floats2half2_rn(0.125f, 0.125f);
#pragma unroll
        for (int i = 0; i < 4; i++) {
            uint4 v = ((const uint4*)src)[i];
            __half2* hp = (__half2*)&v;
            hp[0] = __hmul2(hp[0], s2); hp[1] = __hmul2(hp[1], s2);
            hp[2] = __hmul2(hp[2], s2); hp[3] = __hmul2(hp[3], s2);
            *(uint4*)&Qs[lr * APH + lch + 8 * i] = v;
        }
    }
    __syncthreads();

    // ---- hoist Q fragments to registers (invariant across kb) ----
    uint32_t qfr[4][4];
#pragma unroll
    for (int ks = 0; ks < 4; ks++)
        ldsm_x4(qfr[ks][0], qfr[ks][1], qfr[ks][2], qfr[ks][3],
                QsB + aMap + ks * 32);

    float oacc[8][4];
#pragma unroll
    for (int nf = 0; nf < 8; nf++)
#pragma unroll
        for (int q = 0; q < 4; q++) oacc[nf][q] = 0.f;
    float m0 = -1e30f, m1 = -1e30f, l0 = 0.f, l1 = 0.f;

    const int kv_lr  = tid & 63;            // K/V row
    const int kv_lch = (tid >> 6) << 4;     // half col 0/16/32/48

    const int nkb = 2 * qb + 2;             // 64-key blocks
    for (int kb = 0; kb < nkb; kb++) {
        __syncthreads();
        {   // K and V tiles (64 rows each)
            const __half* ksrc = base + CDIM     + (size_t)(kb * 64 + kv_lr) * QKVW + kv_lch;
            const __half* vsrc = base + 2 * CDIM + (size_t)(kb * 64 + kv_lr) * QKVW + kv_lch;
#pragma unroll
            for (int i = 0; i < 2; i++) {
                *(uint4*)&Ks[kv_lr * APH + kv_lch + 8 * i] = ((const uint4*)ksrc)[i];
                *(uint4*)&Vs[kv_lr * APH + kv_lch + 8 * i] = ((const uint4*)vsrc)[i];
            }
        }
        __syncthreads();

        // ---- S = Q K^T (16x64 per warp); Q from registers ----
        float sacc[8][4];
#pragma unroll
        for (int nf = 0; nf < 8; nf++)
#pragma unroll
            for (int q = 0; q < 4; q++) sacc[nf][q] = 0.f;
#pragma unroll
        for (int ks = 0; ks < 4; ks++) {
            uint32_t bfr[8][2];
#pragma unroll
            for (int p = 0; p < 4; p++)
                ldsm_x4(bfr[2 * p][0], bfr[2 * p][1],
                        bfr[2 * p + 1][0], bfr[2 * p + 1][1],
                        KsB + bMap + (uint32_t)(p * 16 * APH * 2 + ks * 32));
#pragma unroll
            for (int nf = 0; nf < 8; nf++)
                mma_f16(sacc[nf], qfr[ks], bfr[nf][0], bfr[nf][1]);
        }

        // ---- causal mask ----
        if (kb >= 2 * qb) {
            const int rg0 = qb * 128 + r0;
#pragma unroll
            for (int nf = 0; nf < 8; nf++) {
                const int cg = kb * 64 + nf * 8 + 2 * tig;
                if (cg     > rg0)     sacc[nf][0] = -1e30f;
                if (cg + 1 > rg0)     sacc[nf][1] = -1e30f;
                if (cg     > rg0 + 8) sacc[nf][2] = -1e30f;
                if (cg + 1 > rg0 + 8) sacc[nf][3] = -1e30f;
            }
        }

        // ---- online softmax; P packed straight into mma A-fragments ----
        float mx0 = -1e30f, mx1 = -1e30f;
#pragma unroll
        for (int nf = 0; nf < 8; nf++) {
            mx0 = fmaxf(mx0, fmaxf(sacc[nf][0], sacc[nf][1]));
            mx1 = fmaxf(mx1, fmaxf(sacc[nf][2], sacc[nf][3]));
        }
        mx0 = fmaxf(mx0, __shfl_xor_sync(0xffffffffu, mx0, 1));
        mx0 = fmaxf(mx0, __shfl_xor_sync(0xffffffffu, mx0, 2));
        mx1 = fmaxf(mx1, __shfl_xor_sync(0xffffffffu, mx1, 1));
        mx1 = fmaxf(mx1, __shfl_xor_sync(0xffffffffu, mx1, 2));
        const float mn0 = fmaxf(m0, mx0), mn1 = fmaxf(m1, mx1);
        const float al0 = __expf(m0 - mn0), al1 = __expf(m1 - mn1);
        float rs0 = 0.f, rs1 = 0.f;
        uint32_t pf01[8], pf23[8];        // rows gid / gid+8, packed half2
#pragma unroll
        for (int nf = 0; nf < 8; nf++) {
            const __half2 p01 = __floats2half2_rn(__expf(sacc[nf][0] - mn0),
                                                  __expf(sacc[nf][1] - mn0));
            const __half2 p23 = __floats2half2_rn(__expf(sacc[nf][2] - mn1),
                                                  __expf(sacc[nf][3] - mn1));
            const float2 f01 = __half22float2(p01);
            const float2 f23 = __half22float2(p23);
            rs0 += f01.x + f01.y;
            rs1 += f23.x + f23.y;
            pf01[nf] = *(const uint32_t*)&p01;
            pf23[nf] = *(const uint32_t*)&p23;
        }
        rs0 += __shfl_xor_sync(0xffffffffu, rs0, 1);
        rs0 += __shfl_xor_sync(0xffffffffu, rs0, 2);
        rs1 += __shfl_xor_sync(0xffffffffu, rs1, 1);
        rs1 += __shfl_xor_sync(0xffffffffu, rs1, 2);
        l0 = l0 * al0 + rs0;  m0 = mn0;
        l1 = l1 * al1 + rs1;  m1 = mn1;
#pragma unroll
        for (int nf = 0; nf < 8; nf++) {
            oacc[nf][0] *= al0; oacc[nf][1] *= al0;
            oacc[nf][2] *= al1; oacc[nf][3] *= al1;
        }

        // ---- O += P V (A = P registers, B = V via ldmatrix.trans) ----
#pragma unroll
        for (int ks = 0; ks < 4; ks++) {
            uint32_t a[4], bfr[8][2];
            a[0] = pf01[2 * ks];     a[1] = pf23[2 * ks];
            a[2] = pf01[2 * ks + 1]; a[3] = pf23[2 * ks + 1];
#pragma unroll
            for (int p = 0; p < 4; p++)
                ldsm_x4_t(bfr[2 * p][0], bfr[2 * p][1],
                          bfr[2 * p + 1][0], bfr[2 * p + 1][1],
                          VsB + vMap + (uint32_t)(ks * 16 * APH * 2 + p * 32));
#pragma unroll
            for (int nf = 0; nf < 8; nf++)
                mma_f16(oacc[nf], a, bfr[nf][0], bfr[nf][1]);
        }
    }

    const float inv0 = 1.0f / l0, inv1 = 1.0f / l1;
    __half* dst0 = y + (size_t)(b * TDIM + qb * 128 + r0) * CDIM + h * HD;
    __half* dst1 = dst0 + 8 * CDIM;
#pragma unroll
    for (int nf = 0; nf < 8; nf++) {
        const int c = nf * 8 + 2 * tig;
        *(__half2*)(dst0 + c) = __floats2half2_rn(oacc[nf][0] * inv0,
                                                  oacc[nf][1] * inv0);
        *(__half2*)(dst1 + c) = __floats2half2_rn(oacc[nf][2] * inv1,
                                                  oacc[nf][3] * inv1);
    }
}

// ---------------------------------------------------------------------------
// Launch orchestration (graph-capturable)
// ---------------------------------------------------------------------------
extern "C" void kernel_launch(void* const* d_in, const int* in_sizes, int n_in,
                              void* d_out, int out_size)
{
    const float* x      = (const float*)d_in[0];
    const float* g1     = (const float*)d_in[1];
    const float* w_qkv  = (const float*)d_in[2];
    const float* w_o    = (const float*)d_in[3];
    const float* g2     = (const float*)d_in[4];
    const float* w_fc   = (const float*)d_in[5];
    const float* w_proj = (const float*)d_in[6];
    float* out = (float*)d_out;

    __half *ln, *qkvb, *yb, *hb, *wq, *wo, *wfc, *wp;
    float *x2;
    cudaGetSymbolAddress((void**)&ln,   g_ln);
    cudaGetSymbolAddress((void**)&qkvb, g_qkv);
    cudaGetSymbolAddress((void**)&yb,   g_y);
    cudaGetSymbolAddress((void**)&x2,   g_x2);
    cudaGetSymbolAddress((void**)&hb,   g_h);
    cudaGetSymbolAddress((void**)&wq,   g_wq);
    cudaGetSymbolAddress((void**)&wo,   g_wo);
    cudaGetSymbolAddress((void**)&wfc,  g_wfc);
    cudaGetSymbolAddress((void**)&wp,   g_wp);

    cudaFuncSetAttribute(attn_h,
                         cudaFuncAttributeMaxDynamicSharedMemorySize, SMEM_ATTN);
    cudaFuncSetAttribute(gemm_h<0>,
                         cudaFuncAttributeMaxDynamicSharedMemorySize, GSMEMH);
    cudaFuncSetAttribute(gemm_h<1>,
                         cudaFuncAttributeMaxDynamicSharedMemorySize, GSMEMH);
    cudaFuncSetAttribute(gemm_h<2>,
                         cudaFuncAttributeMaxDynamicSharedMemorySize, GSMEMH);

    // Convert all four weights to fp16 (single launch)
    prep_weights<<<(N8_ALL + 255) / 256, 256>>>(w_qkv, w_o, w_fc, w_proj,
                                                wq, wo, wfc, wp);

    // x1 = ln1(x); qkv = x1 @ Wqkv^T   (fp16 out)
    ln_kernel<<<BT, 256>>>(x, g1, ln);
    gemm_h<0><<<dim3(QKVW / 128, BT / 128), 128, GSMEMH>>>(
        ln, wq, nullptr, qkvb, BT, QKVW, CDIM);
    // y = causal attention (fp16 mma; 128-row Q tiles; reg-resident Q/P)
    attn_h<<<dim3(TDIM / 128, BDIM * HEADS), 256, SMEM_ATTN>>>(qkvb, yb);
    // x2 = x + y @ Wo^T   (fp32 out)
    gemm_h<1><<<dim3(CDIM / 128, BT / 128), 128, GSMEMH>>>(
        yb, wo, x, x2, BT, CDIM, CDIM);
    // h = gelu(ln2(x2) @ Wfc^T)   (fp16 out)
    ln_kernel<<<BT, 256>>>(x2, g2, ln);
    gemm_h<2><<<dim3(FFDIM / 128, BT / 128), 128, GSMEMH>>>(
        ln, wfc, nullptr, hb, BT, FFDIM, CDIM);
    // out = x2 + h @ Wproj^T   (fp32 out)
    gemm_h<1><<<dim3(CDIM / 128, BT / 128), 128, GSMEMH>>>(
        hb, wp, x2, out, BT, CDIM, FFDIM);
}

// round 14
// speedup vs baseline: 2.2340x; 1.0460x over previous
#include <cuda_runtime.h>
#include <cuda_fp16.h>
#include <math.h>
#include <stdint.h>

// Problem constants
#define BDIM   4
#define TDIM   2048
#define CDIM   1024
#define HEADS  16
#define HD     64
#define FFDIM  4096
#define BT     8192            // B*T rows
#define QKVW   3072            // 3*C

// ---------------------------------------------------------------------------
// Scratch (no allocations allowed — __device__ globals)
// ---------------------------------------------------------------------------
__device__ __half g_ln [BT * CDIM];
__device__ __half g_qkv[BT * QKVW];
__device__ __half g_y  [BT * CDIM];
__device__ float  g_x2 [BT * CDIM];
__device__ __half g_h  [BT * FFDIM];
__device__ __half g_wq [QKVW * CDIM];
__device__ __half g_wo [CDIM * CDIM];
__device__ __half g_wfc[FFDIM * CDIM];
__device__ __half g_wp [CDIM * FFDIM];

// ---------------------------------------------------------------------------
// Helpers
// ---------------------------------------------------------------------------
__device__ __forceinline__ uint32_t smem_u32(const void* p) {
    uint32_t a;
    asm("{ .reg .u64 t; cvta.to.shared.u64 t, %1; cvt.u32.u64 %0, t; }"
        : "=r"(a) : "l"(p));
    return a;
}
__device__ __forceinline__ void cp_async16(uint32_t saddr, const void* gaddr) {
    asm volatile("cp.async.cg.shared.global [%0], [%1], 16;"
                 :: "r"(saddr), "l"(gaddr) : "memory");
}
__device__ __forceinline__ void cp_commit() {
    asm volatile("cp.async.commit_group;" ::: "memory");
}
__device__ __forceinline__ void ldsm_x4(uint32_t& r0, uint32_t& r1,
                                        uint32_t& r2, uint32_t& r3,
                                        uint32_t addr) {
    asm volatile("ldmatrix.sync.aligned.m8n8.x4.shared.b16 {%0,%1,%2,%3}, [%4];"
                 : "=r"(r0), "=r"(r1), "=r"(r2), "=r"(r3) : "r"(addr));
}
__device__ __forceinline__ void ldsm_x4_t(uint32_t& r0, uint32_t& r1,
                                          uint32_t& r2, uint32_t& r3,
                                          uint32_t addr) {
    asm volatile("ldmatrix.sync.aligned.m8n8.x4.trans.shared.b16 {%0,%1,%2,%3}, [%4];"
                 : "=r"(r0), "=r"(r1), "=r"(r2), "=r"(r3) : "r"(addr));
}
__device__ __forceinline__ void mma_f16(float* d, const uint32_t* a,
                                        uint32_t b0, uint32_t b1) {
    asm volatile(
        "mma.sync.aligned.m16n8k16.row.col.f32.f16.f16.f32 "
        "{%0,%1,%2,%3}, {%4,%5,%6,%7}, {%8,%9}, {%0,%1,%2,%3};"
        : "+f"(d[0]), "+f"(d[1]), "+f"(d[2]), "+f"(d[3])
        : "r"(a[0]), "r"(a[1]), "r"(a[2]), "r"(a[3]), "r"(b0), "r"(b1));
}
__device__ __forceinline__ float gelu_f(float v) {
    return 0.5f * v * (1.0f + erff(v * 0.70710678118654752f));
}

// ---------------------------------------------------------------------------
// Fused weight prep: fp32 -> fp16, all four weights in one launch.
// ---------------------------------------------------------------------------
#define N8_WQ  (QKVW * CDIM / 8)
#define N8_WO  (CDIM * CDIM / 8)
#define N8_WFC (FFDIM * CDIM / 8)
#define N8_WP  (CDIM * FFDIM / 8)
#define N8_ALL (N8_WQ + N8_WO + N8_WFC + N8_WP)

__global__ __launch_bounds__(256)
void prep_weights(const float* __restrict__ wq_s, const float* __restrict__ wo_s,
                  const float* __restrict__ wfc_s, const float* __restrict__ wp_s,
                  __half* __restrict__ wq_d, __half* __restrict__ wo_d,
                  __half* __restrict__ wfc_d, __half* __restrict__ wp_d)
{
    int i = blockIdx.x * blockDim.x + threadIdx.x;
    const float* src;
    __half* dst;
    if (i < N8_WQ)                       { src = wq_s;  dst = wq_d; }
    else if ((i -= N8_WQ)  < N8_WO)      { src = wo_s;  dst = wo_d; }
    else if ((i -= N8_WO)  < N8_WFC)     { src = wfc_s; dst = wfc_d; }
    else if ((i -= N8_WFC) < N8_WP)      { src = wp_s;  dst = wp_d; }
    else return;
    const float4 v0 = ((const float4*)src)[2 * i];
    const float4 v1 = ((const float4*)src)[2 * i + 1];
    __half2 h[4];
    h[0] = __floats2half2_rn(v0.x, v0.y);
    h[1] = __floats2half2_rn(v0.z, v0.w);
    h[2] = __floats2half2_rn(v1.x, v1.y);
    h[3] = __floats2half2_rn(v1.z, v1.w);
    ((uint4*)dst)[i] = *(uint4*)h;
}

// ---------------------------------------------------------------------------
// LayerNorm: one block per row, C=1024, 256 threads x float4 -> fp16 out
// ---------------------------------------------------------------------------
__global__ __launch_bounds__(256)
void ln_kernel(const float* __restrict__ x, const float* __restrict__ g,
               __half* __restrict__ y)
{
    const int row = blockIdx.x;
    const int tid = threadIdx.x;
    const float4 v = ((const float4*)(x + (size_t)row * CDIM))[tid];
    float s  = v.x + v.y + v.z + v.w;
    float ss = v.x * v.x + v.y * v.y + v.z * v.z + v.w * v.w;
#pragma unroll
    for (int o = 16; o > 0; o >>= 1) {
        s  += __shfl_xor_sync(0xffffffffu, s,  o);
        ss += __shfl_xor_sync(0xffffffffu, ss, o);
    }
    __shared__ float rs[8], rss[8];
    const int w = tid >> 5, lane = tid & 31;
    if (lane == 0) { rs[w] = s; rss[w] = ss; }
    __syncthreads();
    if (tid == 0) {
        float a = 0.f, b = 0.f;
#pragma unroll
        for (int i = 0; i < 8; i++) { a += rs[i]; b += rss[i]; }
        const float mean = a * (1.0f / CDIM);
        const float var  = b * (1.0f / CDIM) - mean * mean;
        rs[0]  = mean;
        rss[0] = rsqrtf(var + 1e-5f);
    }
    __syncthreads();
    const float mean = rs[0], rstd = rss[0];
    const float4 gv = ((const float4*)g)[tid];
    __half2 h0 = __floats2half2_rn((v.x - mean) * rstd * gv.x,
                                   (v.y - mean) * rstd * gv.y);
    __half2 h1 = __floats2half2_rn((v.z - mean) * rstd * gv.z,
                                   (v.w - mean) * rstd * gv.w);
    uint2 u;
    u.x = *(uint32_t*)&h0;
    u.y = *(uint32_t*)&h1;
    ((uint2*)(y + (size_t)row * CDIM))[tid] = u;
}

// ---------------------------------------------------------------------------
// FP16 mma.sync GEMM (NT): C[m,n] = sum_k A[m,k]*B[n,k]   (unchanged, R11)
// ---------------------------------------------------------------------------
#define KC      64
#define GPH     72
#define TILE_H  (128 * GPH)
#define GSMEMH  (4 * TILE_H * 2)

template <int EPI>
__global__ __launch_bounds__(128, 2)
void gemm_h(const __half* __restrict__ A, const __half* __restrict__ B,
            const float* __restrict__ res, void* __restrict__ Cv,
            int M, int N, int K)
{
    extern __shared__ __half smh[];
    const uint32_t sb = smem_u32(smh);

    const int tid  = threadIdx.x;
    const int wid  = tid >> 5, lane = tid & 31;
    const int gid  = lane >> 2, tig = lane & 3;
    const int wm   = (wid & 1) << 6;
    const int wn   = (wid >> 1) << 6;
    const int bm   = blockIdx.y << 7, bn = blockIdx.x << 7;

    const int lr  = tid >> 3;
    const int lc8 = (tid & 7) << 3;
    const __half* Ag = A + (size_t)(bm + lr) * K + lc8;
    const __half* Bg = B + (size_t)(bn + lr) * K + lc8;
    uint32_t so[8];
#pragma unroll
    for (int p = 0; p < 8; p++)
        so[p] = (uint32_t)((p * 16 + lr) * GPH + lc8) * 2u;

    const uint32_t aB[2] = { sb,                 sb + 2u * TILE_H * 2u };
    const uint32_t bB[2] = { sb + TILE_H * 2u,   sb + 3u * TILE_H * 2u };

    const int aRow = wm + (lane & 7) + ((lane >> 3) & 1) * 8;
    const uint32_t aMap = (uint32_t)aRow * (GPH * 2) + (lane >> 4) * 16;
    const int bRow = wn + (lane >> 4) * 8 + (lane & 7);
    const uint32_t bMap = (uint32_t)bRow * (GPH * 2) + ((lane >> 3) & 1) * 16;

    float acc[4][8][4];
#pragma unroll
    for (int i = 0; i < 4; i++)
#pragma unroll
        for (int j = 0; j < 8; j++)
#pragma unroll
            for (int q = 0; q < 4; q++) acc[i][j][q] = 0.f;

    const int nk = K / KC;

#pragma unroll
    for (int p = 0; p < 8; p++) {
        cp_async16(aB[0] + so[p], Ag + (size_t)(p * 16) * K);
        cp_async16(bB[0] + so[p], Bg + (size_t)(p * 16) * K);
    }
    cp_commit();

    for (int c = 0; c < nk; c++) {
        if (c + 1 < nk) {
            const int ko = (c + 1) * KC;
            const int nb = (c + 1) & 1;
#pragma unroll
            for (int p = 0; p < 8; p++) {
                cp_async16(aB[nb] + so[p], Ag + (size_t)(p * 16) * K + ko);
                cp_async16(bB[nb] + so[p], Bg + (size_t)(p * 16) * K + ko);
            }
            cp_commit();
            asm volatile("cp.async.wait_group 1;" ::: "memory");
        } else {
            asm volatile("cp.async.wait_group 0;" ::: "memory");
        }
        __syncthreads();

        const uint32_t aBase = aB[c & 1] + aMap;
        const uint32_t bBase = bB[c & 1] + bMap;
#pragma unroll
        for (int ks = 0; ks < 4; ks++) {
            uint32_t afr[4][4], bfr[8][2];
#pragma unroll
            for (int mf = 0; mf < 4; mf++)
                ldsm_x4(afr[mf][0], afr[mf][1], afr[mf][2], afr[mf][3],
                        aBase + (uint32_t)(mf * 16 * GPH * 2 + ks * 32));
#pragma unroll
            for (int p = 0; p < 4; p++)
                ldsm_x4(bfr[2 * p][0], bfr[2 * p][1],
                        bfr[2 * p + 1][0], bfr[2 * p + 1][1],
                        bBase + (uint32_t)(p * 16 * GPH * 2 + ks * 32));
#pragma unroll
            for (int mf = 0; mf < 4; mf++)
#pragma unroll
                for (int nf = 0; nf < 8; nf++)
                    mma_f16(acc[mf][nf], afr[mf], bfr[nf][0], bfr[nf][1]);
        }
        __syncthreads();
    }

    __half* Ch = (__half*)Cv;
    float*  Cf = (float*)Cv;
#pragma unroll
    for (int mf = 0; mf < 4; mf++) {
        const int row0 = bm + wm + mf * 16 + gid;
#pragma unroll
        for (int nf = 0; nf < 8; nf++) {
            const int col = bn + wn + nf * 8 + 2 * tig;
            const size_t i0 = (size_t)row0 * N + col;
            const size_t i1 = (size_t)(row0 + 8) * N + col;
            if (EPI == 1) {
                const float2 r0 = *(const float2*)(res + i0);
                const float2 r1 = *(const float2*)(res + i1);
                *(float2*)(Cf + i0) = make_float2(acc[mf][nf][0] + r0.x,
                                                  acc[mf][nf][1] + r0.y);
                *(float2*)(Cf + i1) = make_float2(acc[mf][nf][2] + r1.x,
                                                  acc[mf][nf][3] + r1.y);
            } else if (EPI == 0) {
                *(__half2*)(Ch + i0) = __floats2half2_rn(acc[mf][nf][0],
                                                         acc[mf][nf][1]);
                *(__half2*)(Ch + i1) = __floats2half2_rn(acc[mf][nf][2],
                                                         acc[mf][nf][3]);
            } else {
                *(__half2*)(Ch + i0) = __floats2half2_rn(gelu_f(acc[mf][nf][0]),
                                                         gelu_f(acc[mf][nf][1]));
                *(__half2*)(Ch + i1) = __floats2half2_rn(gelu_f(acc[mf][nf][2]),
                                                         gelu_f(acc[mf][nf][3]));
            }
        }
    }
}

// ---------------------------------------------------------------------------
// Flash attention v3: fp16 mma, 128-row Q tiles, 128 threads (4 warps),
// warp owns 32 query rows (two m16 tiles) -> halves redundant K/V fragment
// loads per unit of work. Q and P register-resident.
// Smem (halves, stride APH=72): Qs[128] (used once), Ks[64], Vs[64].
// ---------------------------------------------------------------------------
#define APH 72
#define SMEM_ATTN ((128 + 64 + 64) * APH * 2)

__global__ __launch_bounds__(128, 2)
void attn_h(const __half* __restrict__ qkv, __half* __restrict__ y)
{
    extern __shared__ __half smA[];
    __half* Qs = smA;                    // [128][APH]
    __half* Ks = smA + 128 * APH;        // [64][APH]
    __half* Vs = smA + 192 * APH;        // [64][APH]
    const uint32_t QsB = smem_u32(Qs);
    const uint32_t KsB = smem_u32(Ks), VsB = smem_u32(Vs);

    const int qb   = gridDim.x - 1 - blockIdx.x;   // heavy tiles first
    const int b    = blockIdx.y >> 4;
    const int h    = blockIdx.y & 15;
    const int tid  = threadIdx.x;
    const int wid  = tid >> 5, lane = tid & 31;
    const int gid  = lane >> 2, tig = lane & 3;
    const int r0   = wid * 32 + gid;               // rows r0, +8, +16, +24

    // ldmatrix maps
    const int aRow = wid * 32 + (lane & 7) + ((lane >> 3) & 1) * 8;
    const uint32_t aMap = (uint32_t)aRow * (APH * 2) + (lane >> 4) * 16;
    const int bRow = (lane >> 4) * 8 + (lane & 7);
    const uint32_t bMap = (uint32_t)bRow * (APH * 2) + ((lane >> 3) & 1) * 16;
    const int vRow = (lane & 7) + ((lane >> 3) & 1) * 8;
    const uint32_t vMap = (uint32_t)vRow * (APH * 2) + (lane >> 4) * 16;

    const __half* base = qkv + (size_t)b * TDIM * QKVW + h * HD;

    // ---- Q tile: 128 rows x 64 halves; one row per thread, scaled 0.125 ----
    {
        const __half* src = base + (size_t)(qb * 128 + tid) * QKVW;
        const __half2 s2 = __floats2half2_rn(0.125f, 0.125f);
#pragma unroll
        for (int i = 0; i < 8; i++) {
            uint4 v = ((const uint4*)src)[i];
            __half2* hp = (__half2*)&v;
            hp[0] = __hmul2(hp[0], s2); hp[1] = __hmul2(hp[1], s2);
            hp[2] = __hmul2(hp[2], s2); hp[3] = __hmul2(hp[3], s2);
            *(uint4*)&Qs[tid * APH + 8 * i] = v;
        }
    }
    __syncthreads();

    // ---- hoist Q fragments: 2 m16 tiles x 4 k-steps ----
    uint32_t qfr[4][2][4];
#pragma unroll
    for (int ks = 0; ks < 4; ks++)
#pragma unroll
        for (int t = 0; t < 2; t++)
            ldsm_x4(qfr[ks][t][0], qfr[ks][t][1], qfr[ks][t][2], qfr[ks][t][3],
                    QsB + aMap + (uint32_t)(t * 16 * APH * 2 + ks * 32));

    float oacc[2][8][4];
#pragma unroll
    for (int t = 0; t < 2; t++)
#pragma unroll
        for (int nf = 0; nf < 8; nf++)
#pragma unroll
            for (int q = 0; q < 4; q++) oacc[t][nf][q] = 0.f;
    float mstate[2][2] = {{-1e30f, -1e30f}, {-1e30f, -1e30f}};
    float lstate[2][2] = {{0.f, 0.f}, {0.f, 0.f}};

    const int kv_lr  = tid & 63;            // K/V row
    const int kv_lch = (tid >> 6) << 5;     // half col 0 or 32

    const int nkb = 2 * qb + 2;             // 64-key blocks
    for (int kb = 0; kb < nkb; kb++) {
        __syncthreads();
        {   // K and V tiles (64 rows each), 32 halves per thread each
            const __half* ksrc = base + CDIM     + (size_t)(kb * 64 + kv_lr) * QKVW + kv_lch;
            const __half* vsrc = base + 2 * CDIM + (size_t)(kb * 64 + kv_lr) * QKVW + kv_lch;
#pragma unroll
            for (int i = 0; i < 4; i++) {
                *(uint4*)&Ks[kv_lr * APH + kv_lch + 8 * i] = ((const uint4*)ksrc)[i];
                *(uint4*)&Vs[kv_lr * APH + kv_lch + 8 * i] = ((const uint4*)vsrc)[i];
            }
        }
        __syncthreads();

        // ---- S = Q K^T (32x64 per warp) ----
        float sacc[2][8][4];
#pragma unroll
        for (int t = 0; t < 2; t++)
#pragma unroll
            for (int nf = 0; nf < 8; nf++)
#pragma unroll
                for (int q = 0; q < 4; q++) sacc[t][nf][q] = 0.f;
#pragma unroll
        for (int ks = 0; ks < 4; ks++) {
            uint32_t bfr[8][2];
#pragma unroll
            for (int p = 0; p < 4; p++)
                ldsm_x4(bfr[2 * p][0], bfr[2 * p][1],
                        bfr[2 * p + 1][0], bfr[2 * p + 1][1],
                        KsB + bMap + (uint32_t)(p * 16 * APH * 2 + ks * 32));
#pragma unroll
            for (int t = 0; t < 2; t++)
#pragma unroll
                for (int nf = 0; nf < 8; nf++)
                    mma_f16(sacc[t][nf], qfr[ks][t], bfr[nf][0], bfr[nf][1]);
        }

        // ---- causal mask (only last two key blocks cross the diagonal) ----
        if (kb >= 2 * qb) {
#pragma unroll
            for (int t = 0; t < 2; t++) {
                const int rg0 = qb * 128 + r0 + t * 16;
#pragma unroll
                for (int nf = 0; nf < 8; nf++) {
                    const int cg = kb * 64 + nf * 8 + 2 * tig;
                    if (cg     > rg0)     sacc[t][nf][0] = -1e30f;
                    if (cg + 1 > rg0)     sacc[t][nf][1] = -1e30f;
                    if (cg     > rg0 + 8) sacc[t][nf][2] = -1e30f;
                    if (cg + 1 > rg0 + 8) sacc[t][nf][3] = -1e30f;
                }
            }
        }

        // ---- online softmax; P packed straight into mma A-fragments ----
        uint32_t pf01[2][8], pf23[2][8];
#pragma unroll
        for (int t = 0; t < 2; t++) {
            float mx0 = -1e30f, mx1 = -1e30f;
#pragma unroll
            for (int nf = 0; nf < 8; nf++) {
                mx0 = fmaxf(mx0, fmaxf(sacc[t][nf][0], sacc[t][nf][1]));
                mx1 = fmaxf(mx1, fmaxf(sacc[t][nf][2], sacc[t][nf][3]));
            }
            mx0 = fmaxf(mx0, __shfl_xor_sync(0xffffffffu, mx0, 1));
            mx0 = fmaxf(mx0, __shfl_xor_sync(0xffffffffu, mx0, 2));
            mx1 = fmaxf(mx1, __shfl_xor_sync(0xffffffffu, mx1, 1));
            mx1 = fmaxf(mx1, __shfl_xor_sync(0xffffffffu, mx1, 2));
            const float mn0 = fmaxf(mstate[t][0], mx0);
            const float mn1 = fmaxf(mstate[t][1], mx1);
            const float al0 = __expf(mstate[t][0] - mn0);
            const float al1 = __expf(mstate[t][1] - mn1);
            float rs0 = 0.f, rs1 = 0.f;
#pragma unroll
            for (int nf = 0; nf < 8; nf++) {
                const __half2 p01 = __floats2half2_rn(__expf(sacc[t][nf][0] - mn0),
                                                      __expf(sacc[t][nf][1] - mn0));
                const __half2 p23 = __floats2half2_rn(__expf(sacc[t][nf][2] - mn1),
                                                      __expf(sacc[t][nf][3] - mn1));
                const float2 f01 = __half22float2(p01);
                const float2 f23 = __half22float2(p23);
                rs0 += f01.x + f01.y;
                rs1 += f23.x + f23.y;
                pf01[t][nf] = *(const uint32_t*)&p01;
                pf23[t][nf] = *(const uint32_t*)&p23;
            }
            rs0 += __shfl_xor_sync(0xffffffffu, rs0, 1);
            rs0 += __shfl_xor_sync(0xffffffffu, rs0, 2);
            rs1 += __shfl_xor_sync(0xffffffffu, rs1, 1);
            rs1 += __shfl_xor_sync(0xffffffffu, rs1, 2);
            lstate[t][0] = lstate[t][0] * al0 + rs0;  mstate[t][0] = mn0;
            lstate[t][1] = lstate[t][1] * al1 + rs1;  mstate[t][1] = mn1;
#pragma unroll
            for (int nf = 0; nf < 8; nf++) {
                oacc[t][nf][0] *= al0; oacc[t][nf][1] *= al0;
                oacc[t][nf][2] *= al1; oacc[t][nf][3] *= al1;
            }
        }

        // ---- O += P V (A = P registers, B = V via ldmatrix.trans) ----
#pragma unroll
        for (int ks = 0; ks < 4; ks++) {
            uint32_t bfr[8][2];
#pragma unroll
            for (int p = 0; p < 4; p++)
                ldsm_x4_t(bfr[2 * p][0], bfr[2 * p][1],
                          bfr[2 * p + 1][0], bfr[2 * p + 1][1],
                          VsB + vMap + (uint32_t)(ks * 16 * APH * 2 + p * 32));
#pragma unroll
            for (int t = 0; t < 2; t++) {
                uint32_t a[4];
                a[0] = pf01[t][2 * ks];     a[1] = pf23[t][2 * ks];
                a[2] = pf01[t][2 * ks + 1]; a[3] = pf23[t][2 * ks + 1];
#pragma unroll
                for (int nf = 0; nf < 8; nf++)
                    mma_f16(oacc[t][nf], a, bfr[nf][0], bfr[nf][1]);
            }
        }
    }

#pragma unroll
    for (int t = 0; t < 2; t++) {
        const float inv0 = 1.0f / lstate[t][0], inv1 = 1.0f / lstate[t][1];
        __half* dst0 = y + (size_t)(b * TDIM + qb * 128 + r0 + t * 16) * CDIM + h * HD;
        __half* dst1 = dst0 + 8 * CDIM;
#pragma unroll
        for (int nf = 0; nf < 8; nf++) {
            const int c = nf * 8 + 2 * tig;
            *(__half2*)(dst0 + c) = __floats2half2_rn(oacc[t][nf][0] * inv0,
                                                      oacc[t][nf][1] * inv0);
            *(__half2*)(dst1 + c) = __floats2half2_rn(oacc[t][nf][2] * inv1,
                                                      oacc[t][nf][3] * inv1);
        }
    }
}

// ---------------------------------------------------------------------------
// Launch orchestration (graph-capturable)
// ---------------------------------------------------------------------------
extern "C" void kernel_launch(void* const* d_in, const int* in_sizes, int n_in,
                              void* d_out, int out_size)
{
    const float* x      = (const float*)d_in[0];
    const float* g1     = (const float*)d_in[1];
    const float* w_qkv  = (const float*)d_in[2];
    const float* w_o    = (const float*)d_in[3];
    const float* g2     = (const float*)d_in[4];
    const float* w_fc   = (const float*)d_in[5];
    const float* w_proj = (const float*)d_in[6];
    float* out = (float*)d_out;

    __half *ln, *qkvb, *yb, *hb, *wq, *wo, *wfc, *wp;
    float *x2;
    cudaGetSymbolAddress((void**)&ln,   g_ln);
    cudaGetSymbolAddress((void**)&qkvb, g_qkv);
    cudaGetSymbolAddress((void**)&yb,   g_y);
    cudaGetSymbolAddress((void**)&x2,   g_x2);
    cudaGetSymbolAddress((void**)&hb,   g_h);
    cudaGetSymbolAddress((void**)&wq,   g_wq);
    cudaGetSymbolAddress((void**)&wo,   g_wo);
    cudaGetSymbolAddress((void**)&wfc,  g_wfc);
    cudaGetSymbolAddress((void**)&wp,   g_wp);

    cudaFuncSetAttribute(attn_h,
                         cudaFuncAttributeMaxDynamicSharedMemorySize, SMEM_ATTN);
    cudaFuncSetAttribute(gemm_h<0>,
                         cudaFuncAttributeMaxDynamicSharedMemorySize, GSMEMH);
    cudaFuncSetAttribute(gemm_h<1>,
                         cudaFuncAttributeMaxDynamicSharedMemorySize, GSMEMH);
    cudaFuncSetAttribute(gemm_h<2>,
                         cudaFuncAttributeMaxDynamicSharedMemorySize, GSMEMH);

    // Convert all four weights to fp16 (single launch)
    prep_weights<<<(N8_ALL + 255) / 256, 256>>>(w_qkv, w_o, w_fc, w_proj,
                                                wq, wo, wfc, wp);

    // x1 = ln1(x); qkv = x1 @ Wqkv^T   (fp16 out)
    ln_kernel<<<BT, 256>>>(x, g1, ln);
    gemm_h<0><<<dim3(QKVW / 128, BT / 128), 128, GSMEMH>>>(
        ln, wq, nullptr, qkvb, BT, QKVW, CDIM);
    // y = causal attention (fp16 mma; 4 warps x 32 q-rows)
    attn_h<<<dim3(TDIM / 128, BDIM * HEADS), 128, SMEM_ATTN>>>(qkvb, yb);
    // x2 = x + y @ Wo^T   (fp32 out)
    gemm_h<1><<<dim3(CDIM / 128, BT / 128), 128, GSMEMH>>>(
        yb, wo, x, x2, BT, CDIM, CDIM);
    // h = gelu(ln2(x2) @ Wfc^T)   (fp16 out)
    ln_kernel<<<BT, 256>>>(x2, g2, ln);
    gemm_h<2><<<dim3(FFDIM / 128, BT / 128), 128, GSMEMH>>>(
        ln, wfc, nullptr, hb, BT, FFDIM, CDIM);
    // out = x2 + h @ Wproj^T   (fp32 out)
    gemm_h<1><<<dim3(CDIM / 128, BT / 128), 128, GSMEMH>>>(
        hb, wp, x2, out, BT, CDIM, FFDIM);
}

// round 15
// speedup vs baseline: 2.2740x; 1.0179x over previous
#include <cuda_runtime.h>
#include <cuda_fp16.h>
#include <math.h>
#include <stdint.h>

// Problem constants
#define BDIM   4
#define TDIM   2048
#define CDIM   1024
#define HEADS  16
#define HD     64
#define FFDIM  4096
#define BT     8192            // B*T rows
#define QKVW   3072            // 3*C

// ---------------------------------------------------------------------------
// Scratch (no allocations allowed — __device__ globals)
// ---------------------------------------------------------------------------
__device__ __half g_ln [BT * CDIM];
__device__ __half g_qkv[BT * QKVW];
__device__ __half g_y  [BT * CDIM];
__device__ float  g_x2 [BT * CDIM];
__device__ __half g_h  [BT * FFDIM];
__device__ __half g_wq [QKVW * CDIM];
__device__ __half g_wo [CDIM * CDIM];
__device__ __half g_wfc[FFDIM * CDIM];
__device__ __half g_wp [CDIM * FFDIM];

// ---------------------------------------------------------------------------
// Helpers
// ---------------------------------------------------------------------------
__device__ __forceinline__ uint32_t smem_u32(const void* p) {
    uint32_t a;
    asm("{ .reg .u64 t; cvta.to.shared.u64 t, %1; cvt.u32.u64 %0, t; }"
        : "=r"(a) : "l"(p));
    return a;
}
__device__ __forceinline__ void cp_async16(uint32_t saddr, const void* gaddr) {
    asm volatile("cp.async.cg.shared.global [%0], [%1], 16;"
                 :: "r"(saddr), "l"(gaddr) : "memory");
}
__device__ __forceinline__ void cp_commit() {
    asm volatile("cp.async.commit_group;" ::: "memory");
}
__device__ __forceinline__ void ldsm_x4(uint32_t& r0, uint32_t& r1,
                                        uint32_t& r2, uint32_t& r3,
                                        uint32_t addr) {
    asm volatile("ldmatrix.sync.aligned.m8n8.x4.shared.b16 {%0,%1,%2,%3}, [%4];"
                 : "=r"(r0), "=r"(r1), "=r"(r2), "=r"(r3) : "r"(addr));
}
__device__ __forceinline__ void ldsm_x4_t(uint32_t& r0, uint32_t& r1,
                                          uint32_t& r2, uint32_t& r3,
                                          uint32_t addr) {
    asm volatile("ldmatrix.sync.aligned.m8n8.x4.trans.shared.b16 {%0,%1,%2,%3}, [%4];"
                 : "=r"(r0), "=r"(r1), "=r"(r2), "=r"(r3) : "r"(addr));
}
__device__ __forceinline__ void mma_f16(float* d, const uint32_t* a,
                                        uint32_t b0, uint32_t b1) {
    asm volatile(
        "mma.sync.aligned.m16n8k16.row.col.f32.f16.f16.f32 "
        "{%0,%1,%2,%3}, {%4,%5,%6,%7}, {%8,%9}, {%0,%1,%2,%3};"
        : "+f"(d[0]), "+f"(d[1]), "+f"(d[2]), "+f"(d[3])
        : "r"(a[0]), "r"(a[1]), "r"(a[2]), "r"(a[3]), "r"(b0), "r"(b1));
}
__device__ __forceinline__ float gelu_f(float v) {
    return 0.5f * v * (1.0f + erff(v * 0.70710678118654752f));
}

// ---------------------------------------------------------------------------
// Fused weight prep: fp32 -> fp16, all four weights in one launch.
// ---------------------------------------------------------------------------
#define N8_WQ  (QKVW * CDIM / 8)
#define N8_WO  (CDIM * CDIM / 8)
#define N8_WFC (FFDIM * CDIM / 8)
#define N8_WP  (CDIM * FFDIM / 8)
#define N8_ALL (N8_WQ + N8_WO + N8_WFC + N8_WP)

__global__ __launch_bounds__(256)
void prep_weights(const float* __restrict__ wq_s, const float* __restrict__ wo_s,
                  const float* __restrict__ wfc_s, const float* __restrict__ wp_s,
                  __half* __restrict__ wq_d, __half* __restrict__ wo_d,
                  __half* __restrict__ wfc_d, __half* __restrict__ wp_d)
{
    int i = blockIdx.x * blockDim.x + threadIdx.x;
    const float* src;
    __half* dst;
    if (i < N8_WQ)                       { src = wq_s;  dst = wq_d; }
    else if ((i -= N8_WQ)  < N8_WO)      { src = wo_s;  dst = wo_d; }
    else if ((i -= N8_WO)  < N8_WFC)     { src = wfc_s; dst = wfc_d; }
    else if ((i -= N8_WFC) < N8_WP)      { src = wp_s;  dst = wp_d; }
    else return;
    const float4 v0 = ((const float4*)src)[2 * i];
    const float4 v1 = ((const float4*)src)[2 * i + 1];
    __half2 h[4];
    h[0] = __floats2half2_rn(v0.x, v0.y);
    h[1] = __floats2half2_rn(v0.z, v0.w);
    h[2] = __floats2half2_rn(v1.x, v1.y);
    h[3] = __floats2half2_rn(v1.z, v1.w);
    ((uint4*)dst)[i] = *(uint4*)h;
}

// ---------------------------------------------------------------------------
// LayerNorm: one block per row, C=1024, 256 threads x float4 -> fp16 out
// ---------------------------------------------------------------------------
__global__ __launch_bounds__(256)
void ln_kernel(const float* __restrict__ x, const float* __restrict__ g,
               __half* __restrict__ y)
{
    const int row = blockIdx.x;
    const int tid = threadIdx.x;
    const float4 v = ((const float4*)(x + (size_t)row * CDIM))[tid];
    float s  = v.x + v.y + v.z + v.w;
    float ss = v.x * v.x + v.y * v.y + v.z * v.z + v.w * v.w;
#pragma unroll
    for (int o = 16; o > 0; o >>= 1) {
        s  += __shfl_xor_sync(0xffffffffu, s,  o);
        ss += __shfl_xor_sync(0xffffffffu, ss, o);
    }
    __shared__ float rs[8], rss[8];
    const int w = tid >> 5, lane = tid & 31;
    if (lane == 0) { rs[w] = s; rss[w] = ss; }
    __syncthreads();
    if (tid == 0) {
        float a = 0.f, b = 0.f;
#pragma unroll
        for (int i = 0; i < 8; i++) { a += rs[i]; b += rss[i]; }
        const float mean = a * (1.0f / CDIM);
        const float var  = b * (1.0f / CDIM) - mean * mean;
        rs[0]  = mean;
        rss[0] = rsqrtf(var + 1e-5f);
    }
    __syncthreads();
    const float mean = rs[0], rstd = rss[0];
    const float4 gv = ((const float4*)g)[tid];
    __half2 h0 = __floats2half2_rn((v.x - mean) * rstd * gv.x,
                                   (v.y - mean) * rstd * gv.y);
    __half2 h1 = __floats2half2_rn((v.z - mean) * rstd * gv.z,
                                   (v.w - mean) * rstd * gv.w);
    uint2 u;
    u.x = *(uint32_t*)&h0;
    u.y = *(uint32_t*)&h1;
    ((uint2*)(y + (size_t)row * CDIM))[tid] = u;
}

// ---------------------------------------------------------------------------
// FP16 mma.sync GEMM (NT): C[m,n] = sum_k A[m,k]*B[n,k]   (unchanged, R11)
// ---------------------------------------------------------------------------
#define KC      64
#define GPH     72
#define TILE_H  (128 * GPH)
#define GSMEMH  (4 * TILE_H * 2)

template <int EPI>
__global__ __launch_bounds__(128, 2)
void gemm_h(const __half* __restrict__ A, const __half* __restrict__ B,
            const float* __restrict__ res, void* __restrict__ Cv,
            int M, int N, int K)
{
    extern __shared__ __half smh[];
    const uint32_t sb = smem_u32(smh);

    const int tid  = threadIdx.x;
    const int wid  = tid >> 5, lane = tid & 31;
    const int gid  = lane >> 2, tig = lane & 3;
    const int wm   = (wid & 1) << 6;
    const int wn   = (wid >> 1) << 6;
    const int bm   = blockIdx.y << 7, bn = blockIdx.x << 7;

    const int lr  = tid >> 3;
    const int lc8 = (tid & 7) << 3;
    const __half* Ag = A + (size_t)(bm + lr) * K + lc8;
    const __half* Bg = B + (size_t)(bn + lr) * K + lc8;
    uint32_t so[8];
#pragma unroll
    for (int p = 0; p < 8; p++)
        so[p] = (uint32_t)((p * 16 + lr) * GPH + lc8) * 2u;

    const uint32_t aB[2] = { sb,                 sb + 2u * TILE_H * 2u };
    const uint32_t bB[2] = { sb + TILE_H * 2u,   sb + 3u * TILE_H * 2u };

    const int aRow = wm + (lane & 7) + ((lane >> 3) & 1) * 8;
    const uint32_t aMap = (uint32_t)aRow * (GPH * 2) + (lane >> 4) * 16;
    const int bRow = wn + (lane >> 4) * 8 + (lane & 7);
    const uint32_t bMap = (uint32_t)bRow * (GPH * 2) + ((lane >> 3) & 1) * 16;

    float acc[4][8][4];
#pragma unroll
    for (int i = 0; i < 4; i++)
#pragma unroll
        for (int j = 0; j < 8; j++)
#pragma unroll
            for (int q = 0; q < 4; q++) acc[i][j][q] = 0.f;

    const int nk = K / KC;

#pragma unroll
    for (int p = 0; p < 8; p++) {
        cp_async16(aB[0] + so[p], Ag + (size_t)(p * 16) * K);
        cp_async16(bB[0] + so[p], Bg + (size_t)(p * 16) * K);
    }
    cp_commit();

    for (int c = 0; c < nk; c++) {
        if (c + 1 < nk) {
            const int ko = (c + 1) * KC;
            const int nb = (c + 1) & 1;
#pragma unroll
            for (int p = 0; p < 8; p++) {
                cp_async16(aB[nb] + so[p], Ag + (size_t)(p * 16) * K + ko);
                cp_async16(bB[nb] + so[p], Bg + (size_t)(p * 16) * K + ko);
            }
            cp_commit();
            asm volatile("cp.async.wait_group 1;" ::: "memory");
        } else {
            asm volatile("cp.async.wait_group 0;" ::: "memory");
        }
        __syncthreads();

        const uint32_t aBase = aB[c & 1] + aMap;
        const uint32_t bBase = bB[c & 1] + bMap;
#pragma unroll
        for (int ks = 0; ks < 4; ks++) {
            uint32_t afr[4][4], bfr[8][2];
#pragma unroll
            for (int mf = 0; mf < 4; mf++)
                ldsm_x4(afr[mf][0], afr[mf][1], afr[mf][2], afr[mf][3],
                        aBase + (uint32_t)(mf * 16 * GPH * 2 + ks * 32));
#pragma unroll
            for (int p = 0; p < 4; p++)
                ldsm_x4(bfr[2 * p][0], bfr[2 * p][1],
                        bfr[2 * p + 1][0], bfr[2 * p + 1][1],
                        bBase + (uint32_t)(p * 16 * GPH * 2 + ks * 32));
#pragma unroll
            for (int mf = 0; mf < 4; mf++)
#pragma unroll
                for (int nf = 0; nf < 8; nf++)
                    mma_f16(acc[mf][nf], afr[mf], bfr[nf][0], bfr[nf][1]);
        }
        __syncthreads();
    }

    __half* Ch = (__half*)Cv;
    float*  Cf = (float*)Cv;
#pragma unroll
    for (int mf = 0; mf < 4; mf++) {
        const int row0 = bm + wm + mf * 16 + gid;
#pragma unroll
        for (int nf = 0; nf < 8; nf++) {
            const int col = bn + wn + nf * 8 + 2 * tig;
            const size_t i0 = (size_t)row0 * N + col;
            const size_t i1 = (size_t)(row0 + 8) * N + col;
            if (EPI == 1) {
                const float2 r0 = *(const float2*)(res + i0);
                const float2 r1 = *(const float2*)(res + i1);
                *(float2*)(Cf + i0) = make_float2(acc[mf][nf][0] + r0.x,
                                                  acc[mf][nf][1] + r0.y);
                *(float2*)(Cf + i1) = make_float2(acc[mf][nf][2] + r1.x,
                                                  acc[mf][nf][3] + r1.y);
            } else if (EPI == 0) {
                *(__half2*)(Ch + i0) = __floats2half2_rn(acc[mf][nf][0],
                                                         acc[mf][nf][1]);
                *(__half2*)(Ch + i1) = __floats2half2_rn(acc[mf][nf][2],
                                                         acc[mf][nf][3]);
            } else {
                *(__half2*)(Ch + i0) = __floats2half2_rn(gelu_f(acc[mf][nf][0]),
                                                         gelu_f(acc[mf][nf][1]));
                *(__half2*)(Ch + i1) = __floats2half2_rn(gelu_f(acc[mf][nf][2]),
                                                         gelu_f(acc[mf][nf][3]));
            }
        }
    }
}

// ---------------------------------------------------------------------------
// Flash attention v4: fp16 mma, 128-row Q tiles, 128 threads (4 warps),
// warp owns 32 query rows. Q/P register-resident. K/V tiles loaded via
// cp.async into a 2-stage ring: one barrier per kb; load(kb+1) overlaps
// compute(kb). Smem: Qs[128], Ks[2][64], Vs[2][64] (stride APH=72).
// ---------------------------------------------------------------------------
#define APH 72
#define SMEM_ATTN ((128 + 4 * 64) * APH * 2)

__global__ __launch_bounds__(128, 2)
void attn_h(const __half* __restrict__ qkv, __half* __restrict__ y)
{
    extern __shared__ __half smA[];
    __half* Qs = smA;                            // [128][APH]
    const uint32_t QsB = smem_u32(Qs);
    const uint32_t KsB[2] = { QsB + 128u * APH * 2u,
                              QsB + 192u * APH * 2u };
    const uint32_t VsB[2] = { QsB + 256u * APH * 2u,
                              QsB + 320u * APH * 2u };

    const int qb   = gridDim.x - 1 - blockIdx.x;   // heavy tiles first
    const int b    = blockIdx.y >> 4;
    const int h    = blockIdx.y & 15;
    const int tid  = threadIdx.x;
    const int wid  = tid >> 5, lane = tid & 31;
    const int gid  = lane >> 2, tig = lane & 3;
    const int r0   = wid * 32 + gid;               // rows r0, +8, +16, +24

    // ldmatrix maps
    const int aRow = wid * 32 + (lane & 7) + ((lane >> 3) & 1) * 8;
    const uint32_t aMap = (uint32_t)aRow * (APH * 2) + (lane >> 4) * 16;
    const int bRow = (lane >> 4) * 8 + (lane & 7);
    const uint32_t bMap = (uint32_t)bRow * (APH * 2) + ((lane >> 3) & 1) * 16;
    const int vRow = (lane & 7) + ((lane >> 3) & 1) * 8;
    const uint32_t vMap = (uint32_t)vRow * (APH * 2) + (lane >> 4) * 16;

    const __half* base = qkv + (size_t)b * TDIM * QKVW + h * HD;

    // cp.async map for K/V tiles: 128 threads, 64 rows x 128B.
    // Thread covers half a row: row = tid>>1, 32-half chunk = (tid&1)*32.
    const int kv_r  = tid >> 1;
    const int kv_c  = (tid & 1) << 5;
    const __half* Kg = base + CDIM     + (size_t)kv_r * QKVW + kv_c;
    const __half* Vg = base + 2 * CDIM + (size_t)kv_r * QKVW + kv_c;
    const uint32_t kvOff = (uint32_t)(kv_r * APH + kv_c) * 2u;

    const int nkb = 2 * qb + 2;                   // 64-key blocks

    // Prologue: issue kb=0 K/V into stage 0
    {
        const size_t go = 0;
#pragma unroll
        for (int i = 0; i < 4; i++) {
            cp_async16(KsB[0] + kvOff + i * 16u, Kg + go + i * 8);
            cp_async16(VsB[0] + kvOff + i * 16u, Vg + go + i * 8);
        }
        cp_commit();
    }

    // ---- Q tile: 128 rows x 64 halves; one row per thread, scaled 0.125 ----
    {
        const __half* src = base + (size_t)(qb * 128 + tid) * QKVW;
        const __half2 s2 = __floats2half2_rn(0.125f, 0.125f);
#pragma unroll
        for (int i = 0; i < 8; i++) {
            uint4 v = ((const uint4*)src)[i];
            __half2* hp = (__half2*)&v;
            hp[0] = __hmul2(hp[0], s2); hp[1] = __hmul2(hp[1], s2);
            hp[2] = __hmul2(hp[2], s2); hp[3] = __hmul2(hp[3], s2);
            *(uint4*)&Qs[tid * APH + 8 * i] = v;
        }
    }
    __syncthreads();

    // ---- hoist Q fragments: 2 m16 tiles x 4 k-steps ----
    uint32_t qfr[4][2][4];
#pragma unroll
    for (int ks = 0; ks < 4; ks++)
#pragma unroll
        for (int t = 0; t < 2; t++)
            ldsm_x4(qfr[ks][t][0], qfr[ks][t][1], qfr[ks][t][2], qfr[ks][t][3],
                    QsB + aMap + (uint32_t)(t * 16 * APH * 2 + ks * 32));

    float oacc[2][8][4];
#pragma unroll
    for (int t = 0; t < 2; t++)
#pragma unroll
        for (int nf = 0; nf < 8; nf++)
#pragma unroll
            for (int q = 0; q < 4; q++) oacc[t][nf][q] = 0.f;
    float mstate[2][2] = {{-1e30f, -1e30f}, {-1e30f, -1e30f}};
    float lstate[2][2] = {{0.f, 0.f}, {0.f, 0.f}};

    for (int kb = 0; kb < nkb; kb++) {
        // data(kb) ready; all warps finished compute(kb-1)
        asm volatile("cp.async.wait_group 0;" ::: "memory");
        __syncthreads();

        // Issue loads for kb+1 into the other stage (overlaps compute(kb))
        if (kb + 1 < nkb) {
            const int st = (kb + 1) & 1;
            const size_t go = (size_t)(kb + 1) * 64 * QKVW;
#pragma unroll
            for (int i = 0; i < 4; i++) {
                cp_async16(KsB[st] + kvOff + i * 16u, Kg + go + i * 8);
                cp_async16(VsB[st] + kvOff + i * 16u, Vg + go + i * 8);
            }
            cp_commit();
        }

        const uint32_t Kb = KsB[kb & 1];
        const uint32_t Vb = VsB[kb & 1];

        // ---- S = Q K^T (32x64 per warp) ----
        float sacc[2][8][4];
#pragma unroll
        for (int t = 0; t < 2; t++)
#pragma unroll
            for (int nf = 0; nf < 8; nf++)
#pragma unroll
                for (int q = 0; q < 4; q++) sacc[t][nf][q] = 0.f;
#pragma unroll
        for (int ks = 0; ks < 4; ks++) {
            uint32_t bfr[8][2];
#pragma unroll
            for (int p = 0; p < 4; p++)
                ldsm_x4(bfr[2 * p][0], bfr[2 * p][1],
                        bfr[2 * p + 1][0], bfr[2 * p + 1][1],
                        Kb + bMap + (uint32_t)(p * 16 * APH * 2 + ks * 32));
#pragma unroll
            for (int t = 0; t < 2; t++)
#pragma unroll
                for (int nf = 0; nf < 8; nf++)
                    mma_f16(sacc[t][nf], qfr[ks][t], bfr[nf][0], bfr[nf][1]);
        }

        // ---- causal mask (only last two key blocks cross the diagonal) ----
        if (kb >= 2 * qb) {
#pragma unroll
            for (int t = 0; t < 2; t++) {
                const int rg0 = qb * 128 + r0 + t * 16;
#pragma unroll
                for (int nf = 0; nf < 8; nf++) {
                    const int cg = kb * 64 + nf * 8 + 2 * tig;
                    if (cg     > rg0)     sacc[t][nf][0] = -1e30f;
                    if (cg + 1 > rg0)     sacc[t][nf][1] = -1e30f;
                    if (cg     > rg0 + 8) sacc[t][nf][2] = -1e30f;
                    if (cg + 1 > rg0 + 8) sacc[t][nf][3] = -1e30f;
                }
            }
        }

        // ---- online softmax; P packed straight into mma A-fragments ----
        uint32_t pf01[2][8], pf23[2][8];
#pragma unroll
        for (int t = 0; t < 2; t++) {
            float mx0 = -1e30f, mx1 = -1e30f;
#pragma unroll
            for (int nf = 0; nf < 8; nf++) {
                mx0 = fmaxf(mx0, fmaxf(sacc[t][nf][0], sacc[t][nf][1]));
                mx1 = fmaxf(mx1, fmaxf(sacc[t][nf][2], sacc[t][nf][3]));
            }
            mx0 = fmaxf(mx0, __shfl_xor_sync(0xffffffffu, mx0, 1));
            mx0 = fmaxf(mx0, __shfl_xor_sync(0xffffffffu, mx0, 2));
            mx1 = fmaxf(mx1, __shfl_xor_sync(0xffffffffu, mx1, 1));
            mx1 = fmaxf(mx1, __shfl_xor_sync(0xffffffffu, mx1, 2));
            const float mn0 = fmaxf(mstate[t][0], mx0);
            const float mn1 = fmaxf(mstate[t][1], mx1);
            const float al0 = __expf(mstate[t][0] - mn0);
            const float al1 = __expf(mstate[t][1] - mn1);
            float rs0 = 0.f, rs1 = 0.f;
#pragma unroll
            for (int nf = 0; nf < 8; nf++) {
                const __half2 p01 = __floats2half2_rn(__expf(sacc[t][nf][0] - mn0),
                                                      __expf(sacc[t][nf][1] - mn0));
                const __half2 p23 = __floats2half2_rn(__expf(sacc[t][nf][2] - mn1),
                                                      __expf(sacc[t][nf][3] - mn1));
                const float2 f01 = __half22float2(p01);
                const float2 f23 = __half22float2(p23);
                rs0 += f01.x + f01.y;
                rs1 += f23.x + f23.y;
                pf01[t][nf] = *(const uint32_t*)&p01;
                pf23[t][nf] = *(const uint32_t*)&p23;
            }
            rs0 += __shfl_xor_sync(0xffffffffu, rs0, 1);
            rs0 += __shfl_xor_sync(0xffffffffu, rs0, 2);
            rs1 += __shfl_xor_sync(0xffffffffu, rs1, 1);
            rs1 += __shfl_xor_sync(0xffffffffu, rs1, 2);
            lstate[t][0] = lstate[t][0] * al0 + rs0;  mstate[t][0] = mn0;
            lstate[t][1] = lstate[t][1] * al1 + rs1;  mstate[t][1] = mn1;
#pragma unroll
            for (int nf = 0; nf < 8; nf++) {
                oacc[t][nf][0] *= al0; oacc[t][nf][1] *= al0;
                oacc[t][nf][2] *= al1; oacc[t][nf][3] *= al1;
            }
        }

        // ---- O += P V (A = P registers, B = V via ldmatrix.trans) ----
#pragma unroll
        for (int ks = 0; ks < 4; ks++) {
            uint32_t bfr[8][2];
#pragma unroll
            for (int p = 0; p < 4; p++)
                ldsm_x4_t(bfr[2 * p][0], bfr[2 * p][1],
                          bfr[2 * p + 1][0], bfr[2 * p + 1][1],
                          Vb + vMap + (uint32_t)(ks * 16 * APH * 2 + p * 32));
#pragma unroll
            for (int t = 0; t < 2; t++) {
                uint32_t a[4];
                a[0] = pf01[t][2 * ks];     a[1] = pf23[t][2 * ks];
                a[2] = pf01[t][2 * ks + 1]; a[3] = pf23[t][2 * ks + 1];
#pragma unroll
                for (int nf = 0; nf < 8; nf++)
                    mma_f16(oacc[t][nf], a, bfr[nf][0], bfr[nf][1]);
            }
        }
    }

#pragma unroll
    for (int t = 0; t < 2; t++) {
        const float inv0 = 1.0f / lstate[t][0], inv1 = 1.0f / lstate[t][1];
        __half* dst0 = y + (size_t)(b * TDIM + qb * 128 + r0 + t * 16) * CDIM + h * HD;
        __half* dst1 = dst0 + 8 * CDIM;
#pragma unroll
        for (int nf = 0; nf < 8; nf++) {
            const int c = nf * 8 + 2 * tig;
            *(__half2*)(dst0 + c) = __floats2half2_rn(oacc[t][nf][0] * inv0,
                                                      oacc[t][nf][1] * inv0);
            *(__half2*)(dst1 + c) = __floats2half2_rn(oacc[t][nf][2] * inv1,
                                                      oacc[t][nf][3] * inv1);
        }
    }
}

// ---------------------------------------------------------------------------
// Launch orchestration (graph-capturable)
// ---------------------------------------------------------------------------
extern "C" void kernel_launch(void* const* d_in, const int* in_sizes, int n_in,
                              void* d_out, int out_size)
{
    const float* x      = (const float*)d_in[0];
    const float* g1     = (const float*)d_in[1];
    const float* w_qkv  = (const float*)d_in[2];
    const float* w_o    = (const float*)d_in[3];
    const float* g2     = (const float*)d_in[4];
    const float* w_fc   = (const float*)d_in[5];
    const float* w_proj = (const float*)d_in[6];
    float* out = (float*)d_out;

    __half *ln, *qkvb, *yb, *hb, *wq, *wo, *wfc, *wp;
    float *x2;
    cudaGetSymbolAddress((void**)&ln,   g_ln);
    cudaGetSymbolAddress((void**)&qkvb, g_qkv);
    cudaGetSymbolAddress((void**)&yb,   g_y);
    cudaGetSymbolAddress((void**)&x2,   g_x2);
    cudaGetSymbolAddress((void**)&hb,   g_h);
    cudaGetSymbolAddress((void**)&wq,   g_wq);
    cudaGetSymbolAddress((void**)&wo,   g_wo);
    cudaGetSymbolAddress((void**)&wfc,  g_wfc);
    cudaGetSymbolAddress((void**)&wp,   g_wp);

    cudaFuncSetAttribute(attn_h,
                         cudaFuncAttributeMaxDynamicSharedMemorySize, SMEM_ATTN);
    cudaFuncSetAttribute(gemm_h<0>,
                         cudaFuncAttributeMaxDynamicSharedMemorySize, GSMEMH);
    cudaFuncSetAttribute(gemm_h<1>,
                         cudaFuncAttributeMaxDynamicSharedMemorySize, GSMEMH);
    cudaFuncSetAttribute(gemm_h<2>,
                         cudaFuncAttributeMaxDynamicSharedMemorySize, GSMEMH);

    // Convert all four weights to fp16 (single launch)
    prep_weights<<<(N8_ALL + 255) / 256, 256>>>(w_qkv, w_o, w_fc, w_proj,
                                                wq, wo, wfc, wp);

    // x1 = ln1(x); qkv = x1 @ Wqkv^T   (fp16 out)
    ln_kernel<<<BT, 256>>>(x, g1, ln);
    gemm_h<0><<<dim3(QKVW / 128, BT / 128), 128, GSMEMH>>>(
        ln, wq, nullptr, qkvb, BT, QKVW, CDIM);
    // y = causal attention (fp16 mma; cp.async K/V pipeline)
    attn_h<<<dim3(TDIM / 128, BDIM * HEADS), 128, SMEM_ATTN>>>(qkvb, yb);
    // x2 = x + y @ Wo^T   (fp32 out)
    gemm_h<1><<<dim3(CDIM / 128, BT / 128), 128, GSMEMH>>>(
        yb, wo, x, x2, BT, CDIM, CDIM);
    // h = gelu(ln2(x2) @ Wfc^T)   (fp16 out)
    ln_kernel<<<BT, 256>>>(x2, g2, ln);
    gemm_h<2><<<dim3(FFDIM / 128, BT / 128), 128, GSMEMH>>>(
        ln, wfc, nullptr, hb, BT, FFDIM, CDIM);
    // out = x2 + h @ Wproj^T   (fp32 out)
    gemm_h<1><<<dim3(CDIM / 128, BT / 128), 128, GSMEMH>>>(
        hb, wp, x2, out, BT, CDIM, FFDIM);
}

// round 16
// speedup vs baseline: 2.2855x; 1.0051x over previous
#include <cuda_runtime.h>
#include <cuda_fp16.h>
#include <math.h>
#include <stdint.h>

// Problem constants
#define BDIM   4
#define TDIM   2048
#define CDIM   1024
#define HEADS  16
#define HD     64
#define FFDIM  4096
#define BT     8192            // B*T rows
#define QKVW   3072            // 3*C

// Q pre-scale folded into QKV epilogue: 1/sqrt(64) * log2(e)
#define QSCALE 0.18033688011112042f

// ---------------------------------------------------------------------------
// Scratch (no allocations allowed — __device__ globals)
// ---------------------------------------------------------------------------
__device__ __half g_ln [BT * CDIM];
__device__ __half g_qkv[BT * QKVW];
__device__ __half g_y  [BT * CDIM];
__device__ float  g_x2 [BT * CDIM];
__device__ __half g_h  [BT * FFDIM];
__device__ __half g_wq [QKVW * CDIM];
__device__ __half g_wo [CDIM * CDIM];
__device__ __half g_wfc[FFDIM * CDIM];
__device__ __half g_wp [CDIM * FFDIM];

// ---------------------------------------------------------------------------
// Helpers
// ---------------------------------------------------------------------------
__device__ __forceinline__ uint32_t smem_u32(const void* p) {
    uint32_t a;
    asm("{ .reg .u64 t; cvta.to.shared.u64 t, %1; cvt.u32.u64 %0, t; }"
        : "=r"(a) : "l"(p));
    return a;
}
__device__ __forceinline__ void cp_async16(uint32_t saddr, const void* gaddr) {
    asm volatile("cp.async.cg.shared.global [%0], [%1], 16;"
                 :: "r"(saddr), "l"(gaddr) : "memory");
}
__device__ __forceinline__ void cp_commit() {
    asm volatile("cp.async.commit_group;" ::: "memory");
}
__device__ __forceinline__ void ldsm_x4(uint32_t& r0, uint32_t& r1,
                                        uint32_t& r2, uint32_t& r3,
                                        uint32_t addr) {
    asm volatile("ldmatrix.sync.aligned.m8n8.x4.shared.b16 {%0,%1,%2,%3}, [%4];"
                 : "=r"(r0), "=r"(r1), "=r"(r2), "=r"(r3) : "r"(addr));
}
__device__ __forceinline__ void ldsm_x4_t(uint32_t& r0, uint32_t& r1,
                                          uint32_t& r2, uint32_t& r3,
                                          uint32_t addr) {
    asm volatile("ldmatrix.sync.aligned.m8n8.x4.trans.shared.b16 {%0,%1,%2,%3}, [%4];"
                 : "=r"(r0), "=r"(r1), "=r"(r2), "=r"(r3) : "r"(addr));
}
__device__ __forceinline__ void mma_f16(float* d, const uint32_t* a,
                                        uint32_t b0, uint32_t b1) {
    asm volatile(
        "mma.sync.aligned.m16n8k16.row.col.f32.f16.f16.f32 "
        "{%0,%1,%2,%3}, {%4,%5,%6,%7}, {%8,%9}, {%0,%1,%2,%3};"
        : "+f"(d[0]), "+f"(d[1]), "+f"(d[2]), "+f"(d[3])
        : "r"(a[0]), "r"(a[1]), "r"(a[2]), "r"(a[3]), "r"(b0), "r"(b1));
}
__device__ __forceinline__ float ex2f(float x) {     // 2^x, single MUFU op
    float r;
    asm("ex2.approx.f32 %0, %1;" : "=f"(r) : "f"(x));
    return r;
}
__device__ __forceinline__ float gelu_f(float v) {
    return 0.5f * v * (1.0f + erff(v * 0.70710678118654752f));
}

// ---------------------------------------------------------------------------
// Fused weight prep: fp32 -> fp16, all four weights in one launch.
// ---------------------------------------------------------------------------
#define N8_WQ  (QKVW * CDIM / 8)
#define N8_WO  (CDIM * CDIM / 8)
#define N8_WFC (FFDIM * CDIM / 8)
#define N8_WP  (CDIM * FFDIM / 8)
#define N8_ALL (N8_WQ + N8_WO + N8_WFC + N8_WP)

__global__ __launch_bounds__(256)
void prep_weights(const float* __restrict__ wq_s, const float* __restrict__ wo_s,
                  const float* __restrict__ wfc_s, const float* __restrict__ wp_s,
                  __half* __restrict__ wq_d, __half* __restrict__ wo_d,
                  __half* __restrict__ wfc_d, __half* __restrict__ wp_d)
{
    int i = blockIdx.x * blockDim.x + threadIdx.x;
    const float* src;
    __half* dst;
    if (i < N8_WQ)                       { src = wq_s;  dst = wq_d; }
    else if ((i -= N8_WQ)  < N8_WO)      { src = wo_s;  dst = wo_d; }
    else if ((i -= N8_WO)  < N8_WFC)     { src = wfc_s; dst = wfc_d; }
    else if ((i -= N8_WFC) < N8_WP)      { src = wp_s;  dst = wp_d; }
    else return;
    const float4 v0 = ((const float4*)src)[2 * i];
    const float4 v1 = ((const float4*)src)[2 * i + 1];
    __half2 h[4];
    h[0] = __floats2half2_rn(v0.x, v0.y);
    h[1] = __floats2half2_rn(v0.z, v0.w);
    h[2] = __floats2half2_rn(v1.x, v1.y);
    h[3] = __floats2half2_rn(v1.z, v1.w);
    ((uint4*)dst)[i] = *(uint4*)h;
}

// ---------------------------------------------------------------------------
// LayerNorm: one block per row, C=1024, 256 threads x float4 -> fp16 out
// ---------------------------------------------------------------------------
__global__ __launch_bounds__(256)
void ln_kernel(const float* __restrict__ x, const float* __restrict__ g,
               __half* __restrict__ y)
{
    const int row = blockIdx.x;
    const int tid = threadIdx.x;
    const float4 v = ((const float4*)(x + (size_t)row * CDIM))[tid];
    float s  = v.x + v.y + v.z + v.w;
    float ss = v.x * v.x + v.y * v.y + v.z * v.z + v.w * v.w;
#pragma unroll
    for (int o = 16; o > 0; o >>= 1) {
        s  += __shfl_xor_sync(0xffffffffu, s,  o);
        ss += __shfl_xor_sync(0xffffffffu, ss, o);
    }
    __shared__ float rs[8], rss[8];
    const int w = tid >> 5, lane = tid & 31;
    if (lane == 0) { rs[w] = s; rss[w] = ss; }
    __syncthreads();
    if (tid == 0) {
        float a = 0.f, b = 0.f;
#pragma unroll
        for (int i = 0; i < 8; i++) { a += rs[i]; b += rss[i]; }
        const float mean = a * (1.0f / CDIM);
        const float var  = b * (1.0f / CDIM) - mean * mean;
        rs[0]  = mean;
        rss[0] = rsqrtf(var + 1e-5f);
    }
    __syncthreads();
    const float mean = rs[0], rstd = rss[0];
    const float4 gv = ((const float4*)g)[tid];
    __half2 h0 = __floats2half2_rn((v.x - mean) * rstd * gv.x,
                                   (v.y - mean) * rstd * gv.y);
    __half2 h1 = __floats2half2_rn((v.z - mean) * rstd * gv.z,
                                   (v.w - mean) * rstd * gv.w);
    uint2 u;
    u.x = *(uint32_t*)&h0;
    u.y = *(uint32_t*)&h1;
    ((uint2*)(y + (size_t)row * CDIM))[tid] = u;
}

// ---------------------------------------------------------------------------
// FP16 mma.sync GEMM (NT): C[m,n] = sum_k A[m,k]*B[n,k]
// ks-level fragment double buffering (load ks+1 fragments before ks MMAs).
// EPI: 0 = fp16 out, 1 = acc+res (fp32 out), 2 = gelu (fp16 out),
//      3 = fp16 out with QSCALE applied to cols < CDIM (QKV epilogue).
// ---------------------------------------------------------------------------
#define KC      64
#define GPH     72
#define TILE_H  (128 * GPH)
#define GSMEMH  (4 * TILE_H * 2)

template <int EPI>
__global__ __launch_bounds__(128, 2)
void gemm_h(const __half* __restrict__ A, const __half* __restrict__ B,
            const float* __restrict__ res, void* __restrict__ Cv,
            int M, int N, int K)
{
    extern __shared__ __half smh[];
    const uint32_t sb = smem_u32(smh);

    const int tid  = threadIdx.x;
    const int wid  = tid >> 5, lane = tid & 31;
    const int gid  = lane >> 2, tig = lane & 3;
    const int wm   = (wid & 1) << 6;
    const int wn   = (wid >> 1) << 6;
    const int bm   = blockIdx.y << 7, bn = blockIdx.x << 7;

    const int lr  = tid >> 3;
    const int lc8 = (tid & 7) << 3;
    const __half* Ag = A + (size_t)(bm + lr) * K + lc8;
    const __half* Bg = B + (size_t)(bn + lr) * K + lc8;
    uint32_t so[8];
#pragma unroll
    for (int p = 0; p < 8; p++)
        so[p] = (uint32_t)((p * 16 + lr) * GPH + lc8) * 2u;

    const uint32_t aB[2] = { sb,                 sb + 2u * TILE_H * 2u };
    const uint32_t bB[2] = { sb + TILE_H * 2u,   sb + 3u * TILE_H * 2u };

    const int aRow = wm + (lane & 7) + ((lane >> 3) & 1) * 8;
    const uint32_t aMap = (uint32_t)aRow * (GPH * 2) + (lane >> 4) * 16;
    const int bRow = wn + (lane >> 4) * 8 + (lane & 7);
    const uint32_t bMap = (uint32_t)bRow * (GPH * 2) + ((lane >> 3) & 1) * 16;

    float acc[4][8][4];
#pragma unroll
    for (int i = 0; i < 4; i++)
#pragma unroll
        for (int j = 0; j < 8; j++)
#pragma unroll
            for (int q = 0; q < 4; q++) acc[i][j][q] = 0.f;

    const int nk = K / KC;

#pragma unroll
    for (int p = 0; p < 8; p++) {
        cp_async16(aB[0] + so[p], Ag + (size_t)(p * 16) * K);
        cp_async16(bB[0] + so[p], Bg + (size_t)(p * 16) * K);
    }
    cp_commit();

    uint32_t afr[2][4][4], bfr[2][8][2];

    for (int c = 0; c < nk; c++) {
        if (c + 1 < nk) {
            const int ko = (c + 1) * KC;
            const int nb = (c + 1) & 1;
#pragma unroll
            for (int p = 0; p < 8; p++) {
                cp_async16(aB[nb] + so[p], Ag + (size_t)(p * 16) * K + ko);
                cp_async16(bB[nb] + so[p], Bg + (size_t)(p * 16) * K + ko);
            }
            cp_commit();
            asm volatile("cp.async.wait_group 1;" ::: "memory");
        } else {
            asm volatile("cp.async.wait_group 0;" ::: "memory");
        }
        __syncthreads();

        const uint32_t aBase = aB[c & 1] + aMap;
        const uint32_t bBase = bB[c & 1] + bMap;

        // prime ks = 0
#pragma unroll
        for (int mf = 0; mf < 4; mf++)
            ldsm_x4(afr[0][mf][0], afr[0][mf][1], afr[0][mf][2], afr[0][mf][3],
                    aBase + (uint32_t)(mf * 16 * GPH * 2));
#pragma unroll
        for (int p = 0; p < 4; p++)
            ldsm_x4(bfr[0][2 * p][0], bfr[0][2 * p][1],
                    bfr[0][2 * p + 1][0], bfr[0][2 * p + 1][1],
                    bBase + (uint32_t)(p * 16 * GPH * 2));

#pragma unroll
        for (int ks = 0; ks < 4; ks++) {
            const int cur = ks & 1, nxt = cur ^ 1;
            if (ks < 3) {
#pragma unroll
                for (int mf = 0; mf < 4; mf++)
                    ldsm_x4(afr[nxt][mf][0], afr[nxt][mf][1],
                            afr[nxt][mf][2], afr[nxt][mf][3],
                            aBase + (uint32_t)(mf * 16 * GPH * 2 + (ks + 1) * 32));
#pragma unroll
                for (int p = 0; p < 4; p++)
                    ldsm_x4(bfr[nxt][2 * p][0], bfr[nxt][2 * p][1],
                            bfr[nxt][2 * p + 1][0], bfr[nxt][2 * p + 1][1],
                            bBase + (uint32_t)(p * 16 * GPH * 2 + (ks + 1) * 32));
            }
#pragma unroll
            for (int mf = 0; mf < 4; mf++)
#pragma unroll
                for (int nf = 0; nf < 8; nf++)
                    mma_f16(acc[mf][nf], afr[cur][mf],
                            bfr[cur][nf][0], bfr[cur][nf][1]);
        }
        __syncthreads();
    }

    __half* Ch = (__half*)Cv;
    float*  Cf = (float*)Cv;
#pragma unroll
    for (int mf = 0; mf < 4; mf++) {
        const int row0 = bm + wm + mf * 16 + gid;
#pragma unroll
        for (int nf = 0; nf < 8; nf++) {
            const int col = bn + wn + nf * 8 + 2 * tig;
            const size_t i0 = (size_t)row0 * N + col;
            const size_t i1 = (size_t)(row0 + 8) * N + col;
            if (EPI == 1) {
                const float2 r0 = *(const float2*)(res + i0);
                const float2 r1 = *(const float2*)(res + i1);
                *(float2*)(Cf + i0) = make_float2(acc[mf][nf][0] + r0.x,
                                                  acc[mf][nf][1] + r0.y);
                *(float2*)(Cf + i1) = make_float2(acc[mf][nf][2] + r1.x,
                                                  acc[mf][nf][3] + r1.y);
            } else if (EPI == 0) {
                *(__half2*)(Ch + i0) = __floats2half2_rn(acc[mf][nf][0],
                                                         acc[mf][nf][1]);
                *(__half2*)(Ch + i1) = __floats2half2_rn(acc[mf][nf][2],
                                                         acc[mf][nf][3]);
            } else if (EPI == 3) {
                const float sc = (col < CDIM) ? QSCALE : 1.0f;
                *(__half2*)(Ch + i0) = __floats2half2_rn(acc[mf][nf][0] * sc,
                                                         acc[mf][nf][1] * sc);
                *(__half2*)(Ch + i1) = __floats2half2_rn(acc[mf][nf][2] * sc,
                                                         acc[mf][nf][3] * sc);
            } else {
                *(__half2*)(Ch + i0) = __floats2half2_rn(gelu_f(acc[mf][nf][0]),
                                                         gelu_f(acc[mf][nf][1]));
                *(__half2*)(Ch + i1) = __floats2half2_rn(gelu_f(acc[mf][nf][2]),
                                                         gelu_f(acc[mf][nf][3]));
            }
        }
    }
}

// ---------------------------------------------------------------------------
// Flash attention v5: fp16 mma, 128-row Q tiles, 128 threads (4 warps),
// warp owns 32 query rows. Q/P register-resident, cp.async K/V 2-stage ring.
// Q arrives pre-scaled by 0.125*log2e -> softmax in log2 domain (bare ex2).
// ---------------------------------------------------------------------------
#define APH 72
#define SMEM_ATTN ((128 + 4 * 64) * APH * 2)

__global__ __launch_bounds__(128, 2)
void attn_h(const __half* __restrict__ qkv, __half* __restrict__ y)
{
    extern __shared__ __half smA[];
    __half* Qs = smA;                            // [128][APH]
    const uint32_t QsB = smem_u32(Qs);
    const uint32_t KsB[2] = { QsB + 128u * APH * 2u,
                              QsB + 192u * APH * 2u };
    const uint32_t VsB[2] = { QsB + 256u * APH * 2u,
                              QsB + 320u * APH * 2u };

    const int qb   = gridDim.x - 1 - blockIdx.x;   // heavy tiles first
    const int b    = blockIdx.y >> 4;
    const int h    = blockIdx.y & 15;
    const int tid  = threadIdx.x;
    const int wid  = tid >> 5, lane = tid & 31;
    const int gid  = lane >> 2, tig = lane & 3;
    const int r0   = wid * 32 + gid;               // rows r0, +8, +16, +24

    // ldmatrix maps
    const int aRow = wid * 32 + (lane & 7) + ((lane >> 3) & 1) * 8;
    const uint32_t aMap = (uint32_t)aRow * (APH * 2) + (lane >> 4) * 16;
    const int bRow = (lane >> 4) * 8 + (lane & 7);
    const uint32_t bMap = (uint32_t)bRow * (APH * 2) + ((lane >> 3) & 1) * 16;
    const int vRow = (lane & 7) + ((lane >> 3) & 1) * 8;
    const uint32_t vMap = (uint32_t)vRow * (APH * 2) + (lane >> 4) * 16;

    const __half* base = qkv + (size_t)b * TDIM * QKVW + h * HD;

    // cp.async map for K/V tiles
    const int kv_r  = tid >> 1;
    const int kv_c  = (tid & 1) << 5;
    const __half* Kg = base + CDIM     + (size_t)kv_r * QKVW + kv_c;
    const __half* Vg = base + 2 * CDIM + (size_t)kv_r * QKVW + kv_c;
    const uint32_t kvOff = (uint32_t)(kv_r * APH + kv_c) * 2u;

    const int nkb = 2 * qb + 2;                   // 64-key blocks

    // Prologue: issue kb=0 K/V into stage 0
#pragma unroll
    for (int i = 0; i < 4; i++) {
        cp_async16(KsB[0] + kvOff + i * 16u, Kg + i * 8);
        cp_async16(VsB[0] + kvOff + i * 16u, Vg + i * 8);
    }
    cp_commit();

    // ---- Q tile: 128 rows x 64 halves (already scaled in QKV epilogue) ----
    {
        const __half* src = base + (size_t)(qb * 128 + tid) * QKVW;
#pragma unroll
        for (int i = 0; i < 8; i++)
            *(uint4*)&Qs[tid * APH + 8 * i] = ((const uint4*)src)[i];
    }
    __syncthreads();

    // ---- hoist Q fragments: 2 m16 tiles x 4 k-steps ----
    uint32_t qfr[4][2][4];
#pragma unroll
    for (int ks = 0; ks < 4; ks++)
#pragma unroll
        for (int t = 0; t < 2; t++)
            ldsm_x4(qfr[ks][t][0], qfr[ks][t][1], qfr[ks][t][2], qfr[ks][t][3],
                    QsB + aMap + (uint32_t)(t * 16 * APH * 2 + ks * 32));

    float oacc[2][8][4];
#pragma unroll
    for (int t = 0; t < 2; t++)
#pragma unroll
        for (int nf = 0; nf < 8; nf++)
#pragma unroll
            for (int q = 0; q < 4; q++) oacc[t][nf][q] = 0.f;
    float mstate[2][2] = {{-1e30f, -1e30f}, {-1e30f, -1e30f}};
    float lstate[2][2] = {{0.f, 0.f}, {0.f, 0.f}};

    for (int kb = 0; kb < nkb; kb++) {
        asm volatile("cp.async.wait_group 0;" ::: "memory");
        __syncthreads();

        if (kb + 1 < nkb) {
            const int st = (kb + 1) & 1;
            const size_t go = (size_t)(kb + 1) * 64 * QKVW;
#pragma unroll
            for (int i = 0; i < 4; i++) {
                cp_async16(KsB[st] + kvOff + i * 16u, Kg + go + i * 8);
                cp_async16(VsB[st] + kvOff + i * 16u, Vg + go + i * 8);
            }
            cp_commit();
        }

        const uint32_t Kb = KsB[kb & 1];
        const uint32_t Vb = VsB[kb & 1];

        // ---- S = Q K^T (32x64 per warp), log2-domain logits ----
        float sacc[2][8][4];
#pragma unroll
        for (int t = 0; t < 2; t++)
#pragma unroll
            for (int nf = 0; nf < 8; nf++)
#pragma unroll
                for (int q = 0; q < 4; q++) sacc[t][nf][q] = 0.f;
#pragma unroll
        for (int ks = 0; ks < 4; ks++) {
            uint32_t bfr[8][2];
#pragma unroll
            for (int p = 0; p < 4; p++)
                ldsm_x4(bfr[2 * p][0], bfr[2 * p][1],
                        bfr[2 * p + 1][0], bfr[2 * p + 1][1],
                        Kb + bMap + (uint32_t)(p * 16 * APH * 2 + ks * 32));
#pragma unroll
            for (int t = 0; t < 2; t++)
#pragma unroll
                for (int nf = 0; nf < 8; nf++)
                    mma_f16(sacc[t][nf], qfr[ks][t], bfr[nf][0], bfr[nf][1]);
        }

        // ---- causal mask ----
        if (kb >= 2 * qb) {
#pragma unroll
            for (int t = 0; t < 2; t++) {
                const int rg0 = qb * 128 + r0 + t * 16;
#pragma unroll
                for (int nf = 0; nf < 8; nf++) {
                    const int cg = kb * 64 + nf * 8 + 2 * tig;
                    if (cg     > rg0)     sacc[t][nf][0] = -1e30f;
                    if (cg + 1 > rg0)     sacc[t][nf][1] = -1e30f;
                    if (cg     > rg0 + 8) sacc[t][nf][2] = -1e30f;
                    if (cg + 1 > rg0 + 8) sacc[t][nf][3] = -1e30f;
                }
            }
        }

        // ---- online softmax in log2 domain (bare ex2) ----
        uint32_t pf01[2][8], pf23[2][8];
#pragma unroll
        for (int t = 0; t < 2; t++) {
            float mx0 = -1e30f, mx1 = -1e30f;
#pragma unroll
            for (int nf = 0; nf < 8; nf++) {
                mx0 = fmaxf(mx0, fmaxf(sacc[t][nf][0], sacc[t][nf][1]));
                mx1 = fmaxf(mx1, fmaxf(sacc[t][nf][2], sacc[t][nf][3]));
            }
            mx0 = fmaxf(mx0, __shfl_xor_sync(0xffffffffu, mx0, 1));
            mx0 = fmaxf(mx0, __shfl_xor_sync(0xffffffffu, mx0, 2));
            mx1 = fmaxf(mx1, __shfl_xor_sync(0xffffffffu, mx1, 1));
            mx1 = fmaxf(mx1, __shfl_xor_sync(0xffffffffu, mx1, 2));
            const float mn0 = fmaxf(mstate[t][0], mx0);
            const float mn1 = fmaxf(mstate[t][1], mx1);
            const float al0 = ex2f(mstate[t][0] - mn0);
            const float al1 = ex2f(mstate[t][1] - mn1);
            float rs0 = 0.f, rs1 = 0.f;
#pragma unroll
            for (int nf = 0; nf < 8; nf++) {
                const __half2 p01 = __floats2half2_rn(ex2f(sacc[t][nf][0] - mn0),
                                                      ex2f(sacc[t][nf][1] - mn0));
                const __half2 p23 = __floats2half2_rn(ex2f(sacc[t][nf][2] - mn1),
                                                      ex2f(sacc[t][nf][3] - mn1));
                const float2 f01 = __half22float2(p01);
                const float2 f23 = __half22float2(p23);
                rs0 += f01.x + f01.y;
                rs1 += f23.x + f23.y;
                pf01[t][nf] = *(const uint32_t*)&p01;
                pf23[t][nf] = *(const uint32_t*)&p23;
            }
            rs0 += __shfl_xor_sync(0xffffffffu, rs0, 1);
            rs0 += __shfl_xor_sync(0xffffffffu, rs0, 2);
            rs1 += __shfl_xor_sync(0xffffffffu, rs1, 1);
            rs1 += __shfl_xor_sync(0xffffffffu, rs1, 2);
            lstate[t][0] = lstate[t][0] * al0 + rs0;  mstate[t][0] = mn0;
            lstate[t][1] = lstate[t][1] * al1 + rs1;  mstate[t][1] = mn1;
#pragma unroll
            for (int nf = 0; nf < 8; nf++) {
                oacc[t][nf][0] *= al0; oacc[t][nf][1] *= al0;
                oacc[t][nf][2] *= al1; oacc[t][nf][3] *= al1;
            }
        }

        // ---- O += P V (A = P registers, B = V via ldmatrix.trans) ----
#pragma unroll
        for (int ks = 0; ks < 4; ks++) {
            uint32_t bfr[8][2];
#pragma unroll
            for (int p = 0; p < 4; p++)
                ldsm_x4_t(bfr[2 * p][0], bfr[2 * p][1],
                          bfr[2 * p + 1][0], bfr[2 * p + 1][1],
                          Vb + vMap + (uint32_t)(ks * 16 * APH * 2 + p * 32));
#pragma unroll
            for (int t = 0; t < 2; t++) {
                uint32_t a[4];
                a[0] = pf01[t][2 * ks];     a[1] = pf23[t][2 * ks];
                a[2] = pf01[t][2 * ks + 1]; a[3] = pf23[t][2 * ks + 1];
#pragma unroll
                for (int nf = 0; nf < 8; nf++)
                    mma_f16(oacc[t][nf], a, bfr[nf][0], bfr[nf][1]);
            }
        }
    }

#pragma unroll
    for (int t = 0; t < 2; t++) {
        const float inv0 = 1.0f / lstate[t][0], inv1 = 1.0f / lstate[t][1];
        __half* dst0 = y + (size_t)(b * TDIM + qb * 128 + r0 + t * 16) * CDIM + h * HD;
        __half* dst1 = dst0 + 8 * CDIM;
#pragma unroll
        for (int nf = 0; nf < 8; nf++) {
            const int c = nf * 8 + 2 * tig;
            *(__half2*)(dst0 + c) = __floats2half2_rn(oacc[t][nf][0] * inv0,
                                                      oacc[t][nf][1] * inv0);
            *(__half2*)(dst1 + c) = __floats2half2_rn(oacc[t][nf][2] * inv1,
                                                      oacc[t][nf][3] * inv1);
        }
    }
}

// ---------------------------------------------------------------------------
// Launch orchestration (graph-capturable)
// ---------------------------------------------------------------------------
extern "C" void kernel_launch(void* const* d_in, const int* in_sizes, int n_in,
                              void* d_out, int out_size)
{
    const float* x      = (const float*)d_in[0];
    const float* g1     = (const float*)d_in[1];
    const float* w_qkv  = (const float*)d_in[2];
    const float* w_o    = (const float*)d_in[3];
    const float* g2     = (const float*)d_in[4];
    const float* w_fc   = (const float*)d_in[5];
    const float* w_proj = (const float*)d_in[6];
    float* out = (float*)d_out;

    __half *ln, *qkvb, *yb, *hb, *wq, *wo, *wfc, *wp;
    float *x2;
    cudaGetSymbolAddress((void**)&ln,   g_ln);
    cudaGetSymbolAddress((void**)&qkvb, g_qkv);
    cudaGetSymbolAddress((void**)&yb,   g_y);
    cudaGetSymbolAddress((void**)&x2,   g_x2);
    cudaGetSymbolAddress((void**)&hb,   g_h);
    cudaGetSymbolAddress((void**)&wq,   g_wq);
    cudaGetSymbolAddress((void**)&wo,   g_wo);
    cudaGetSymbolAddress((void**)&wfc,  g_wfc);
    cudaGetSymbolAddress((void**)&wp,   g_wp);

    cudaFuncSetAttribute(attn_h,
                         cudaFuncAttributeMaxDynamicSharedMemorySize, SMEM_ATTN);
    cudaFuncSetAttribute(gemm_h<0>,
                         cudaFuncAttributeMaxDynamicSharedMemorySize, GSMEMH);
    cudaFuncSetAttribute(gemm_h<1>,
                         cudaFuncAttributeMaxDynamicSharedMemorySize, GSMEMH);
    cudaFuncSetAttribute(gemm_h<2>,
                         cudaFuncAttributeMaxDynamicSharedMemorySize, GSMEMH);
    cudaFuncSetAttribute(gemm_h<3>,
                         cudaFuncAttributeMaxDynamicSharedMemorySize, GSMEMH);

    // Convert all four weights to fp16 (single launch)
    prep_weights<<<(N8_ALL + 255) / 256, 256>>>(w_qkv, w_o, w_fc, w_proj,
                                                wq, wo, wfc, wp);

    // x1 = ln1(x); qkv = x1 @ Wqkv^T   (fp16 out; Q cols pre-scaled)
    ln_kernel<<<BT, 256>>>(x, g1, ln);
    gemm_h<3><<<dim3(QKVW / 128, BT / 128), 128, GSMEMH>>>(
        ln, wq, nullptr, qkvb, BT, QKVW, CDIM);
    // y = causal attention (fp16 mma; log2-domain softmax)
    attn_h<<<dim3(TDIM / 128, BDIM * HEADS), 128, SMEM_ATTN>>>(qkvb, yb);
    // x2 = x + y @ Wo^T   (fp32 out)
    gemm_h<1><<<dim3(CDIM / 128, BT / 128), 128, GSMEMH>>>(
        yb, wo, x, x2, BT, CDIM, CDIM);
    // h = gelu(ln2(x2) @ Wfc^T)   (fp16 out)
    ln_kernel<<<BT, 256>>>(x2, g2, ln);
    gemm_h<2><<<dim3(FFDIM / 128, BT / 128), 128, GSMEMH>>>(
        ln, wfc, nullptr, hb, BT, FFDIM, CDIM);
    // out = x2 + h @ Wproj^T   (fp32 out)
    gemm_h<1><<<dim3(CDIM / 128, BT / 128), 128, GSMEMH>>>(
        hb, wp, x2, out, BT, CDIM, FFDIM);
}

// round 17
// speedup vs baseline: 2.2952x; 1.0042x over previous
#include <cuda_runtime.h>
#include <cuda_fp16.h>
#include <math.h>
#include <stdint.h>

// Problem constants
#define BDIM   4
#define TDIM   2048
#define CDIM   1024
#define HEADS  16
#define HD     64
#define FFDIM  4096
#define BT     8192            // B*T rows
#define QKVW   3072            // 3*C

// Q pre-scale folded into QKV epilogue: 1/sqrt(64) * log2(e)
#define QSCALE 0.18033688011112042f

// ---------------------------------------------------------------------------
// Scratch (no allocations allowed — __device__ globals)
// ---------------------------------------------------------------------------
__device__ __half g_ln [BT * CDIM];
__device__ __half g_qkv[BT * QKVW];
__device__ __half g_y  [BT * CDIM];
__device__ float  g_x2 [BT * CDIM];
__device__ __half g_h  [BT * FFDIM];
__device__ __half g_wq [QKVW * CDIM];
__device__ __half g_wo [CDIM * CDIM];
__device__ __half g_wfc[FFDIM * CDIM];
__device__ __half g_wp [CDIM * FFDIM];

// ---------------------------------------------------------------------------
// Helpers
// ---------------------------------------------------------------------------
__device__ __forceinline__ uint32_t smem_u32(const void* p) {
    uint32_t a;
    asm("{ .reg .u64 t; cvta.to.shared.u64 t, %1; cvt.u32.u64 %0, t; }"
        : "=r"(a) : "l"(p));
    return a;
}
__device__ __forceinline__ void cp_async16(uint32_t saddr, const void* gaddr) {
    asm volatile("cp.async.cg.shared.global [%0], [%1], 16;"
                 :: "r"(saddr), "l"(gaddr) : "memory");
}
__device__ __forceinline__ void cp_commit() {
    asm volatile("cp.async.commit_group;" ::: "memory");
}
__device__ __forceinline__ void ldsm_x4(uint32_t& r0, uint32_t& r1,
                                        uint32_t& r2, uint32_t& r3,
                                        uint32_t addr) {
    asm volatile("ldmatrix.sync.aligned.m8n8.x4.shared.b16 {%0,%1,%2,%3}, [%4];"
                 : "=r"(r0), "=r"(r1), "=r"(r2), "=r"(r3) : "r"(addr));
}
__device__ __forceinline__ void ldsm_x4_t(uint32_t& r0, uint32_t& r1,
                                          uint32_t& r2, uint32_t& r3,
                                          uint32_t addr) {
    asm volatile("ldmatrix.sync.aligned.m8n8.x4.trans.shared.b16 {%0,%1,%2,%3}, [%4];"
                 : "=r"(r0), "=r"(r1), "=r"(r2), "=r"(r3) : "r"(addr));
}
__device__ __forceinline__ void mma_f16(float* d, const uint32_t* a,
                                        uint32_t b0, uint32_t b1) {
    asm volatile(
        "mma.sync.aligned.m16n8k16.row.col.f32.f16.f16.f32 "
        "{%0,%1,%2,%3}, {%4,%5,%6,%7}, {%8,%9}, {%0,%1,%2,%3};"
        : "+f"(d[0]), "+f"(d[1]), "+f"(d[2]), "+f"(d[3])
        : "r"(a[0]), "r"(a[1]), "r"(a[2]), "r"(a[3]), "r"(b0), "r"(b1));
}
__device__ __forceinline__ float ex2f(float x) {     // 2^x, single MUFU op
    float r;
    asm("ex2.approx.f32 %0, %1;" : "=f"(r) : "f"(x));
    return r;
}
__device__ __forceinline__ float gelu_f(float v) {
    return 0.5f * v * (1.0f + erff(v * 0.70710678118654752f));
}

// ---------------------------------------------------------------------------
// Fused weight prep: fp32 -> fp16, all four weights in one launch.
// ---------------------------------------------------------------------------
#define N8_WQ  (QKVW * CDIM / 8)
#define N8_WO  (CDIM * CDIM / 8)
#define N8_WFC (FFDIM * CDIM / 8)
#define N8_WP  (CDIM * FFDIM / 8)
#define N8_ALL (N8_WQ + N8_WO + N8_WFC + N8_WP)

__global__ __launch_bounds__(256)
void prep_weights(const float* __restrict__ wq_s, const float* __restrict__ wo_s,
                  const float* __restrict__ wfc_s, const float* __restrict__ wp_s,
                  __half* __restrict__ wq_d, __half* __restrict__ wo_d,
                  __half* __restrict__ wfc_d, __half* __restrict__ wp_d)
{
    int i = blockIdx.x * blockDim.x + threadIdx.x;
    const float* src;
    __half* dst;
    if (i < N8_WQ)                       { src = wq_s;  dst = wq_d; }
    else if ((i -= N8_WQ)  < N8_WO)      { src = wo_s;  dst = wo_d; }
    else if ((i -= N8_WO)  < N8_WFC)     { src = wfc_s; dst = wfc_d; }
    else if ((i -= N8_WFC) < N8_WP)      { src = wp_s;  dst = wp_d; }
    else return;
    const float4 v0 = ((const float4*)src)[2 * i];
    const float4 v1 = ((const float4*)src)[2 * i + 1];
    __half2 h[4];
    h[0] = __floats2half2_rn(v0.x, v0.y);
    h[1] = __floats2half2_rn(v0.z, v0.w);
    h[2] = __floats2half2_rn(v1.x, v1.y);
    h[3] = __floats2half2_rn(v1.z, v1.w);
    ((uint4*)dst)[i] = *(uint4*)h;
}

// ---------------------------------------------------------------------------
// LayerNorm: one block per row, C=1024, 256 threads x float4 -> fp16 out
// ---------------------------------------------------------------------------
__global__ __launch_bounds__(256)
void ln_kernel(const float* __restrict__ x, const float* __restrict__ g,
               __half* __restrict__ y)
{
    const int row = blockIdx.x;
    const int tid = threadIdx.x;
    const float4 v = ((const float4*)(x + (size_t)row * CDIM))[tid];
    float s  = v.x + v.y + v.z + v.w;
    float ss = v.x * v.x + v.y * v.y + v.z * v.z + v.w * v.w;
#pragma unroll
    for (int o = 16; o > 0; o >>= 1) {
        s  += __shfl_xor_sync(0xffffffffu, s,  o);
        ss += __shfl_xor_sync(0xffffffffu, ss, o);
    }
    __shared__ float rs[8], rss[8];
    const int w = tid >> 5, lane = tid & 31;
    if (lane == 0) { rs[w] = s; rss[w] = ss; }
    __syncthreads();
    if (tid == 0) {
        float a = 0.f, b = 0.f;
#pragma unroll
        for (int i = 0; i < 8; i++) { a += rs[i]; b += rss[i]; }
        const float mean = a * (1.0f / CDIM);
        const float var  = b * (1.0f / CDIM) - mean * mean;
        rs[0]  = mean;
        rss[0] = rsqrtf(var + 1e-5f);
    }
    __syncthreads();
    const float mean = rs[0], rstd = rss[0];
    const float4 gv = ((const float4*)g)[tid];
    __half2 h0 = __floats2half2_rn((v.x - mean) * rstd * gv.x,
                                   (v.y - mean) * rstd * gv.y);
    __half2 h1 = __floats2half2_rn((v.z - mean) * rstd * gv.z,
                                   (v.w - mean) * rstd * gv.w);
    uint2 u;
    u.x = *(uint32_t*)&h0;
    u.y = *(uint32_t*)&h1;
    ((uint2*)(y + (size_t)row * CDIM))[tid] = u;
}

// ---------------------------------------------------------------------------
// FP16 mma.sync GEMM (NT): C[m,n] = sum_k A[m,k]*B[n,k]
// R11 inner loop (fragments per-ks, no reg pipelining — fastest measured).
// EPI: 0 = fp16 out, 1 = acc+res (fp32 out), 2 = gelu (fp16 out),
//      3 = fp16 out with QSCALE applied to cols < CDIM (QKV epilogue).
// ---------------------------------------------------------------------------
#define KC      64
#define GPH     72
#define TILE_H  (128 * GPH)
#define GSMEMH  (4 * TILE_H * 2)

template <int EPI>
__global__ __launch_bounds__(128, 2)
void gemm_h(const __half* __restrict__ A, const __half* __restrict__ B,
            const float* __restrict__ res, void* __restrict__ Cv,
            int M, int N, int K)
{
    extern __shared__ __half smh[];
    const uint32_t sb = smem_u32(smh);

    const int tid  = threadIdx.x;
    const int wid  = tid >> 5, lane = tid & 31;
    const int gid  = lane >> 2, tig = lane & 3;
    const int wm   = (wid & 1) << 6;
    const int wn   = (wid >> 1) << 6;
    const int bm   = blockIdx.y << 7, bn = blockIdx.x << 7;

    const int lr  = tid >> 3;
    const int lc8 = (tid & 7) << 3;
    const __half* Ag = A + (size_t)(bm + lr) * K + lc8;
    const __half* Bg = B + (size_t)(bn + lr) * K + lc8;
    uint32_t so[8];
#pragma unroll
    for (int p = 0; p < 8; p++)
        so[p] = (uint32_t)((p * 16 + lr) * GPH + lc8) * 2u;

    const uint32_t aB[2] = { sb,                 sb + 2u * TILE_H * 2u };
    const uint32_t bB[2] = { sb + TILE_H * 2u,   sb + 3u * TILE_H * 2u };

    const int aRow = wm + (lane & 7) + ((lane >> 3) & 1) * 8;
    const uint32_t aMap = (uint32_t)aRow * (GPH * 2) + (lane >> 4) * 16;
    const int bRow = wn + (lane >> 4) * 8 + (lane & 7);
    const uint32_t bMap = (uint32_t)bRow * (GPH * 2) + ((lane >> 3) & 1) * 16;

    float acc[4][8][4];
#pragma unroll
    for (int i = 0; i < 4; i++)
#pragma unroll
        for (int j = 0; j < 8; j++)
#pragma unroll
            for (int q = 0; q < 4; q++) acc[i][j][q] = 0.f;

    const int nk = K / KC;

#pragma unroll
    for (int p = 0; p < 8; p++) {
        cp_async16(aB[0] + so[p], Ag + (size_t)(p * 16) * K);
        cp_async16(bB[0] + so[p], Bg + (size_t)(p * 16) * K);
    }
    cp_commit();

    for (int c = 0; c < nk; c++) {
        if (c + 1 < nk) {
            const int ko = (c + 1) * KC;
            const int nb = (c + 1) & 1;
#pragma unroll
            for (int p = 0; p < 8; p++) {
                cp_async16(aB[nb] + so[p], Ag + (size_t)(p * 16) * K + ko);
                cp_async16(bB[nb] + so[p], Bg + (size_t)(p * 16) * K + ko);
            }
            cp_commit();
            asm volatile("cp.async.wait_group 1;" ::: "memory");
        } else {
            asm volatile("cp.async.wait_group 0;" ::: "memory");
        }
        __syncthreads();

        const uint32_t aBase = aB[c & 1] + aMap;
        const uint32_t bBase = bB[c & 1] + bMap;
#pragma unroll
        for (int ks = 0; ks < 4; ks++) {
            uint32_t afr[4][4], bfr[8][2];
#pragma unroll
            for (int mf = 0; mf < 4; mf++)
                ldsm_x4(afr[mf][0], afr[mf][1], afr[mf][2], afr[mf][3],
                        aBase + (uint32_t)(mf * 16 * GPH * 2 + ks * 32));
#pragma unroll
            for (int p = 0; p < 4; p++)
                ldsm_x4(bfr[2 * p][0], bfr[2 * p][1],
                        bfr[2 * p + 1][0], bfr[2 * p + 1][1],
                        bBase + (uint32_t)(p * 16 * GPH * 2 + ks * 32));
#pragma unroll
            for (int mf = 0; mf < 4; mf++)
#pragma unroll
                for (int nf = 0; nf < 8; nf++)
                    mma_f16(acc[mf][nf], afr[mf], bfr[nf][0], bfr[nf][1]);
        }
        __syncthreads();
    }

    __half* Ch = (__half*)Cv;
    float*  Cf = (float*)Cv;
#pragma unroll
    for (int mf = 0; mf < 4; mf++) {
        const int row0 = bm + wm + mf * 16 + gid;
#pragma unroll
        for (int nf = 0; nf < 8; nf++) {
            const int col = bn + wn + nf * 8 + 2 * tig;
            const size_t i0 = (size_t)row0 * N + col;
            const size_t i1 = (size_t)(row0 + 8) * N + col;
            if (EPI == 1) {
                const float2 r0 = *(const float2*)(res + i0);
                const float2 r1 = *(const float2*)(res + i1);
                *(float2*)(Cf + i0) = make_float2(acc[mf][nf][0] + r0.x,
                                                  acc[mf][nf][1] + r0.y);
                *(float2*)(Cf + i1) = make_float2(acc[mf][nf][2] + r1.x,
                                                  acc[mf][nf][3] + r1.y);
            } else if (EPI == 0) {
                *(__half2*)(Ch + i0) = __floats2half2_rn(acc[mf][nf][0],
                                                         acc[mf][nf][1]);
                *(__half2*)(Ch + i1) = __floats2half2_rn(acc[mf][nf][2],
                                                         acc[mf][nf][3]);
            } else if (EPI == 3) {
                const float sc = (col < CDIM) ? QSCALE : 1.0f;
                *(__half2*)(Ch + i0) = __floats2half2_rn(acc[mf][nf][0] * sc,
                                                         acc[mf][nf][1] * sc);
                *(__half2*)(Ch + i1) = __floats2half2_rn(acc[mf][nf][2] * sc,
                                                         acc[mf][nf][3] * sc);
            } else {
                *(__half2*)(Ch + i0) = __floats2half2_rn(gelu_f(acc[mf][nf][0]),
                                                         gelu_f(acc[mf][nf][1]));
                *(__half2*)(Ch + i1) = __floats2half2_rn(gelu_f(acc[mf][nf][2]),
                                                         gelu_f(acc[mf][nf][3]));
            }
        }
    }
}

// ---------------------------------------------------------------------------
// Flash attention v6: fp16 mma, 128-row Q tiles, 128 threads (4 warps),
// warp owns 32 query rows. Q/P register-resident, cp.async K/V 2-stage ring,
// log2-domain softmax. V fragments for ks=0 prefetched BEFORE the softmax
// block (latency hidden under the FMA/MUFU chain); ks+1 V loads pipelined
// ahead of the ks MMA block.
// ---------------------------------------------------------------------------
#define APH 72
#define SMEM_ATTN ((128 + 4 * 64) * APH * 2)

__global__ __launch_bounds__(128, 2)
void attn_h(const __half* __restrict__ qkv, __half* __restrict__ y)
{
    extern __shared__ __half smA[];
    __half* Qs = smA;                            // [128][APH]
    const uint32_t QsB = smem_u32(Qs);
    const uint32_t KsB[2] = { QsB + 128u * APH * 2u,
                              QsB + 192u * APH * 2u };
    const uint32_t VsB[2] = { QsB + 256u * APH * 2u,
                              QsB + 320u * APH * 2u };

    const int qb   = gridDim.x - 1 - blockIdx.x;   // heavy tiles first
    const int b    = blockIdx.y >> 4;
    const int h    = blockIdx.y & 15;
    const int tid  = threadIdx.x;
    const int wid  = tid >> 5, lane = tid & 31;
    const int gid  = lane >> 2, tig = lane & 3;
    const int r0   = wid * 32 + gid;               // rows r0, +8, +16, +24

    // ldmatrix maps
    const int aRow = wid * 32 + (lane & 7) + ((lane >> 3) & 1) * 8;
    const uint32_t aMap = (uint32_t)aRow * (APH * 2) + (lane >> 4) * 16;
    const int bRow = (lane >> 4) * 8 + (lane & 7);
    const uint32_t bMap = (uint32_t)bRow * (APH * 2) + ((lane >> 3) & 1) * 16;
    const int vRow = (lane & 7) + ((lane >> 3) & 1) * 8;
    const uint32_t vMap = (uint32_t)vRow * (APH * 2) + (lane >> 4) * 16;

    const __half* base = qkv + (size_t)b * TDIM * QKVW + h * HD;

    // cp.async map for K/V tiles
    const int kv_r  = tid >> 1;
    const int kv_c  = (tid & 1) << 5;
    const __half* Kg = base + CDIM     + (size_t)kv_r * QKVW + kv_c;
    const __half* Vg = base + 2 * CDIM + (size_t)kv_r * QKVW + kv_c;
    const uint32_t kvOff = (uint32_t)(kv_r * APH + kv_c) * 2u;

    const int nkb = 2 * qb + 2;                   // 64-key blocks

    // Prologue: issue kb=0 K/V into stage 0
#pragma unroll
    for (int i = 0; i < 4; i++) {
        cp_async16(KsB[0] + kvOff + i * 16u, Kg + i * 8);
        cp_async16(VsB[0] + kvOff + i * 16u, Vg + i * 8);
    }
    cp_commit();

    // ---- Q tile: 128 rows x 64 halves (already scaled in QKV epilogue) ----
    {
        const __half* src = base + (size_t)(qb * 128 + tid) * QKVW;
#pragma unroll
        for (int i = 0; i < 8; i++)
            *(uint4*)&Qs[tid * APH + 8 * i] = ((const uint4*)src)[i];
    }
    __syncthreads();

    // ---- hoist Q fragments: 2 m16 tiles x 4 k-steps ----
    uint32_t qfr[4][2][4];
#pragma unroll
    for (int ks = 0; ks < 4; ks++)
#pragma unroll
        for (int t = 0; t < 2; t++)
            ldsm_x4(qfr[ks][t][0], qfr[ks][t][1], qfr[ks][t][2], qfr[ks][t][3],
                    QsB + aMap + (uint32_t)(t * 16 * APH * 2 + ks * 32));

    float oacc[2][8][4];
#pragma unroll
    for (int t = 0; t < 2; t++)
#pragma unroll
        for (int nf = 0; nf < 8; nf++)
#pragma unroll
            for (int q = 0; q < 4; q++) oacc[t][nf][q] = 0.f;
    float mstate[2][2] = {{-1e30f, -1e30f}, {-1e30f, -1e30f}};
    float lstate[2][2] = {{0.f, 0.f}, {0.f, 0.f}};

    for (int kb = 0; kb < nkb; kb++) {
        asm volatile("cp.async.wait_group 0;" ::: "memory");
        __syncthreads();

        if (kb + 1 < nkb) {
            const int st = (kb + 1) & 1;
            const size_t go = (size_t)(kb + 1) * 64 * QKVW;
#pragma unroll
            for (int i = 0; i < 4; i++) {
                cp_async16(KsB[st] + kvOff + i * 16u, Kg + go + i * 8);
                cp_async16(VsB[st] + kvOff + i * 16u, Vg + go + i * 8);
            }
            cp_commit();
        }

        const uint32_t Kb = KsB[kb & 1];
        const uint32_t Vb = VsB[kb & 1];

        // ---- S = Q K^T (32x64 per warp), log2-domain logits ----
        float sacc[2][8][4];
#pragma unroll
        for (int t = 0; t < 2; t++)
#pragma unroll
            for (int nf = 0; nf < 8; nf++)
#pragma unroll
                for (int q = 0; q < 4; q++) sacc[t][nf][q] = 0.f;
#pragma unroll
        for (int ks = 0; ks < 4; ks++) {
            uint32_t bfr[8][2];
#pragma unroll
            for (int p = 0; p < 4; p++)
                ldsm_x4(bfr[2 * p][0], bfr[2 * p][1],
                        bfr[2 * p + 1][0], bfr[2 * p + 1][1],
                        Kb + bMap + (uint32_t)(p * 16 * APH * 2 + ks * 32));
#pragma unroll
            for (int t = 0; t < 2; t++)
#pragma unroll
                for (int nf = 0; nf < 8; nf++)
                    mma_f16(sacc[t][nf], qfr[ks][t], bfr[nf][0], bfr[nf][1]);
        }

        // ---- causal mask ----
        if (kb >= 2 * qb) {
#pragma unroll
            for (int t = 0; t < 2; t++) {
                const int rg0 = qb * 128 + r0 + t * 16;
#pragma unroll
                for (int nf = 0; nf < 8; nf++) {
                    const int cg = kb * 64 + nf * 8 + 2 * tig;
                    if (cg     > rg0)     sacc[t][nf][0] = -1e30f;
                    if (cg + 1 > rg0)     sacc[t][nf][1] = -1e30f;
                    if (cg     > rg0 + 8) sacc[t][nf][2] = -1e30f;
                    if (cg + 1 > rg0 + 8) sacc[t][nf][3] = -1e30f;
                }
            }
        }

        // ---- prefetch V fragments for ks=0 (latency hides under softmax) ----
        uint32_t vfr[2][8][2];
#pragma unroll
        for (int p = 0; p < 4; p++)
            ldsm_x4_t(vfr[0][2 * p][0], vfr[0][2 * p][1],
                      vfr[0][2 * p + 1][0], vfr[0][2 * p + 1][1],
                      Vb + vMap + (uint32_t)(p * 32));

        // ---- online softmax in log2 domain (bare ex2) ----
        uint32_t pf01[2][8], pf23[2][8];
#pragma unroll
        for (int t = 0; t < 2; t++) {
            float mx0 = -1e30f, mx1 = -1e30f;
#pragma unroll
            for (int nf = 0; nf < 8; nf++) {
                mx0 = fmaxf(mx0, fmaxf(sacc[t][nf][0], sacc[t][nf][1]));
                mx1 = fmaxf(mx1, fmaxf(sacc[t][nf][2], sacc[t][nf][3]));
            }
            mx0 = fmaxf(mx0, __shfl_xor_sync(0xffffffffu, mx0, 1));
            mx0 = fmaxf(mx0, __shfl_xor_sync(0xffffffffu, mx0, 2));
            mx1 = fmaxf(mx1, __shfl_xor_sync(0xffffffffu, mx1, 1));
            mx1 = fmaxf(mx1, __shfl_xor_sync(0xffffffffu, mx1, 2));
            const float mn0 = fmaxf(mstate[t][0], mx0);
            const float mn1 = fmaxf(mstate[t][1], mx1);
            const float al0 = ex2f(mstate[t][0] - mn0);
            const float al1 = ex2f(mstate[t][1] - mn1);
            float rs0 = 0.f, rs1 = 0.f;
#pragma unroll
            for (int nf = 0; nf < 8; nf++) {
                const __half2 p01 = __floats2half2_rn(ex2f(sacc[t][nf][0] - mn0),
                                                      ex2f(sacc[t][nf][1] - mn0));
                const __half2 p23 = __floats2half2_rn(ex2f(sacc[t][nf][2] - mn1),
                                                      ex2f(sacc[t][nf][3] - mn1));
                const float2 f01 = __half22float2(p01);
                const float2 f23 = __half22float2(p23);
                rs0 += f01.x + f01.y;
                rs1 += f23.x + f23.y;
                pf01[t][nf] = *(const uint32_t*)&p01;
                pf23[t][nf] = *(const uint32_t*)&p23;
            }
            rs0 += __shfl_xor_sync(0xffffffffu, rs0, 1);
            rs0 += __shfl_xor_sync(0xffffffffu, rs0, 2);
            rs1 += __shfl_xor_sync(0xffffffffu, rs1, 1);
            rs1 += __shfl_xor_sync(0xffffffffu, rs1, 2);
            lstate[t][0] = lstate[t][0] * al0 + rs0;  mstate[t][0] = mn0;
            lstate[t][1] = lstate[t][1] * al1 + rs1;  mstate[t][1] = mn1;
#pragma unroll
            for (int nf = 0; nf < 8; nf++) {
                oacc[t][nf][0] *= al0; oacc[t][nf][1] *= al0;
                oacc[t][nf][2] *= al1; oacc[t][nf][3] *= al1;
            }
        }

        // ---- O += P V (A = P registers; V fragments pipelined over ks) ----
#pragma unroll
        for (int ks = 0; ks < 4; ks++) {
            const int cur = ks & 1, nxt = cur ^ 1;
            if (ks < 3) {
#pragma unroll
                for (int p = 0; p < 4; p++)
                    ldsm_x4_t(vfr[nxt][2 * p][0], vfr[nxt][2 * p][1],
                              vfr[nxt][2 * p + 1][0], vfr[nxt][2 * p + 1][1],
                              Vb + vMap + (uint32_t)((ks + 1) * 16 * APH * 2 + p * 32));
            }
#pragma unroll
            for (int t = 0; t < 2; t++) {
                uint32_t a[4];
                a[0] = pf01[t][2 * ks];     a[1] = pf23[t][2 * ks];
                a[2] = pf01[t][2 * ks + 1]; a[3] = pf23[t][2 * ks + 1];
#pragma unroll
                for (int nf = 0; nf < 8; nf++)
                    mma_f16(oacc[t][nf], a, vfr[cur][nf][0], vfr[cur][nf][1]);
            }
        }
    }

#pragma unroll
    for (int t = 0; t < 2; t++) {
        const float inv0 = 1.0f / lstate[t][0], inv1 = 1.0f / lstate[t][1];
        __half* dst0 = y + (size_t)(b * TDIM + qb * 128 + r0 + t * 16) * CDIM + h * HD;
        __half* dst1 = dst0 + 8 * CDIM;
#pragma unroll
        for (int nf = 0; nf < 8; nf++) {
            const int c = nf * 8 + 2 * tig;
            *(__half2*)(dst0 + c) = __floats2half2_rn(oacc[t][nf][0] * inv0,
                                                      oacc[t][nf][1] * inv0);
            *(__half2*)(dst1 + c) = __floats2half2_rn(oacc[t][nf][2] * inv1,
                                                      oacc[t][nf][3] * inv1);
        }
    }
}

// ---------------------------------------------------------------------------
// Launch orchestration (graph-capturable)
// ---------------------------------------------------------------------------
extern "C" void kernel_launch(void* const* d_in, const int* in_sizes, int n_in,
                              void* d_out, int out_size)
{
    const float* x      = (const float*)d_in[0];
    const float* g1     = (const float*)d_in[1];
    const float* w_qkv  = (const float*)d_in[2];
    const float* w_o    = (const float*)d_in[3];
    const float* g2     = (const float*)d_in[4];
    const float* w_fc   = (const float*)d_in[5];
    const float* w_proj = (const float*)d_in[6];
    float* out = (float*)d_out;

    __half *ln, *qkvb, *yb, *hb, *wq, *wo, *wfc, *wp;
    float *x2;
    cudaGetSymbolAddress((void**)&ln,   g_ln);
    cudaGetSymbolAddress((void**)&qkvb, g_qkv);
    cudaGetSymbolAddress((void**)&yb,   g_y);
    cudaGetSymbolAddress((void**)&x2,   g_x2);
    cudaGetSymbolAddress((void**)&hb,   g_h);
    cudaGetSymbolAddress((void**)&wq,   g_wq);
    cudaGetSymbolAddress((void**)&wo,   g_wo);
    cudaGetSymbolAddress((void**)&wfc,  g_wfc);
    cudaGetSymbolAddress((void**)&wp,   g_wp);

    cudaFuncSetAttribute(attn_h,
                         cudaFuncAttributeMaxDynamicSharedMemorySize, SMEM_ATTN);
    cudaFuncSetAttribute(gemm_h<0>,
                         cudaFuncAttributeMaxDynamicSharedMemorySize, GSMEMH);
    cudaFuncSetAttribute(gemm_h<1>,
                         cudaFuncAttributeMaxDynamicSharedMemorySize, GSMEMH);
    cudaFuncSetAttribute(gemm_h<2>,
                         cudaFuncAttributeMaxDynamicSharedMemorySize, GSMEMH);
    cudaFuncSetAttribute(gemm_h<3>,
                         cudaFuncAttributeMaxDynamicSharedMemorySize, GSMEMH);

    // Convert all four weights to fp16 (single launch)
    prep_weights<<<(N8_ALL + 255) / 256, 256>>>(w_qkv, w_o, w_fc, w_proj,
                                                wq, wo, wfc, wp);

    // x1 = ln1(x); qkv = x1 @ Wqkv^T   (fp16 out; Q cols pre-scaled)
    ln_kernel<<<BT, 256>>>(x, g1, ln);
    gemm_h<3><<<dim3(QKVW / 128, BT / 128), 128, GSMEMH>>>(
        ln, wq, nullptr, qkvb, BT, QKVW, CDIM);
    // y = causal attention (fp16 mma; log2 softmax; V prefetch)
    attn_h<<<dim3(TDIM / 128, BDIM * HEADS), 128, SMEM_ATTN>>>(qkvb, yb);
    // x2 = x + y @ Wo^T   (fp32 out)
    gemm_h<1><<<dim3(CDIM / 128, BT / 128), 128, GSMEMH>>>(
        yb, wo, x, x2, BT, CDIM, CDIM);
    // h = gelu(ln2(x2) @ Wfc^T)   (fp16 out)
    ln_kernel<<<BT, 256>>>(x2, g2, ln);
    gemm_h<2><<<dim3(FFDIM / 128, BT / 128), 128, GSMEMH>>>(
        ln, wfc, nullptr, hb, BT, FFDIM, CDIM);
    // out = x2 + h @ Wproj^T   (fp32 out)
    gemm_h<1><<<dim3(CDIM / 128, BT / 128), 128, GSMEMH>>>(
        hb, wp, x2, out, BT, CDIM, FFDIM);
}